// round 14
// baseline (speedup 1.0000x reference)
#include <cuda_runtime.h>
#include <cuda_bf16.h>
#include <math.h>
#include <stdint.h>

#define N_TOT 32768
#define B_    8
#define NG_   4096
#define KNN_  3
#define IN_CH_ 32
#define HID_  64
#define M_    100
#define OUT_CH_ 16
#define NP_   800      // B*M pooled nodes
#define E_PPI_ 600

// ------------------------------ scratch (device globals; no allocs) ---------
__device__ float g_sq[N_TOT];
__device__ int   g_knn[N_TOT * 3];
__device__ int   g_cand [N_TOT * 64];
__device__ float g_cdist[N_TOT * 64];
__device__ float g_dn[N_TOT];
__device__ float g_wn[N_TOT * 3];
__device__ float g_Z[(size_t)N_TOT * 256];
__device__ float g_u0[(size_t)N_TOT * 64];
__device__ float g_u1[(size_t)N_TOT * 400];
__device__ float g_t1[(size_t)N_TOT * 200];
__device__ float g_t2[(size_t)N_TOT * 100];
__device__ float g_S [(size_t)N_TOT * 100];
__device__ float g_amean[B_ * HID_];
__device__ float g_rstd [B_ * HID_];
__device__ float g_xp[NP_ * IN_CH_];
__device__ float g_h [NP_ * HID_];
__device__ float g_y [NP_ * HID_];
__device__ int   g_knn2[NP_ * 3];
__device__ float g_poolpart[32 * NP_ * 33];   // [ntile][g][c(32)+ssum]
// bf16 split images for kNN, row-major [N][K<=128]
__device__ __nv_bfloat16 g_imgA[(size_t)N_TOT * 192];
__device__ __nv_bfloat16 g_imgB[(size_t)N_TOT * 192];
// bf16 split weight images for GEMM, row-major [Nimg][Kp] (max 448*416)
__device__ __nv_bfloat16 g_whi[448 * 416];
__device__ __nv_bfloat16 g_wlo[448 * 416];

// ------------------------------ helpers -------------------------------------
__device__ __forceinline__ float selu_f(float x) {
    const float sc = 1.0507009873554804934193349852946f;
    const float al = 1.6732632423543772848170429916717f;
    return x > 0.f ? sc * x : sc * al * expm1f(x);
}

__device__ __forceinline__ void ffma2(unsigned long long& d,
                                      unsigned long long a,
                                      unsigned long long b) {
    asm("fma.rn.f32x2 %0, %1, %2, %3;" : "=l"(d) : "l"(a), "l"(b), "l"(d));
}
__device__ __forceinline__ void unpack2(unsigned long long v, float& lo, float& hi) {
    unsigned int a, b;
    asm("mov.b64 {%0, %1}, %2;" : "=r"(a), "=r"(b) : "l"(v));
    lo = __uint_as_float(a); hi = __uint_as_float(b);
}

__device__ __forceinline__ unsigned int smem_u32(const void* p) {
    unsigned int a;
    asm("{ .reg .u64 t; cvta.to.shared.u64 t, %1; cvt.u32.u64 %0, t; }"
        : "=r"(a) : "l"(p));
    return a;
}
__device__ __forceinline__ void ldm4(unsigned& r0, unsigned& r1, unsigned& r2,
                                     unsigned& r3, unsigned addr) {
    asm volatile("ldmatrix.sync.aligned.m8n8.x4.shared.b16 {%0,%1,%2,%3}, [%4];"
                 : "=r"(r0), "=r"(r1), "=r"(r2), "=r"(r3) : "r"(addr));
}
__device__ __forceinline__ void mma_bf16(float* d, const unsigned* a, const unsigned* b) {
    asm volatile("mma.sync.aligned.m16n8k16.row.col.f32.bf16.bf16.f32 "
        "{%0,%1,%2,%3}, {%4,%5,%6,%7}, {%8,%9}, {%0,%1,%2,%3};"
        : "+f"(d[0]), "+f"(d[1]), "+f"(d[2]), "+f"(d[3])
        : "r"(a[0]), "r"(a[1]), "r"(a[2]), "r"(a[3]), "r"(b[0]), "r"(b[1]));
}
__device__ __forceinline__ void cp_async16(unsigned int saddr, const void* g) {
    asm volatile("cp.async.cg.shared.global [%0], [%1], 16;"
                 :: "r"(saddr), "l"(g));
}
__device__ __forceinline__ void cp_commit() {
    asm volatile("cp.async.commit_group;");
}
__device__ __forceinline__ void cp_wait1() {
    asm volatile("cp.async.wait_group 1;");
}
__device__ __forceinline__ void cp_wait0() {
    asm volatile("cp.async.wait_group 0;");
}
__device__ __forceinline__ unsigned packbf2(__nv_bfloat16 a, __nv_bfloat16 b) {
    return (unsigned)__bfloat16_as_ushort(a)
         | ((unsigned)__bfloat16_as_ushort(b) << 16);
}

// ---- fused sq-norm + bf16-split image prep (stage 1, C=32, K=64) -----------
// A groups: [hi|hi], B groups: [hi|lo]  (lo_i*hi_j term dropped; candidate-
// level error ~0.01 abs, far below rank-8 gaps; exact rerank fixes the rest).
__global__ void sqprep32_kernel(const float* __restrict__ x, float* __restrict__ sq,
                                __nv_bfloat16* __restrict__ imgA,
                                __nv_bfloat16* __restrict__ imgB) {
    int gi = blockIdx.x * blockDim.x + threadIdx.x;
    if (gi >= N_TOT) return;
    const float4* r4 = (const float4*)(x + (size_t)gi * 32);
    uint4* a4 = (uint4*)(imgA + (size_t)gi * 64);
    uint4* b4 = (uint4*)(imgB + (size_t)gi * 64);
    float p[32];
#pragma unroll
    for (int t = 0; t < 4; t++) {
        float4 va = r4[2 * t], vb = r4[2 * t + 1];
        float vv[8] = {va.x, va.y, va.z, va.w, vb.x, vb.y, vb.z, vb.w};
        unsigned hw[4], lw[4];
#pragma unroll
        for (int i = 0; i < 4; i++) {
            float v0 = vv[2 * i], v1 = vv[2 * i + 1];
            __nv_bfloat16 h0 = __float2bfloat16(v0), h1 = __float2bfloat16(v1);
            __nv_bfloat16 l0 = __float2bfloat16(v0 - __bfloat162float(h0));
            __nv_bfloat16 l1 = __float2bfloat16(v1 - __bfloat162float(h1));
            hw[i] = packbf2(h0, h1);
            lw[i] = packbf2(l0, l1);
        }
#pragma unroll
        for (int i = 0; i < 8; i++) p[8 * t + i] = __fmul_rn(vv[i], vv[i]);
        uint4 H = make_uint4(hw[0], hw[1], hw[2], hw[3]);
        uint4 L = make_uint4(lw[0], lw[1], lw[2], lw[3]);
        a4[t] = H; a4[4 + t] = H;   // A: [hi|hi]
        b4[t] = H; b4[4 + t] = L;   // B: [hi|lo]
    }
#pragma unroll
    for (int off = 16; off > 0; off >>= 1)
#pragma unroll
        for (int c = 0; c < 16; c++)
            if (c < off) p[c] = __fadd_rn(p[c], p[c + off]);
    sq[gi] = p[0];
}

// ---- fused sq-norm + image prep (stage 2, C=64, K=128) ---------------------
__global__ void sqprep64_kernel(const float* __restrict__ u, float* __restrict__ sq,
                                __nv_bfloat16* __restrict__ imgA,
                                __nv_bfloat16* __restrict__ imgB) {
    int gi = blockIdx.x * blockDim.x + threadIdx.x;
    if (gi >= N_TOT) return;
    const float4* r4 = (const float4*)(u + (size_t)gi * 64);
    uint4* a4 = (uint4*)(imgA + (size_t)gi * 128);
    uint4* b4 = (uint4*)(imgB + (size_t)gi * 128);
    float p[32];
#pragma unroll
    for (int t = 0; t < 8; t++) {
        float4 va = r4[2 * t], vb = r4[2 * t + 1];
        float vv[8] = {va.x, va.y, va.z, va.w, vb.x, vb.y, vb.z, vb.w};
        unsigned hw[4], lw[4];
#pragma unroll
        for (int i = 0; i < 4; i++) {
            float v0 = vv[2 * i], v1 = vv[2 * i + 1];
            __nv_bfloat16 h0 = __float2bfloat16(v0), h1 = __float2bfloat16(v1);
            __nv_bfloat16 l0 = __float2bfloat16(v0 - __bfloat162float(h0));
            __nv_bfloat16 l1 = __float2bfloat16(v1 - __bfloat162float(h1));
            hw[i] = packbf2(h0, h1);
            lw[i] = packbf2(l0, l1);
        }
        float a0 = __fmaf_rn(vv[0], vv[0], 0.f);
        p[4 * t + 0] = __fmaf_rn(vv[1], vv[1], a0);
        float a1 = __fmaf_rn(vv[2], vv[2], 0.f);
        p[4 * t + 1] = __fmaf_rn(vv[3], vv[3], a1);
        float a2 = __fmaf_rn(vv[4], vv[4], 0.f);
        p[4 * t + 2] = __fmaf_rn(vv[5], vv[5], a2);
        float a3 = __fmaf_rn(vv[6], vv[6], 0.f);
        p[4 * t + 3] = __fmaf_rn(vv[7], vv[7], a3);
        uint4 H = make_uint4(hw[0], hw[1], hw[2], hw[3]);
        uint4 L = make_uint4(lw[0], lw[1], lw[2], lw[3]);
        a4[t] = H; a4[8 + t] = H;   // A: [hi|hi]
        b4[t] = H; b4[8 + t] = L;   // B: [hi|lo]
    }
#pragma unroll
    for (int off = 16; off > 0; off >>= 1)
#pragma unroll
        for (int c = 0; c < 16; c++)
            if (c < off) p[c] = __fadd_rn(p[c], p[c + off]);
    sq[gi] = p[0];
}

// ------------------------------ weight split prep (GEMM) ---------------------
__global__ void prep_w_kernel(const float* __restrict__ W,
                              __nv_bfloat16* __restrict__ whi,
                              __nv_bfloat16* __restrict__ wlo,
                              int K, int N, int Kp, int Nimg) {
    int idx = blockIdx.x * blockDim.x + threadIdx.x;
    int total = Nimg * (Kp / 8);
    if (idx >= total) return;
    int n = idx / (Kp / 8), k0 = (idx % (Kp / 8)) * 8;
    unsigned hh[4], ll[4];
#pragma unroll
    for (int e = 0; e < 4; e++) {
        float v0 = 0.f, v1 = 0.f;
        int k = k0 + 2 * e;
        if (n < N && k < K)     v0 = W[(size_t)k * N + n];
        if (n < N && k + 1 < K) v1 = W[(size_t)(k + 1) * N + n];
        __nv_bfloat16 h0 = __float2bfloat16(v0), h1 = __float2bfloat16(v1);
        __nv_bfloat16 l0 = __float2bfloat16(v0 - __bfloat162float(h0));
        __nv_bfloat16 l1 = __float2bfloat16(v1 - __bfloat162float(h1));
        hh[e] = packbf2(h0, h1);
        ll[e] = packbf2(l0, l1);
    }
    *(uint4*)&whi[(size_t)n * Kp + k0] = make_uint4(hh[0], hh[1], hh[2], hh[3]);
    *(uint4*)&wlo[(size_t)n * Kp + k0] = make_uint4(ll[0], ll[1], ll[2], ll[3]);
}

// ------------------------------ bf16-split tensor GEMM -----------------------
template<int ACT>
__global__ void __launch_bounds__(128) gemm_bf16_kernel(
        const float* __restrict__ A, const __nv_bfloat16* __restrict__ whi,
        const __nv_bfloat16* __restrict__ wlo, const float* __restrict__ bias,
        float* __restrict__ C, int K, int Kp, int Ncols) {
    const int SKW = 40;
    __shared__ __align__(16) __nv_bfloat16 Ahi[64][SKW], Alo[64][SKW],
                                           Bhi[64][SKW], Blo[64][SKW];
    int tid = threadIdx.x, lane = tid & 31, w = tid >> 5;
    int row0 = blockIdx.y * 64, col0 = blockIdx.x * 64;

    float acc[8][4];
#pragma unroll
    for (int nt = 0; nt < 8; nt++)
#pragma unroll
        for (int e = 0; e < 4; e++) acc[nt][e] = 0.f;

    const int ar = lane & 7, ah = (lane >> 3) & 1, akh = (lane >> 4) & 1;
    const int bn = (lane & 7) | (((lane >> 4) & 1) << 3), bh = (lane >> 3) & 1;
    const int m0 = w * 16;

    for (int k0 = 0; k0 < Kp; k0 += 32) {
#pragma unroll
        for (int s = 0; s < 4; s++) {
            int idx = tid + s * 128;
            int r = idx >> 3, c4 = idx & 7;
            int gk = k0 + c4 * 4;
            float4 v = make_float4(0.f, 0.f, 0.f, 0.f);
            if (gk < K) v = *(const float4*)(A + (size_t)(row0 + r) * K + gk);
            __nv_bfloat16 h0 = __float2bfloat16(v.x), h1 = __float2bfloat16(v.y);
            __nv_bfloat16 h2 = __float2bfloat16(v.z), h3 = __float2bfloat16(v.w);
            __nv_bfloat16 l0 = __float2bfloat16(v.x - __bfloat162float(h0));
            __nv_bfloat16 l1 = __float2bfloat16(v.y - __bfloat162float(h1));
            __nv_bfloat16 l2 = __float2bfloat16(v.z - __bfloat162float(h2));
            __nv_bfloat16 l3 = __float2bfloat16(v.w - __bfloat162float(h3));
            *(uint2*)&Ahi[r][c4 * 4] = make_uint2(packbf2(h0, h1), packbf2(h2, h3));
            *(uint2*)&Alo[r][c4 * 4] = make_uint2(packbf2(l0, l1), packbf2(l2, l3));
        }
#pragma unroll
        for (int s = 0; s < 2; s++) {
            int idx = tid + s * 128;
            int n = idx >> 2, c = idx & 3;
            size_t go = (size_t)(col0 + n) * Kp + k0 + c * 8;
            *(uint4*)&Bhi[n][c * 8] = *(const uint4*)&whi[go];
            *(uint4*)&Blo[n][c * 8] = *(const uint4*)&wlo[go];
        }
        __syncthreads();
#pragma unroll
        for (int kc = 0; kc < 2; kc++) {
            unsigned afh[4], afl[4];
            ldm4(afh[0], afh[1], afh[2], afh[3],
                 smem_u32(&Ahi[m0 + ar + 8 * ah][kc * 16 + 8 * akh]));
            ldm4(afl[0], afl[1], afl[2], afl[3],
                 smem_u32(&Alo[m0 + ar + 8 * ah][kc * 16 + 8 * akh]));
            unsigned bfh[8][2], bfl[8][2];
#pragma unroll
            for (int np = 0; np < 4; np++) {
                unsigned r0, r1, r2, r3;
                ldm4(r0, r1, r2, r3,
                     smem_u32(&Bhi[np * 16 + bn][kc * 16 + 8 * bh]));
                bfh[2 * np][0] = r0; bfh[2 * np][1] = r1;
                bfh[2 * np + 1][0] = r2; bfh[2 * np + 1][1] = r3;
                ldm4(r0, r1, r2, r3,
                     smem_u32(&Blo[np * 16 + bn][kc * 16 + 8 * bh]));
                bfl[2 * np][0] = r0; bfl[2 * np][1] = r1;
                bfl[2 * np + 1][0] = r2; bfl[2 * np + 1][1] = r3;
            }
#pragma unroll
            for (int nt = 0; nt < 8; nt++) {
                mma_bf16(acc[nt], afh, bfh[nt]);
                mma_bf16(acc[nt], afh, bfl[nt]);
                mma_bf16(acc[nt], afl, bfh[nt]);
            }
        }
        __syncthreads();
    }
    int r0e = row0 + m0 + (lane >> 2);
    int c0e = col0 + 2 * (lane & 3);
#pragma unroll
    for (int nt = 0; nt < 8; nt++)
#pragma unroll
        for (int e = 0; e < 4; e++) {
            int row = r0e + 8 * (e >> 1);
            int col = c0e + nt * 8 + (e & 1);
            if (col < Ncols) {
                float v = acc[nt][e] + bias[col];
                if (ACT == 1) v = selu_f(v);
                C[(size_t)row * Ncols + col] = v;
            }
        }
}

// ------------------------------ epilogue insert (kNN, min-gated) -------------
template<bool SELF>
__device__ __forceinline__ void epi_insert(float (&acc)[4][4], const float* sqb,
                                           const int (&jc16)[16], int j0,
                                           const int (&li2)[2],
                                           float (&cd)[2][4], int (&ci)[2][4]) {
#pragma unroll
    for (int nt = 0; nt < 4; nt++)
#pragma unroll
        for (int e = 0; e < 4; e++) {
            int jc = jc16[nt * 4 + e];
            float dv = __fmaf_rn(-2.f, acc[nt][e], sqb[jc]);
            if (SELF && (j0 + jc) == li2[e >> 1]) dv = 3.4e38f;
            acc[nt][e] = dv;
        }
    float mn0 = fminf(fminf(fminf(acc[0][0], acc[0][1]), fminf(acc[1][0], acc[1][1])),
                      fminf(fminf(acc[2][0], acc[2][1]), fminf(acc[3][0], acc[3][1])));
    float mn1 = fminf(fminf(fminf(acc[0][2], acc[0][3]), fminf(acc[1][2], acc[1][3])),
                      fminf(fminf(acc[2][2], acc[2][3]), fminf(acc[3][2], acc[3][3])));
    if (mn0 < cd[0][3]) {
#pragma unroll
        for (int nt = 0; nt < 4; nt++)
#pragma unroll
            for (int e = 0; e < 2; e++) {
                float d = acc[nt][e];
                if (d < cd[0][3]) {
                    int col = j0 + jc16[nt * 4 + e];
                    float vd = d; int vi = col;
#pragma unroll
                    for (int p = 0; p < 4; p++) {
                        if (vd < cd[0][p]) {
                            float td = cd[0][p]; int ti = ci[0][p];
                            cd[0][p] = vd; ci[0][p] = vi;
                            vd = td; vi = ti;
                        }
                    }
                }
            }
    }
    if (mn1 < cd[1][3]) {
#pragma unroll
        for (int nt = 0; nt < 4; nt++)
#pragma unroll
            for (int e = 2; e < 4; e++) {
                float d = acc[nt][e];
                if (d < cd[1][3]) {
                    int col = j0 + jc16[nt * 4 + e];
                    float vd = d; int vi = col;
#pragma unroll
                    for (int p = 0; p < 4; p++) {
                        if (vd < cd[1][p]) {
                            float td = cd[1][p]; int ti = ci[1][p];
                            cd[1][p] = vd; ci[1][p] = vi;
                            vd = td; vi = ti;
                        }
                    }
                }
            }
    }
}

// ------------------------------ mma.sync kNN candidates (K = 2C) -------------
template<int C>
__global__ void __launch_bounds__(128) knn_mma_kernel(
        const __nv_bfloat16* __restrict__ imgA, const __nv_bfloat16* __restrict__ imgB,
        const float* __restrict__ sq, float* __restrict__ candd,
        int* __restrict__ candi, int nper) {
    const int K   = 2 * C;
    const int SKW = K + 16;
    const int KC  = K / 16;
    const int JT  = 32;
    const int CH  = K / 8;
    const int SLOTS = JT * CH / 128;
    extern __shared__ __align__(16) __nv_bfloat16 sh[];
    __nv_bfloat16* Ash  = sh;
    __nv_bfloat16* Bsh  = sh + 64 * SKW;
    float*         sqsh = (float*)(Bsh + 2 * JT * SKW);

    int tid  = threadIdx.x;
    int lane = tid & 31, w = tid >> 5;
    int b = blockIdx.z, it = blockIdx.x, split = blockIdx.y;
    int ibase = it * 64;
    int gbase = b * nper;
    int jlen  = nper >> 2;
    int js    = split * jlen;
    const int NT = jlen / JT;

    for (int t = tid; t < 64 * CH; t += 128) {
        int r = t / CH, cc = t % CH;
        *(uint4*)&Ash[r * SKW + cc * 8] =
            *(const uint4*)&imgA[((size_t)(gbase + ibase + r)) * K + cc * 8];
    }

    unsigned sBoff[SLOTS]; unsigned gBoff[SLOTS];
#pragma unroll
    for (int s = 0; s < SLOTS; s++) {
        int q = tid + s * 128;
        int r = q / CH, cc = q % CH;
        sBoff[s] = (unsigned)((r * SKW + cc * 8) * 2);
        gBoff[s] = (unsigned)(r * K + cc * 8);
    }
    unsigned bufB[2] = { smem_u32(Bsh), smem_u32(Bsh + JT * SKW) };
    unsigned sqBuf[2] = { smem_u32(sqsh), smem_u32(sqsh + JT) };

    const __nv_bfloat16* gtile = imgB + (size_t)(gbase + js) * K;
    const float* gsq = sq + gbase + js;
#pragma unroll
    for (int s = 0; s < SLOTS; s++)
        cp_async16(bufB[0] + sBoff[s], gtile + gBoff[s]);
    if (tid < JT / 4)
        cp_async16(sqBuf[0] + tid * 16, gsq + tid * 4);
    cp_commit();
    const __nv_bfloat16* gnext = gtile + (size_t)JT * K;
    const float* gsqnext = gsq + JT;

    const int m0 = w * 16;
    int li2[2];
#pragma unroll
    for (int s = 0; s < 2; s++) li2[s] = ibase + m0 + (lane >> 2) + 8 * s;
    float cd[2][4]; int ci[2][4];
#pragma unroll
    for (int s = 0; s < 2; s++)
#pragma unroll
        for (int p = 0; p < 4; p++) { cd[s][p] = 3.4e38f; ci[s][p] = 0; }

    const int ar  = lane & 7;
    const int ah  = (lane >> 3) & 1;
    const int akh = (lane >> 4) & 1;
    const int bn  = (lane & 7) | (((lane >> 4) & 1) << 3);
    const int bh  = (lane >> 3) & 1;
    unsigned aBase = smem_u32(&Ash[(m0 + ar + 8 * ah) * SKW + 8 * akh]);
    unsigned bnOff = (unsigned)((bn * SKW + 8 * bh) * 2);

    int jc16[16];
#pragma unroll
    for (int nt = 0; nt < 4; nt++)
#pragma unroll
        for (int e = 0; e < 4; e++)
            jc16[nt * 4 + e] = nt * 8 + 2 * (lane & 3) + (e & 1);

    int j0 = js;
    for (int t = 0; t < NT; t++) {
        if (t + 1 < NT) {
            unsigned bb = bufB[(t + 1) & 1];
#pragma unroll
            for (int s = 0; s < SLOTS; s++)
                cp_async16(bb + sBoff[s], gnext + gBoff[s]);
            if (tid < JT / 4)
                cp_async16(sqBuf[(t + 1) & 1] + tid * 16, gsqnext + tid * 4);
            cp_commit();
            cp_wait1();
            gnext += (size_t)JT * K;
            gsqnext += JT;
        } else {
            cp_wait0();
        }
        __syncthreads();

        unsigned bBufBase = bufB[t & 1] + bnOff;
        const float* sqb = (t & 1) ? (sqsh + JT) : sqsh;

        float acc[4][4];
#pragma unroll
        for (int nt = 0; nt < 4; nt++)
#pragma unroll
            for (int e = 0; e < 4; e++) acc[nt][e] = 0.f;

#pragma unroll
        for (int kc = 0; kc < KC; kc++) {
            unsigned af[4];
            ldm4(af[0], af[1], af[2], af[3], aBase + kc * 32);
            unsigned bf[4][2];
#pragma unroll
            for (int np = 0; np < 2; np++) {
                unsigned r0, r1, r2, r3;
                ldm4(r0, r1, r2, r3, bBufBase + np * (16 * SKW * 2) + kc * 32);
                bf[2 * np][0] = r0; bf[2 * np][1] = r1;
                bf[2 * np + 1][0] = r2; bf[2 * np + 1][1] = r3;
            }
#pragma unroll
            for (int nt = 0; nt < 4; nt++)
                mma_bf16(acc[nt], af, bf[nt]);
        }

        bool ovl = (j0 < ibase + 64) && (j0 + JT > ibase);
        if (ovl) epi_insert<true >(acc, sqb, jc16, j0, li2, cd, ci);
        else     epi_insert<false>(acc, sqb, jc16, j0, li2, cd, ci);
        j0 += JT;
        __syncthreads();
    }
#pragma unroll
    for (int s = 0; s < 2; s++)
#pragma unroll
        for (int p = 0; p < 4; p++) {
            size_t base = ((size_t)(gbase + li2[s])) * 64 + split * 16 + (lane & 3) * 4 + p;
            candd[base] = cd[s][p];
            candi[base] = gbase + ci[s][p];
        }
}

// ------------------------------ warp-cooperative re-rank + wn ----------------
template<int C>
__global__ void rerank_kernel(const float* __restrict__ x, const float* __restrict__ sq,
                              const float* __restrict__ candd, const int* __restrict__ candi,
                              int* __restrict__ knn,
                              const float* __restrict__ ew, const float* __restrict__ dnv,
                              float* __restrict__ wn, int n) {
    int t = blockIdx.x * blockDim.x + threadIdx.x;
    int gi = t >> 3;
    int r8 = t & 7;
    if (gi >= n) return;

    const float* cdp = candd + (size_t)gi * 64 + r8 * 8;
    const int*   cip = candi + (size_t)gi * 64 + r8 * 8;
    float d8[8]; int i8[8];
#pragma unroll
    for (int p = 0; p < 8; p++) { d8[p] = cdp[p]; i8[p] = cip[p]; }

    unsigned taken = 0;
    float myD = 3.4e38f; int myI = 0;
#pragma unroll
    for (int r = 0; r < 8; r++) {
        float ld = 3.4e38f; int li = 0x7fffffff; int lp = -1;
#pragma unroll
        for (int p = 0; p < 8; p++) {
            if (!(taken & (1u << p)) &&
                (d8[p] < ld || (d8[p] == ld && i8[p] < li))) {
                ld = d8[p]; li = i8[p]; lp = p;
            }
        }
        float bd = ld; int bi = li; int bl = r8;
#pragma unroll
        for (int off = 4; off > 0; off >>= 1) {
            float od = __shfl_xor_sync(0xffffffffu, bd, off);
            int   oi = __shfl_xor_sync(0xffffffffu, bi, off);
            int   ol = __shfl_xor_sync(0xffffffffu, bl, off);
            if (od < bd || (od == bd && (oi < bi || (oi == bi && ol < bl)))) {
                bd = od; bi = oi; bl = ol;
            }
        }
        if (bl == r8 && lp >= 0) taken |= (1u << lp);
        if (r == r8) { myD = bd; myI = bi; }
    }

    const float* xi = x + (size_t)gi * C;
    const float* xr = x + (size_t)myI * C;
    float dot = 0.f;
#pragma unroll
    for (int c = 0; c < C; c++) dot = __fmaf_rn(__ldg(xi + c), __ldg(xr + c), dot);
    float dd = __fsub_rn(__fadd_rn(sq[gi], sq[myI]), __fmul_rn(2.f, dot));

    bool used = false;
    float dng = dnv[gi];
#pragma unroll
    for (int r = 0; r < 3; r++) {
        float bd = used ? 3.4e38f : dd;
        int   bi = used ? 0x7fffffff : myI;
        int   bl = r8;
#pragma unroll
        for (int off = 4; off > 0; off >>= 1) {
            float od = __shfl_xor_sync(0xffffffffu, bd, off);
            int   oi = __shfl_xor_sync(0xffffffffu, bi, off);
            int   ol = __shfl_xor_sync(0xffffffffu, bl, off);
            if (od < bd || (od == bd && (oi < bi || (oi == bi && ol < bl)))) {
                bd = od; bi = oi; bl = ol;
            }
        }
        if (bl == r8) used = true;
        if (r8 == 0) {
            knn[gi * 3 + r] = bi;
            wn [gi * 3 + r] = __fmul_rn(__fmul_rn(ew[gi * 3 + r], dng), dnv[bi]);
        }
    }
}

// ------------------------------ degree normalization -------------------------
__global__ void dn_kernel(const float* __restrict__ w, float* __restrict__ dn, int n) {
    int g = blockIdx.x * blockDim.x + threadIdx.x;
    if (g >= n) return;
    float d = w[3 * g] + w[3 * g + 1] + w[3 * g + 2];
    dn[g] = d > 0.f ? rsqrtf(fmaxf(d, 1e-12f)) : 0.f;
}

// ------------------------------ copy into Z slice (stage 1 only) -------------
__global__ void copy_slice_kernel(const float* __restrict__ src, float* __restrict__ Z,
                                  int Cq, int stride4, int total) {
    int idx = blockIdx.x * blockDim.x + threadIdx.x;
    if (idx >= total) return;
    int g = idx / Cq, q = idx % Cq;
    ((float4*)Z)[(size_t)g * stride4 + q] = ((const float4*)src)[(size_t)g * Cq + q];
}

// ------------------------------ Laplacian step -------------------------------
__global__ void lap_kernel(const float* __restrict__ Zin, const float* __restrict__ Zprev,
                           float* __restrict__ Zout, int stride, int Cq,
                           float alpha, float beta,
                           const int* __restrict__ knn, const float* __restrict__ wn,
                           int total) {
    int idx = blockIdx.x * blockDim.x + threadIdx.x;
    if (idx >= total) return;
    int g = idx / Cq, q = idx % Cq;
    int s0 = knn[3 * g], s1 = knn[3 * g + 1], s2 = knn[3 * g + 2];
    float w0 = wn[3 * g], w1 = wn[3 * g + 1], w2 = wn[3 * g + 2];
    float4 a0 = ((const float4*)(Zin + (size_t)s0 * stride))[q];
    float4 a1 = ((const float4*)(Zin + (size_t)s1 * stride))[q];
    float4 a2 = ((const float4*)(Zin + (size_t)s2 * stride))[q];
    float4 r;
    r.x = alpha * (-(w0 * a0.x + w1 * a1.x + w2 * a2.x));
    r.y = alpha * (-(w0 * a0.y + w1 * a1.y + w2 * a2.y));
    r.z = alpha * (-(w0 * a0.z + w1 * a1.z + w2 * a2.z));
    r.w = alpha * (-(w0 * a0.w + w1 * a1.w + w2 * a2.w));
    if (beta != 0.f) {
        float4 p = ((const float4*)(Zprev + (size_t)g * stride))[q];
        r.x += beta * p.x; r.y += beta * p.y; r.z += beta * p.z; r.w += beta * p.w;
    }
    ((float4*)(Zout + (size_t)g * stride))[q] = r;
}

// ------------------------------ fused copy + first lap (stage 2) -------------
__global__ void lap_first_kernel(const float* __restrict__ src, float* __restrict__ Z,
                                 int stride4, int Cq,
                                 const int* __restrict__ knn, const float* __restrict__ wn,
                                 int total) {
    int idx = blockIdx.x * blockDim.x + threadIdx.x;
    if (idx >= total) return;
    int g = idx / Cq, q = idx % Cq;
    int s0 = knn[3 * g], s1 = knn[3 * g + 1], s2 = knn[3 * g + 2];
    float w0 = wn[3 * g], w1 = wn[3 * g + 1], w2 = wn[3 * g + 2];
    const float4* s4 = (const float4*)src;
    float4 own = s4[(size_t)g * Cq + q];
    float4 a0 = s4[(size_t)s0 * Cq + q];
    float4 a1 = s4[(size_t)s1 * Cq + q];
    float4 a2 = s4[(size_t)s2 * Cq + q];
    float4 r;
    r.x = -(w0 * a0.x + w1 * a1.x + w2 * a2.x);
    r.y = -(w0 * a0.y + w1 * a1.y + w2 * a2.y);
    r.z = -(w0 * a0.z + w1 * a1.z + w2 * a2.z);
    r.w = -(w0 * a0.w + w1 * a1.w + w2 * a2.w);
    ((float4*)Z)[(size_t)g * stride4 + q]      = own;
    ((float4*)Z)[(size_t)g * stride4 + Cq + q] = r;
}

// ------------------------------ fp32 FFMA2 GEMM (conv0 only) ----------------
template<int ACT>
__global__ void gemm_kernel(const float* __restrict__ A, const float* __restrict__ B,
                            const float* __restrict__ bias, float* __restrict__ C,
                            int K, int Ncols) {
    __shared__ __align__(16) float As2[16][128];
    __shared__ __align__(16) float Bs[16][64];
    const int tid  = threadIdx.x;
    const int row0 = blockIdx.y * 64;
    const int col0 = blockIdx.x * 64;
    const int tx = tid & 15, ty = tid >> 4;
    unsigned long long acc2[4][2];
#pragma unroll
    for (int i = 0; i < 4; i++) { acc2[i][0] = 0ull; acc2[i][1] = 0ull; }

    const int lin  = tid * 4;
    const int arow = lin >> 4, acol = lin & 15;
    const int brow = lin >> 6, bcol = lin & 63;

    for (int k0 = 0; k0 < K; k0 += 16) {
        float4 av = make_float4(0.f, 0.f, 0.f, 0.f);
        if (k0 + acol < K)
            av = *(const float4*)(A + (size_t)(row0 + arow) * K + k0 + acol);
        *(float2*)&As2[acol + 0][2 * arow] = make_float2(av.x, av.x);
        *(float2*)&As2[acol + 1][2 * arow] = make_float2(av.y, av.y);
        *(float2*)&As2[acol + 2][2 * arow] = make_float2(av.z, av.z);
        *(float2*)&As2[acol + 3][2 * arow] = make_float2(av.w, av.w);

        float4 bv = make_float4(0.f, 0.f, 0.f, 0.f);
        int gk = k0 + brow, gc = col0 + bcol;
        if (gk < K && gc < Ncols)
            bv = *(const float4*)(B + (size_t)gk * Ncols + gc);
        *(float4*)&Bs[brow][bcol] = bv;
        __syncthreads();
#pragma unroll
        for (int kk = 0; kk < 16; kk++) {
            ulonglong2 a01 = *(const ulonglong2*)&As2[kk][ty * 8];
            ulonglong2 a23 = *(const ulonglong2*)&As2[kk][ty * 8 + 4];
            ulonglong2 bq  = *(const ulonglong2*)&Bs[kk][tx * 4];
            ffma2(acc2[0][0], a01.x, bq.x); ffma2(acc2[0][1], a01.x, bq.y);
            ffma2(acc2[1][0], a01.y, bq.x); ffma2(acc2[1][1], a01.y, bq.y);
            ffma2(acc2[2][0], a23.x, bq.x); ffma2(acc2[2][1], a23.x, bq.y);
            ffma2(acc2[3][0], a23.y, bq.x); ffma2(acc2[3][1], a23.y, bq.y);
        }
        __syncthreads();
    }
#pragma unroll
    for (int i = 0; i < 4; i++) {
        float a0, a1, a2, a3;
        unpack2(acc2[i][0], a0, a1);
        unpack2(acc2[i][1], a2, a3);
        float accs[4] = {a0, a1, a2, a3};
        int row = row0 + ty * 4 + i;
#pragma unroll
        for (int j = 0; j < 4; j++) {
            int col = col0 + tx * 4 + j;
            if (col < Ncols) {
                float v = accs[j] + bias[col];
                if (ACT == 1) v = selu_f(v);
                C[(size_t)row * Ncols + col] = v;
            }
        }
    }
}

// ------------------------------ GraphNorm -----------------------------------
__global__ void gn_reduce_kernel(const float* __restrict__ u, const float* __restrict__ alpha,
                                 float* __restrict__ amean, float* __restrict__ rstd) {
    int b = blockIdx.x;
    int t = threadIdx.x;               // 256
    int c = t & 63, rg = t >> 6;
    float s = 0.f;
    for (int n = rg; n < NG_; n += 4) s += u[((size_t)(b * NG_ + n)) * 64 + c];
    __shared__ float sh[256];
    sh[t] = s;
    __syncthreads();
    __shared__ float smean[64];
    if (t < 64) {
        s = sh[t] + sh[t + 64] + sh[t + 128] + sh[t + 192];
        smean[t] = s * (1.f / NG_);
    }
    __syncthreads();
    float am = alpha[c] * smean[c];
    float s2 = 0.f;
    for (int n = rg; n < NG_; n += 4) {
        float v = u[((size_t)(b * NG_ + n)) * 64 + c] - am;
        s2 += v * v;
    }
    sh[t] = s2;
    __syncthreads();
    if (t < 64) {
        s2 = sh[t] + sh[t + 64] + sh[t + 128] + sh[t + 192];
        float var = s2 * (1.f / NG_);
        amean[b * 64 + t] = alpha[t] * smean[t];
        rstd [b * 64 + t] = rsqrtf(var + 1e-5f);
    }
}

__global__ void gn_norm_kernel(float* __restrict__ u, const float* __restrict__ gamma,
                               const float* __restrict__ beta, const float* __restrict__ amean,
                               const float* __restrict__ rstd) {
    int idx = blockIdx.x * blockDim.x + threadIdx.x;
    if (idx >= N_TOT * 64) return;
    int g = idx >> 6, c = idx & 63;
    int b = g >> 12;   // /4096
    float v = u[idx];
    u[idx] = gamma[c] * (v - amean[b * 64 + c]) * rstd[b * 64 + c] + beta[c];
}

// ------------------------------ softmax rows (warp per row) ------------------
__global__ void softmax_kernel(const float* __restrict__ u, float* __restrict__ S) {
    int row = blockIdx.x * 4 + (threadIdx.x >> 5);
    int lane = threadIdx.x & 31;
    if (row >= N_TOT) return;
    const float* rp = u + (size_t)row * M_;
    float v0 = rp[lane], v1 = rp[lane + 32], v2 = rp[lane + 64];
    float v3 = (lane < 4) ? rp[lane + 96] : -3.4e38f;
    float m = fmaxf(fmaxf(v0, v1), fmaxf(v2, v3));
#pragma unroll
    for (int off = 16; off > 0; off >>= 1)
        m = fmaxf(m, __shfl_xor_sync(0xffffffffu, m, off));
    float e0 = expf(v0 - m), e1 = expf(v1 - m), e2 = expf(v2 - m);
    float e3 = (lane < 4) ? expf(v3 - m) : 0.f;
    float s = e0 + e1 + e2 + e3;
#pragma unroll
    for (int off = 16; off > 0; off >>= 1)
        s += __shfl_xor_sync(0xffffffffu, s, off);
    float inv = 1.f / s;
    float* so = S + (size_t)row * M_;
    so[lane] = e0 * inv; so[lane + 32] = e1 * inv; so[lane + 64] = e2 * inv;
    if (lane < 4) so[lane + 96] = e3 * inv;
}

// ------------------------------ DiffPool pooling (tiled, deterministic) ------
__global__ void pool_partial_kernel(const float* __restrict__ S, const float* __restrict__ x,
                                    float* __restrict__ part) {
    extern __shared__ float psm[];         // sS[128*100] + sX[128*32]
    float* sS = psm;
    float* sX = psm + 128 * M_;
    int b = blockIdx.y, nt = blockIdx.x, tid = threadIdx.x;
    size_t nbase = (size_t)(b * NG_ + nt * 128);
    const float4* gS = (const float4*)(S + nbase * M_);
    float4* s4 = (float4*)sS;
    for (int i = tid; i < 128 * M_ / 4; i += 128) s4[i] = gS[i];
    const float4* gX = (const float4*)(x + nbase * 32);
    float4* x4 = (float4*)sX;
    for (int i = tid; i < 128 * 32 / 4; i += 128) x4[i] = gX[i];
    __syncthreads();
    int ty = tid >> 5, tx = tid & 31;
    int mbase = ty * 25;
    float acc[25];
#pragma unroll
    for (int k = 0; k < 25; k++) acc[k] = 0.f;
    for (int n = 0; n < 128; n++) {
        float xv = sX[n * 32 + tx];
        const float* srow = &sS[n * M_ + mbase];
#pragma unroll
        for (int k = 0; k < 25; k++) acc[k] = __fmaf_rn(srow[k], xv, acc[k]);
    }
    float* po = part + ((size_t)nt * NP_ + b * M_) * 33;
#pragma unroll
    for (int k = 0; k < 25; k++) po[(mbase + k) * 33 + tx] = acc[k];
    if (tid < M_) {
        float s = 0.f;
        for (int n = 0; n < 128; n++) s += sS[n * M_ + tid];
        po[tid * 33 + 32] = s;
    }
}

__global__ void pool_reduce_kernel(const float* __restrict__ part, float* __restrict__ xp) {
    int idx = blockIdx.x * blockDim.x + threadIdx.x;
    if (idx >= NP_ * 32) return;
    int g = idx >> 5, c = idx & 31;
    float p = 0.f, s = 0.f;
    for (int t = 0; t < 32; t++) {
        const float* base = part + ((size_t)t * NP_ + g) * 33;
        p += base[c];
        s += base[32];
    }
    xp[idx] = p / s;
}

// ------------------------------ zero-init -----------------------------------
__global__ void zero2_kernel(float* a, float* b, int n) {
    int i = blockIdx.x * blockDim.x + threadIdx.x;
    if (i < n) { a[i] = 0.f; b[i] = 0.f; }
}

// ------------------------------ PPI edge conv -------------------------------
__global__ void ppi_conv_kernel(const float* __restrict__ xp, const int* __restrict__ connect,
                                const float* __restrict__ W2, const float* __restrict__ b2,
                                float* __restrict__ h) {
    __shared__ float feat[4][64];
    int t = threadIdx.x;
    int el = t >> 6, o = t & 63;
    int e = blockIdx.x * 4 + el;
    int dst = 0;
    if (e < B_ * E_PPI_) {
        int b = e / E_PPI_, le = e % E_PPI_;
        int s = connect[le] + b * M_;
        dst   = connect[E_PPI_ + le] + b * M_;
        float v;
        if (o < 32) v = xp[dst * 32 + o];
        else        v = xp[s * 32 + (o - 32)] - xp[dst * 32 + (o - 32)];
        feat[el][o] = v;
    }
    __syncthreads();
    if (e < B_ * E_PPI_) {
        float s = b2[o];
#pragma unroll
        for (int k = 0; k < 64; k++) s += feat[el][k] * W2[k * 64 + o];
        s = fmaxf(s, 0.f);
        atomicMax((int*)&h[dst * 64 + o], __float_as_int(s));
    }
}

// ------------------------------ small kNN on pooled graphs (100 nodes) ------
__global__ void knn_small_kernel(const float* __restrict__ h, int* __restrict__ knn2) {
    __shared__ float xsf[M_ * 64];
    __shared__ float sqs[M_];
    int b = blockIdx.x, t = threadIdx.x;   // 128 threads
    const float4* src4 = (const float4*)(h + (size_t)b * M_ * 64);
    float4* dst4 = (float4*)xsf;
    for (int idx = t; idx < M_ * 16; idx += 128) dst4[idx] = src4[idx];
    __syncthreads();
    if (t < M_) {
        const float* r = xsf + t * 64;
        float p[32];
#pragma unroll
        for (int q = 0; q < 32; q++) {
            float a = __fmaf_rn(r[2 * q], r[2 * q], 0.f);
            p[q] = __fmaf_rn(r[2 * q + 1], r[2 * q + 1], a);
        }
#pragma unroll
        for (int off = 16; off > 0; off >>= 1)
#pragma unroll
            for (int c = 0; c < 16; c++)
                if (c < off) p[c] = __fadd_rn(p[c], p[c + off]);
        sqs[t] = p[0];
    }
    __syncthreads();
    if (t < M_) {
        float sqi = sqs[t];
        float bd0 = 3.4e38f, bd1 = 3.4e38f, bd2 = 3.4e38f;
        int bi0 = 0, bi1 = 0, bi2 = 0;
        for (int j = 0; j < M_; j++) {
            if (j == t) continue;
            float dot = 0.f;
#pragma unroll
            for (int c = 0; c < 64; c++)
                dot = __fmaf_rn(xsf[t * 64 + c], xsf[j * 64 + c], dot);
            float t1 = __fadd_rn(sqi, sqs[j]);
            float t2 = __fmul_rn(2.f, dot);
            float d  = __fsub_rn(t1, t2);
            if (d < bd2) {
                if (d < bd0)      { bd2=bd1; bi2=bi1; bd1=bd0; bi1=bi0; bd0=d; bi0=j; }
                else if (d < bd1) { bd2=bd1; bi2=bi1; bd1=d;   bi1=j; }
                else              { bd2=d;   bi2=j; }
            }
        }
        int g = b * M_ + t;
        knn2[g * 3 + 0] = b * M_ + bi0;
        knn2[g * 3 + 1] = b * M_ + bi1;
        knn2[g * 3 + 2] = b * M_ + bi2;
    }
}

// ------------------------------ dynamic edge conv ---------------------------
__global__ void dyn_conv_kernel(const float* __restrict__ h, const int* __restrict__ knn2,
                                const float* __restrict__ W3, const float* __restrict__ b3,
                                float* __restrict__ y) {
    __shared__ float feat[2][128];
    int t = threadIdx.x;
    int e0 = blockIdx.x * 2;
#pragma unroll
    for (int p = 0; p < 2; p++) {
        int e = e0 + p;
        if (e < NP_ * 3) {
            int g = e / 3;
            int src = knn2[e];
            int c = t;
            float v = (c < 64) ? h[g * 64 + c] : (h[src * 64 + (c - 64)] - h[g * 64 + (c - 64)]);
            feat[p][c] = v;
        }
    }
    __syncthreads();
    int el = t >> 6, o = t & 63;
    int e = e0 + el;
    if (e < NP_ * 3) {
        int g = e / 3;
        float s = b3[o];
#pragma unroll
        for (int k = 0; k < 128; k++) s += feat[el][k] * W3[k * 64 + o];
        s = fmaxf(s, 0.f);
        atomicMax((int*)&y[g * 64 + o], __float_as_int(s));
    }
}

// ------------------------------ final MLP (f2) ------------------------------
__global__ void final_mlp_kernel(const float* __restrict__ h, const float* __restrict__ y,
                                 const float* __restrict__ w1, const float* __restrict__ b1,
                                 const float* __restrict__ w2, const float* __restrict__ b2,
                                 const float* __restrict__ w3, const float* __restrict__ b3,
                                 float* __restrict__ out) {
    int r = blockIdx.x * blockDim.x + threadIdx.x;
    if (r >= NP_) return;
    float z[64];
#pragma unroll
    for (int c = 0; c < 64; c++) z[c] = h[r * 64 + c] + y[r * 64 + c];
    float a1[32];
#pragma unroll
    for (int o = 0; o < 32; o++) {
        float s = b1[o];
        for (int k = 0; k < 64; k++) s += z[k] * w1[k * 32 + o];
        a1[o] = selu_f(s);
    }
    float a2[16];
#pragma unroll
    for (int o = 0; o < 16; o++) {
        float s = b2[o];
        for (int k = 0; k < 32; k++) s += a1[k] * w2[k * 16 + o];
        a2[o] = selu_f(s);
    }
#pragma unroll
    for (int o = 0; o < 16; o++) {
        float s = b3[o];
        for (int k = 0; k < 16; k++) s += a2[k] * w3[k * 16 + o];
        out[r * 16 + o] = s;
    }
}

// ------------------------------ host orchestration --------------------------
template<typename T>
static T* sym_addr(const void* sym) {
    void* p = nullptr;
    cudaGetSymbolAddress(&p, sym);
    return (T*)p;
}

extern "C" void kernel_launch(void* const* d_in, const int* in_sizes, int n_in,
                              void* d_out, int out_size) {
    const float* x    = (const float*)d_in[0];
    const float* ew   = (const float*)d_in[1];
    const int*   conn = (const int*)d_in[3];
    const float* W0   = (const float*)d_in[4];
    const float* b0   = (const float*)d_in[5];
    const float* gna  = (const float*)d_in[6];
    const float* gng  = (const float*)d_in[7];
    const float* gnb  = (const float*)d_in[8];
    const float* W1   = (const float*)d_in[9];
    const float* b1c  = (const float*)d_in[10];
    const float* f1w1 = (const float*)d_in[11];
    const float* f1b1 = (const float*)d_in[12];
    const float* f1w2 = (const float*)d_in[13];
    const float* f1b2 = (const float*)d_in[14];
    const float* f1w3 = (const float*)d_in[15];
    const float* f1b3 = (const float*)d_in[16];
    const float* W2   = (const float*)d_in[17];
    const float* b2   = (const float*)d_in[18];
    const float* W3   = (const float*)d_in[19];
    const float* b3   = (const float*)d_in[20];
    const float* f2w1 = (const float*)d_in[21];
    const float* f2b1 = (const float*)d_in[22];
    const float* f2w2 = (const float*)d_in[23];
    const float* f2b2 = (const float*)d_in[24];
    const float* f2w3 = (const float*)d_in[25];
    const float* f2b3 = (const float*)d_in[26];

    float* out_u = (float*)d_out;                       // [32768, 100]
    float* out_v = out_u + (size_t)N_TOT * M_;          // [800, 16]

    float* sq    = sym_addr<float>(g_sq);
    int*   knn   = sym_addr<int>(g_knn);
    int*   cand  = sym_addr<int>(g_cand);
    float* cdist = sym_addr<float>(g_cdist);
    float* dn    = sym_addr<float>(g_dn);
    float* wn    = sym_addr<float>(g_wn);
    float* Z     = sym_addr<float>(g_Z);
    float* u0    = sym_addr<float>(g_u0);
    float* u1    = sym_addr<float>(g_u1);
    float* t1    = sym_addr<float>(g_t1);
    float* t2    = sym_addr<float>(g_t2);
    float* S     = sym_addr<float>(g_S);
    float* amean = sym_addr<float>(g_amean);
    float* rstd  = sym_addr<float>(g_rstd);
    float* xp    = sym_addr<float>(g_xp);
    float* h     = sym_addr<float>(g_h);
    float* y     = sym_addr<float>(g_y);
    int*   knn2  = sym_addr<int>(g_knn2);
    float* ppart = sym_addr<float>(g_poolpart);
    __nv_bfloat16* imgA = sym_addr<__nv_bfloat16>(g_imgA);
    __nv_bfloat16* imgB = sym_addr<__nv_bfloat16>(g_imgB);
    __nv_bfloat16* whi  = sym_addr<__nv_bfloat16>(g_whi);
    __nv_bfloat16* wlo  = sym_addr<__nv_bfloat16>(g_wlo);

    // K = 2C images: SKW = 2C+16
    const int SM32 = 64 * 80 * 2 + 2 * 32 * 80 * 2 + 2 * 32 * 4;    // 20736 B
    const int SM64 = 64 * 144 * 2 + 2 * 32 * 144 * 2 + 2 * 32 * 4;  // 37120 B
    const int SMPOOL = 128 * (M_ + 32) * 4;                          // 67584 B
    static bool attr_done = false;
    if (!attr_done) {
        cudaFuncSetAttribute(pool_partial_kernel,
                             cudaFuncAttributeMaxDynamicSharedMemorySize, SMPOOL);
        attr_done = true;
    }

    // ---- edge normalization prerequisites
    dn_kernel<<<(N_TOT + 255) / 256, 256>>>(ew, dn, N_TOT);

    // ---- stage 1: kNN on x (C=32)
    sqprep32_kernel<<<(N_TOT + 127) / 128, 128>>>(x, sq, imgA, imgB);
    knn_mma_kernel<32><<<dim3(NG_ / 64, 4, B_), 128, SM32>>>(imgA, imgB, sq, cdist, cand, NG_);
    rerank_kernel<32><<<(N_TOT * 8 + 255) / 256, 256>>>(x, sq, cdist, cand, knn, ew, dn, wn, N_TOT);

    // ---- conv0: Chebyshev terms into Z (N x 128), fp32 GEMM (u0 bit-exact)
    {
        int total = N_TOT * 8;   // N * C/4, C=32
        copy_slice_kernel<<<(total + 255) / 256, 256>>>(x, Z, 8, 32, total);
        lap_kernel<<<(total + 255) / 256, 256>>>(Z + 0,  Z,       Z + 32, 128, 8, 1.f,  0.f, knn, wn, total);
        lap_kernel<<<(total + 255) / 256, 256>>>(Z + 32, Z + 0,   Z + 64, 128, 8, 2.f, -1.f, knn, wn, total);
        lap_kernel<<<(total + 255) / 256, 256>>>(Z + 64, Z + 32,  Z + 96, 128, 8, 2.f, -1.f, knn, wn, total);
        gemm_kernel<0><<<dim3(1, N_TOT / 64), 256>>>(Z, W0, b0, u0, 128, 64);
    }

    // ---- GraphNorm (unchanged; u0 bits preserved)
    gn_reduce_kernel<<<B_, 256>>>(u0, gna, amean, rstd);
    gn_norm_kernel<<<(N_TOT * 64) / 256, 256>>>(u0, gng, gnb, amean, rstd);

    // ---- stage 2: kNN on u0 (C=64)
    sqprep64_kernel<<<(N_TOT + 127) / 128, 128>>>(u0, sq, imgA, imgB);
    knn_mma_kernel<64><<<dim3(NG_ / 64, 4, B_), 128, SM64>>>(imgA, imgB, sq, cdist, cand, NG_);
    rerank_kernel<64><<<(N_TOT * 8 + 255) / 256, 256>>>(u0, sq, cdist, cand, knn, ew, dn, wn, N_TOT);

    // ---- conv1: fused copy+lap, laps, bf16-split tensor GEMM -> u1
    {
        int total = N_TOT * 16;  // N * C/4, C=64
        lap_first_kernel<<<(total + 255) / 256, 256>>>(u0, Z, 64, 16, knn, wn, total);
        lap_kernel<<<(total + 255) / 256, 256>>>(Z + 64,  Z + 0,    Z + 128, 256, 16, 2.f, -1.f, knn, wn, total);
        lap_kernel<<<(total + 255) / 256, 256>>>(Z + 128, Z + 64,   Z + 192, 256, 16, 2.f, -1.f, knn, wn, total);
        prep_w_kernel<<<(448 * 32 + 255) / 256, 256>>>(W1, whi, wlo, 256, 400, 256, 448);
        gemm_bf16_kernel<0><<<dim3(7, N_TOT / 64), 128>>>(Z, whi, wlo, b1c, u1, 256, 256, 400);
    }

    // ---- fc1 MLP: 400 -> 200 -> 100 -> 100 (bf16-split tensor GEMMs)
    prep_w_kernel<<<(256 * 52 + 255) / 256, 256>>>(f1w1, whi, wlo, 400, 200, 416, 256);
    gemm_bf16_kernel<1><<<dim3(4, N_TOT / 64), 128>>>(u1, whi, wlo, f1b1, t1, 400, 416, 200);
    prep_w_kernel<<<(128 * 28 + 255) / 256, 256>>>(f1w2, whi, wlo, 200, 100, 224, 128);
    gemm_bf16_kernel<1><<<dim3(2, N_TOT / 64), 128>>>(t1, whi, wlo, f1b2, t2, 200, 224, 100);
    prep_w_kernel<<<(128 * 16 + 255) / 256, 256>>>(f1w3, whi, wlo, 100, 100, 128, 128);
    gemm_bf16_kernel<0><<<dim3(2, N_TOT / 64), 128>>>(t2, whi, wlo, f1b3, out_u, 100, 128, 100);

    // ---- DiffPool soft pooling (tiled partials + deterministic reduce)
    softmax_kernel<<<N_TOT / 4, 128>>>(out_u, S);
    pool_partial_kernel<<<dim3(NG_ / 128, B_), 128, SMPOOL>>>(S, x, ppart);
    pool_reduce_kernel<<<(NP_ * 32 + 255) / 256, 256>>>(ppart, xp);

    // ---- PPI edge conv + dynamic edge conv
    zero2_kernel<<<(NP_ * HID_ + 255) / 256, 256>>>(h, y, NP_ * HID_);
    ppi_conv_kernel<<<(B_ * E_PPI_ + 3) / 4, 256>>>(xp, conn, W2, b2, h);
    knn_small_kernel<<<B_, 128>>>(h, knn2);
    dyn_conv_kernel<<<(NP_ * 3 + 1) / 2, 128>>>(h, knn2, W3, b3, y);

    // ---- final MLP -> v
    final_mlp_kernel<<<(NP_ + 127) / 128, 128>>>(h, y, f2w1, f2b1, f2w2, f2b2,
                                                 f2w3, f2b3, out_v);
}

// round 15
// speedup vs baseline: 1.3457x; 1.3457x over previous
#include <cuda_runtime.h>
#include <cuda_bf16.h>
#include <math.h>
#include <stdint.h>

#define N_TOT 32768
#define B_    8
#define NG_   4096
#define KNN_  3
#define IN_CH_ 32
#define HID_  64
#define M_    100
#define OUT_CH_ 16
#define NP_   800      // B*M pooled nodes
#define E_PPI_ 600

// ------------------------------ scratch (device globals; no allocs) ---------
__device__ float g_sq[N_TOT];
__device__ int   g_knn[N_TOT * 3];
__device__ int   g_cand [N_TOT * 64];
__device__ float g_cdist[N_TOT * 64];
__device__ float g_dn[N_TOT];
__device__ float g_wn[N_TOT * 3];
__device__ float g_Z[(size_t)N_TOT * 256];
__device__ float g_u0[(size_t)N_TOT * 64];
__device__ float g_u1[(size_t)N_TOT * 400];
__device__ float g_t1[(size_t)N_TOT * 200];
__device__ float g_t2[(size_t)N_TOT * 100];
__device__ float g_S [(size_t)N_TOT * 100];
__device__ float g_amean[B_ * HID_];
__device__ float g_rstd [B_ * HID_];
__device__ float g_xp[NP_ * IN_CH_];
__device__ float g_h [NP_ * HID_];
__device__ float g_y [NP_ * HID_];
__device__ int   g_knn2[NP_ * 3];
__device__ float g_poolpart[32 * NP_ * 33];   // [ntile][g][c(32)+ssum]
// bf16 split images for kNN, row-major [N][K<=192]
__device__ __nv_bfloat16 g_imgA[(size_t)N_TOT * 192];
__device__ __nv_bfloat16 g_imgB[(size_t)N_TOT * 192];
// bf16 split weight images for GEMM, row-major [Nimg][Kp] (max 448*416)
__device__ __nv_bfloat16 g_whi[448 * 416];
__device__ __nv_bfloat16 g_wlo[448 * 416];

// ------------------------------ helpers -------------------------------------
__device__ __forceinline__ float selu_f(float x) {
    const float sc = 1.0507009873554804934193349852946f;
    const float al = 1.6732632423543772848170429916717f;
    return x > 0.f ? sc * x : sc * al * expm1f(x);
}

__device__ __forceinline__ void ffma2(unsigned long long& d,
                                      unsigned long long a,
                                      unsigned long long b) {
    asm("fma.rn.f32x2 %0, %1, %2, %3;" : "=l"(d) : "l"(a), "l"(b), "l"(d));
}
__device__ __forceinline__ void unpack2(unsigned long long v, float& lo, float& hi) {
    unsigned int a, b;
    asm("mov.b64 {%0, %1}, %2;" : "=r"(a), "=r"(b) : "l"(v));
    lo = __uint_as_float(a); hi = __uint_as_float(b);
}

__device__ __forceinline__ unsigned int smem_u32(const void* p) {
    unsigned int a;
    asm("{ .reg .u64 t; cvta.to.shared.u64 t, %1; cvt.u32.u64 %0, t; }"
        : "=r"(a) : "l"(p));
    return a;
}
__device__ __forceinline__ void ldm4(unsigned& r0, unsigned& r1, unsigned& r2,
                                     unsigned& r3, unsigned addr) {
    asm volatile("ldmatrix.sync.aligned.m8n8.x4.shared.b16 {%0,%1,%2,%3}, [%4];"
                 : "=r"(r0), "=r"(r1), "=r"(r2), "=r"(r3) : "r"(addr));
}
__device__ __forceinline__ void mma_bf16(float* d, const unsigned* a, const unsigned* b) {
    asm volatile("mma.sync.aligned.m16n8k16.row.col.f32.bf16.bf16.f32 "
        "{%0,%1,%2,%3}, {%4,%5,%6,%7}, {%8,%9}, {%0,%1,%2,%3};"
        : "+f"(d[0]), "+f"(d[1]), "+f"(d[2]), "+f"(d[3])
        : "r"(a[0]), "r"(a[1]), "r"(a[2]), "r"(a[3]), "r"(b[0]), "r"(b[1]));
}
__device__ __forceinline__ void cp_async16(unsigned int saddr, const void* g) {
    asm volatile("cp.async.cg.shared.global [%0], [%1], 16;"
                 :: "r"(saddr), "l"(g));
}
__device__ __forceinline__ void cp_commit() {
    asm volatile("cp.async.commit_group;");
}
__device__ __forceinline__ void cp_wait1() {
    asm volatile("cp.async.wait_group 1;");
}
__device__ __forceinline__ void cp_wait0() {
    asm volatile("cp.async.wait_group 0;");
}
__device__ __forceinline__ unsigned packbf2(__nv_bfloat16 a, __nv_bfloat16 b) {
    return (unsigned)__bfloat16_as_ushort(a)
         | ((unsigned)__bfloat16_as_ushort(b) << 16);
}

// ---- fused sq-norm + dn + bf16-split image prep (stage 1, C=32, K=96) ------
// sq: identical ops to the verified sqnorm32; dn folded in (same arithmetic).
__global__ void sqprep32_kernel(const float* __restrict__ x, float* __restrict__ sq,
                                __nv_bfloat16* __restrict__ imgA,
                                __nv_bfloat16* __restrict__ imgB,
                                const float* __restrict__ ew, float* __restrict__ dn) {
    int gi = blockIdx.x * blockDim.x + threadIdx.x;
    if (gi >= N_TOT) return;
    {
        float d = ew[3 * gi] + ew[3 * gi + 1] + ew[3 * gi + 2];
        dn[gi] = d > 0.f ? rsqrtf(fmaxf(d, 1e-12f)) : 0.f;
    }
    const float4* r4 = (const float4*)(x + (size_t)gi * 32);
    uint4* a4 = (uint4*)(imgA + (size_t)gi * 96);
    uint4* b4 = (uint4*)(imgB + (size_t)gi * 96);
    float p[32];
#pragma unroll
    for (int t = 0; t < 4; t++) {
        float4 va = r4[2 * t], vb = r4[2 * t + 1];
        float vv[8] = {va.x, va.y, va.z, va.w, vb.x, vb.y, vb.z, vb.w};
        unsigned hw[4], lw[4];
#pragma unroll
        for (int i = 0; i < 4; i++) {
            float v0 = vv[2 * i], v1 = vv[2 * i + 1];
            __nv_bfloat16 h0 = __float2bfloat16(v0), h1 = __float2bfloat16(v1);
            __nv_bfloat16 l0 = __float2bfloat16(v0 - __bfloat162float(h0));
            __nv_bfloat16 l1 = __float2bfloat16(v1 - __bfloat162float(h1));
            hw[i] = packbf2(h0, h1);
            lw[i] = packbf2(l0, l1);
        }
#pragma unroll
        for (int i = 0; i < 8; i++) p[8 * t + i] = __fmul_rn(vv[i], vv[i]);
        uint4 H = make_uint4(hw[0], hw[1], hw[2], hw[3]);
        uint4 L = make_uint4(lw[0], lw[1], lw[2], lw[3]);
        a4[t] = H; a4[4 + t] = H; a4[8 + t] = L;   // A: [hi|hi|lo]
        b4[t] = H; b4[4 + t] = L; b4[8 + t] = H;   // B: [hi|lo|hi]
    }
#pragma unroll
    for (int off = 16; off > 0; off >>= 1)
#pragma unroll
        for (int c = 0; c < 16; c++)
            if (c < off) p[c] = __fadd_rn(p[c], p[c + off]);
    sq[gi] = p[0];
}

// ---- fused sq-norm + image prep (stage 2, C=64, K=192) ---------------------
__global__ void sqprep64_kernel(const float* __restrict__ u, float* __restrict__ sq,
                                __nv_bfloat16* __restrict__ imgA,
                                __nv_bfloat16* __restrict__ imgB) {
    int gi = blockIdx.x * blockDim.x + threadIdx.x;
    if (gi >= N_TOT) return;
    const float4* r4 = (const float4*)(u + (size_t)gi * 64);
    uint4* a4 = (uint4*)(imgA + (size_t)gi * 192);
    uint4* b4 = (uint4*)(imgB + (size_t)gi * 192);
    float p[32];
#pragma unroll
    for (int t = 0; t < 8; t++) {
        float4 va = r4[2 * t], vb = r4[2 * t + 1];
        float vv[8] = {va.x, va.y, va.z, va.w, vb.x, vb.y, vb.z, vb.w};
        unsigned hw[4], lw[4];
#pragma unroll
        for (int i = 0; i < 4; i++) {
            float v0 = vv[2 * i], v1 = vv[2 * i + 1];
            __nv_bfloat16 h0 = __float2bfloat16(v0), h1 = __float2bfloat16(v1);
            __nv_bfloat16 l0 = __float2bfloat16(v0 - __bfloat162float(h0));
            __nv_bfloat16 l1 = __float2bfloat16(v1 - __bfloat162float(h1));
            hw[i] = packbf2(h0, h1);
            lw[i] = packbf2(l0, l1);
        }
        float a0 = __fmaf_rn(vv[0], vv[0], 0.f);
        p[4 * t + 0] = __fmaf_rn(vv[1], vv[1], a0);
        float a1 = __fmaf_rn(vv[2], vv[2], 0.f);
        p[4 * t + 1] = __fmaf_rn(vv[3], vv[3], a1);
        float a2 = __fmaf_rn(vv[4], vv[4], 0.f);
        p[4 * t + 2] = __fmaf_rn(vv[5], vv[5], a2);
        float a3 = __fmaf_rn(vv[6], vv[6], 0.f);
        p[4 * t + 3] = __fmaf_rn(vv[7], vv[7], a3);
        uint4 H = make_uint4(hw[0], hw[1], hw[2], hw[3]);
        uint4 L = make_uint4(lw[0], lw[1], lw[2], lw[3]);
        a4[t] = H; a4[8 + t] = H; a4[16 + t] = L;  // A: [hi|hi|lo]
        b4[t] = H; b4[8 + t] = L; b4[16 + t] = H;  // B: [hi|lo|hi]
    }
#pragma unroll
    for (int off = 16; off > 0; off >>= 1)
#pragma unroll
        for (int c = 0; c < 16; c++)
            if (c < off) p[c] = __fadd_rn(p[c], p[c + off]);
    sq[gi] = p[0];
}

// ------------------------------ weight split prep (GEMM) ---------------------
__global__ void prep_w_kernel(const float* __restrict__ W,
                              __nv_bfloat16* __restrict__ whi,
                              __nv_bfloat16* __restrict__ wlo,
                              int K, int N, int Kp, int Nimg) {
    int idx = blockIdx.x * blockDim.x + threadIdx.x;
    int total = Nimg * (Kp / 8);
    if (idx >= total) return;
    int n = idx / (Kp / 8), k0 = (idx % (Kp / 8)) * 8;
    unsigned hh[4], ll[4];
#pragma unroll
    for (int e = 0; e < 4; e++) {
        float v0 = 0.f, v1 = 0.f;
        int k = k0 + 2 * e;
        if (n < N && k < K)     v0 = W[(size_t)k * N + n];
        if (n < N && k + 1 < K) v1 = W[(size_t)(k + 1) * N + n];
        __nv_bfloat16 h0 = __float2bfloat16(v0), h1 = __float2bfloat16(v1);
        __nv_bfloat16 l0 = __float2bfloat16(v0 - __bfloat162float(h0));
        __nv_bfloat16 l1 = __float2bfloat16(v1 - __bfloat162float(h1));
        hh[e] = packbf2(h0, h1);
        ll[e] = packbf2(l0, l1);
    }
    *(uint4*)&whi[(size_t)n * Kp + k0] = make_uint4(hh[0], hh[1], hh[2], hh[3]);
    *(uint4*)&wlo[(size_t)n * Kp + k0] = make_uint4(ll[0], ll[1], ll[2], ll[3]);
}

// ------------------------------ bf16-split tensor GEMM -----------------------
template<int ACT>
__global__ void __launch_bounds__(128) gemm_bf16_kernel(
        const float* __restrict__ A, const __nv_bfloat16* __restrict__ whi,
        const __nv_bfloat16* __restrict__ wlo, const float* __restrict__ bias,
        float* __restrict__ C, int K, int Kp, int Ncols) {
    const int SKW = 40;
    __shared__ __align__(16) __nv_bfloat16 Ahi[64][SKW], Alo[64][SKW],
                                           Bhi[64][SKW], Blo[64][SKW];
    int tid = threadIdx.x, lane = tid & 31, w = tid >> 5;
    int row0 = blockIdx.y * 64, col0 = blockIdx.x * 64;

    float acc[8][4];
#pragma unroll
    for (int nt = 0; nt < 8; nt++)
#pragma unroll
        for (int e = 0; e < 4; e++) acc[nt][e] = 0.f;

    const int ar = lane & 7, ah = (lane >> 3) & 1, akh = (lane >> 4) & 1;
    const int bn = (lane & 7) | (((lane >> 4) & 1) << 3), bh = (lane >> 3) & 1;
    const int m0 = w * 16;

    for (int k0 = 0; k0 < Kp; k0 += 32) {
#pragma unroll
        for (int s = 0; s < 4; s++) {
            int idx = tid + s * 128;
            int r = idx >> 3, c4 = idx & 7;
            int gk = k0 + c4 * 4;
            float4 v = make_float4(0.f, 0.f, 0.f, 0.f);
            if (gk < K) v = *(const float4*)(A + (size_t)(row0 + r) * K + gk);
            __nv_bfloat16 h0 = __float2bfloat16(v.x), h1 = __float2bfloat16(v.y);
            __nv_bfloat16 h2 = __float2bfloat16(v.z), h3 = __float2bfloat16(v.w);
            __nv_bfloat16 l0 = __float2bfloat16(v.x - __bfloat162float(h0));
            __nv_bfloat16 l1 = __float2bfloat16(v.y - __bfloat162float(h1));
            __nv_bfloat16 l2 = __float2bfloat16(v.z - __bfloat162float(h2));
            __nv_bfloat16 l3 = __float2bfloat16(v.w - __bfloat162float(h3));
            *(uint2*)&Ahi[r][c4 * 4] = make_uint2(packbf2(h0, h1), packbf2(h2, h3));
            *(uint2*)&Alo[r][c4 * 4] = make_uint2(packbf2(l0, l1), packbf2(l2, l3));
        }
#pragma unroll
        for (int s = 0; s < 2; s++) {
            int idx = tid + s * 128;
            int n = idx >> 2, c = idx & 3;
            size_t go = (size_t)(col0 + n) * Kp + k0 + c * 8;
            *(uint4*)&Bhi[n][c * 8] = *(const uint4*)&whi[go];
            *(uint4*)&Blo[n][c * 8] = *(const uint4*)&wlo[go];
        }
        __syncthreads();
#pragma unroll
        for (int kc = 0; kc < 2; kc++) {
            unsigned afh[4], afl[4];
            ldm4(afh[0], afh[1], afh[2], afh[3],
                 smem_u32(&Ahi[m0 + ar + 8 * ah][kc * 16 + 8 * akh]));
            ldm4(afl[0], afl[1], afl[2], afl[3],
                 smem_u32(&Alo[m0 + ar + 8 * ah][kc * 16 + 8 * akh]));
            unsigned bfh[8][2], bfl[8][2];
#pragma unroll
            for (int np = 0; np < 4; np++) {
                unsigned r0, r1, r2, r3;
                ldm4(r0, r1, r2, r3,
                     smem_u32(&Bhi[np * 16 + bn][kc * 16 + 8 * bh]));
                bfh[2 * np][0] = r0; bfh[2 * np][1] = r1;
                bfh[2 * np + 1][0] = r2; bfh[2 * np + 1][1] = r3;
                ldm4(r0, r1, r2, r3,
                     smem_u32(&Blo[np * 16 + bn][kc * 16 + 8 * bh]));
                bfl[2 * np][0] = r0; bfl[2 * np][1] = r1;
                bfl[2 * np + 1][0] = r2; bfl[2 * np + 1][1] = r3;
            }
#pragma unroll
            for (int nt = 0; nt < 8; nt++) {
                mma_bf16(acc[nt], afh, bfh[nt]);
                mma_bf16(acc[nt], afh, bfl[nt]);
                mma_bf16(acc[nt], afl, bfh[nt]);
            }
        }
        __syncthreads();
    }
    int r0e = row0 + m0 + (lane >> 2);
    int c0e = col0 + 2 * (lane & 3);
#pragma unroll
    for (int nt = 0; nt < 8; nt++)
#pragma unroll
        for (int e = 0; e < 4; e++) {
            int row = r0e + 8 * (e >> 1);
            int col = c0e + nt * 8 + (e & 1);
            if (col < Ncols) {
                float v = acc[nt][e] + bias[col];
                if (ACT == 1) v = selu_f(v);
                C[(size_t)row * Ncols + col] = v;
            }
        }
}

// ------------------------------ epilogue insert (kNN, min-gated) -------------
template<bool SELF>
__device__ __forceinline__ void epi_insert(float (&acc)[4][4], const float* sqb,
                                           const int (&jc16)[16], int j0,
                                           const int (&li2)[2],
                                           float (&cd)[2][4], int (&ci)[2][4]) {
#pragma unroll
    for (int nt = 0; nt < 4; nt++)
#pragma unroll
        for (int e = 0; e < 4; e++) {
            int jc = jc16[nt * 4 + e];
            float dv = __fmaf_rn(-2.f, acc[nt][e], sqb[jc]);
            if (SELF && (j0 + jc) == li2[e >> 1]) dv = 3.4e38f;
            acc[nt][e] = dv;
        }
    float mn0 = fminf(fminf(fminf(acc[0][0], acc[0][1]), fminf(acc[1][0], acc[1][1])),
                      fminf(fminf(acc[2][0], acc[2][1]), fminf(acc[3][0], acc[3][1])));
    float mn1 = fminf(fminf(fminf(acc[0][2], acc[0][3]), fminf(acc[1][2], acc[1][3])),
                      fminf(fminf(acc[2][2], acc[2][3]), fminf(acc[3][2], acc[3][3])));
    if (mn0 < cd[0][3]) {
#pragma unroll
        for (int nt = 0; nt < 4; nt++)
#pragma unroll
            for (int e = 0; e < 2; e++) {
                float d = acc[nt][e];
                if (d < cd[0][3]) {
                    int col = j0 + jc16[nt * 4 + e];
                    float vd = d; int vi = col;
#pragma unroll
                    for (int p = 0; p < 4; p++) {
                        if (vd < cd[0][p]) {
                            float td = cd[0][p]; int ti = ci[0][p];
                            cd[0][p] = vd; ci[0][p] = vi;
                            vd = td; vi = ti;
                        }
                    }
                }
            }
    }
    if (mn1 < cd[1][3]) {
#pragma unroll
        for (int nt = 0; nt < 4; nt++)
#pragma unroll
            for (int e = 2; e < 4; e++) {
                float d = acc[nt][e];
                if (d < cd[1][3]) {
                    int col = j0 + jc16[nt * 4 + e];
                    float vd = d; int vi = col;
#pragma unroll
                    for (int p = 0; p < 4; p++) {
                        if (vd < cd[1][p]) {
                            float td = cd[1][p]; int ti = ci[1][p];
                            cd[1][p] = vd; ci[1][p] = vi;
                            vd = td; vi = ti;
                        }
                    }
                }
            }
    }
}

// ------------------------------ mma.sync kNN candidates (K = 3C) -------------
template<int C>
__global__ void __launch_bounds__(128) knn_mma_kernel(
        const __nv_bfloat16* __restrict__ imgA, const __nv_bfloat16* __restrict__ imgB,
        const float* __restrict__ sq, float* __restrict__ candd,
        int* __restrict__ candi, int nper) {
    const int K   = 3 * C;
    const int SKW = K + 16;
    const int KC  = K / 16;
    const int JT  = 32;
    const int CH  = K / 8;
    const int SLOTS = JT * CH / 128;
    extern __shared__ __align__(16) __nv_bfloat16 sh[];
    __nv_bfloat16* Ash  = sh;
    __nv_bfloat16* Bsh  = sh + 64 * SKW;
    float*         sqsh = (float*)(Bsh + 2 * JT * SKW);

    int tid  = threadIdx.x;
    int lane = tid & 31, w = tid >> 5;
    int b = blockIdx.z, it = blockIdx.x, split = blockIdx.y;
    int ibase = it * 64;
    int gbase = b * nper;
    int jlen  = nper >> 2;
    int js    = split * jlen;
    const int NT = jlen / JT;

    for (int t = tid; t < 64 * CH; t += 128) {
        int r = t / CH, cc = t % CH;
        *(uint4*)&Ash[r * SKW + cc * 8] =
            *(const uint4*)&imgA[((size_t)(gbase + ibase + r)) * K + cc * 8];
    }

    unsigned sBoff[SLOTS]; unsigned gBoff[SLOTS];
#pragma unroll
    for (int s = 0; s < SLOTS; s++) {
        int q = tid + s * 128;
        int r = q / CH, cc = q % CH;
        sBoff[s] = (unsigned)((r * SKW + cc * 8) * 2);
        gBoff[s] = (unsigned)(r * K + cc * 8);
    }
    unsigned bufB[2] = { smem_u32(Bsh), smem_u32(Bsh + JT * SKW) };
    unsigned sqBuf[2] = { smem_u32(sqsh), smem_u32(sqsh + JT) };

    const __nv_bfloat16* gtile = imgB + (size_t)(gbase + js) * K;
    const float* gsq = sq + gbase + js;
#pragma unroll
    for (int s = 0; s < SLOTS; s++)
        cp_async16(bufB[0] + sBoff[s], gtile + gBoff[s]);
    if (tid < JT / 4)
        cp_async16(sqBuf[0] + tid * 16, gsq + tid * 4);
    cp_commit();
    const __nv_bfloat16* gnext = gtile + (size_t)JT * K;
    const float* gsqnext = gsq + JT;

    const int m0 = w * 16;
    int li2[2];
#pragma unroll
    for (int s = 0; s < 2; s++) li2[s] = ibase + m0 + (lane >> 2) + 8 * s;
    float cd[2][4]; int ci[2][4];
#pragma unroll
    for (int s = 0; s < 2; s++)
#pragma unroll
        for (int p = 0; p < 4; p++) { cd[s][p] = 3.4e38f; ci[s][p] = 0; }

    const int ar  = lane & 7;
    const int ah  = (lane >> 3) & 1;
    const int akh = (lane >> 4) & 1;
    const int bn  = (lane & 7) | (((lane >> 4) & 1) << 3);
    const int bh  = (lane >> 3) & 1;
    unsigned aBase = smem_u32(&Ash[(m0 + ar + 8 * ah) * SKW + 8 * akh]);
    unsigned bnOff = (unsigned)((bn * SKW + 8 * bh) * 2);

    int jc16[16];
#pragma unroll
    for (int nt = 0; nt < 4; nt++)
#pragma unroll
        for (int e = 0; e < 4; e++)
            jc16[nt * 4 + e] = nt * 8 + 2 * (lane & 3) + (e & 1);

    int j0 = js;
    for (int t = 0; t < NT; t++) {
        if (t + 1 < NT) {
            unsigned bb = bufB[(t + 1) & 1];
#pragma unroll
            for (int s = 0; s < SLOTS; s++)
                cp_async16(bb + sBoff[s], gnext + gBoff[s]);
            if (tid < JT / 4)
                cp_async16(sqBuf[(t + 1) & 1] + tid * 16, gsqnext + tid * 4);
            cp_commit();
            cp_wait1();
            gnext += (size_t)JT * K;
            gsqnext += JT;
        } else {
            cp_wait0();
        }
        __syncthreads();

        unsigned bBufBase = bufB[t & 1] + bnOff;
        const float* sqb = (t & 1) ? (sqsh + JT) : sqsh;

        float acc[4][4];
#pragma unroll
        for (int nt = 0; nt < 4; nt++)
#pragma unroll
            for (int e = 0; e < 4; e++) acc[nt][e] = 0.f;

#pragma unroll
        for (int kc = 0; kc < KC; kc++) {
            unsigned af[4];
            ldm4(af[0], af[1], af[2], af[3], aBase + kc * 32);
            unsigned bf[4][2];
#pragma unroll
            for (int np = 0; np < 2; np++) {
                unsigned r0, r1, r2, r3;
                ldm4(r0, r1, r2, r3, bBufBase + np * (16 * SKW * 2) + kc * 32);
                bf[2 * np][0] = r0; bf[2 * np][1] = r1;
                bf[2 * np + 1][0] = r2; bf[2 * np + 1][1] = r3;
            }
#pragma unroll
            for (int nt = 0; nt < 4; nt++)
                mma_bf16(acc[nt], af, bf[nt]);
        }

        bool ovl = (j0 < ibase + 64) && (j0 + JT > ibase);
        if (ovl) epi_insert<true >(acc, sqb, jc16, j0, li2, cd, ci);
        else     epi_insert<false>(acc, sqb, jc16, j0, li2, cd, ci);
        j0 += JT;
        __syncthreads();
    }
#pragma unroll
    for (int s = 0; s < 2; s++)
#pragma unroll
        for (int p = 0; p < 4; p++) {
            size_t base = ((size_t)(gbase + li2[s])) * 64 + split * 16 + (lane & 3) * 4 + p;
            candd[base] = cd[s][p];
            candi[base] = gbase + ci[s][p];
        }
}

// ------------------------------ warp-cooperative re-rank + wn ----------------
template<int C>
__global__ void rerank_kernel(const float* __restrict__ x, const float* __restrict__ sq,
                              const float* __restrict__ candd, const int* __restrict__ candi,
                              int* __restrict__ knn,
                              const float* __restrict__ ew, const float* __restrict__ dnv,
                              float* __restrict__ wn, int n) {
    int t = blockIdx.x * blockDim.x + threadIdx.x;
    int gi = t >> 3;
    int r8 = t & 7;
    if (gi >= n) return;

    const float* cdp = candd + (size_t)gi * 64 + r8 * 8;
    const int*   cip = candi + (size_t)gi * 64 + r8 * 8;
    float d8[8]; int i8[8];
#pragma unroll
    for (int p = 0; p < 8; p++) { d8[p] = cdp[p]; i8[p] = cip[p]; }

    unsigned taken = 0;
    float myD = 3.4e38f; int myI = 0;
#pragma unroll
    for (int r = 0; r < 8; r++) {
        float ld = 3.4e38f; int li = 0x7fffffff; int lp = -1;
#pragma unroll
        for (int p = 0; p < 8; p++) {
            if (!(taken & (1u << p)) &&
                (d8[p] < ld || (d8[p] == ld && i8[p] < li))) {
                ld = d8[p]; li = i8[p]; lp = p;
            }
        }
        float bd = ld; int bi = li; int bl = r8;
#pragma unroll
        for (int off = 4; off > 0; off >>= 1) {
            float od = __shfl_xor_sync(0xffffffffu, bd, off);
            int   oi = __shfl_xor_sync(0xffffffffu, bi, off);
            int   ol = __shfl_xor_sync(0xffffffffu, bl, off);
            if (od < bd || (od == bd && (oi < bi || (oi == bi && ol < bl)))) {
                bd = od; bi = oi; bl = ol;
            }
        }
        if (bl == r8 && lp >= 0) taken |= (1u << lp);
        if (r == r8) { myD = bd; myI = bi; }
    }

    const float* xi = x + (size_t)gi * C;
    const float* xr = x + (size_t)myI * C;
    float dot = 0.f;
#pragma unroll
    for (int c = 0; c < C; c++) dot = __fmaf_rn(__ldg(xi + c), __ldg(xr + c), dot);
    float dd = __fsub_rn(__fadd_rn(sq[gi], sq[myI]), __fmul_rn(2.f, dot));

    bool used = false;
    float dng = dnv[gi];
#pragma unroll
    for (int r = 0; r < 3; r++) {
        float bd = used ? 3.4e38f : dd;
        int   bi = used ? 0x7fffffff : myI;
        int   bl = r8;
#pragma unroll
        for (int off = 4; off > 0; off >>= 1) {
            float od = __shfl_xor_sync(0xffffffffu, bd, off);
            int   oi = __shfl_xor_sync(0xffffffffu, bi, off);
            int   ol = __shfl_xor_sync(0xffffffffu, bl, off);
            if (od < bd || (od == bd && (oi < bi || (oi == bi && ol < bl)))) {
                bd = od; bi = oi; bl = ol;
            }
        }
        if (bl == r8) used = true;
        if (r8 == 0) {
            knn[gi * 3 + r] = bi;
            wn [gi * 3 + r] = __fmul_rn(__fmul_rn(ew[gi * 3 + r], dng), dnv[bi]);
        }
    }
}

// ------------------------------ copy into Z slice (stage 1 only) -------------
__global__ void copy_slice_kernel(const float* __restrict__ src, float* __restrict__ Z,
                                  int Cq, int stride4, int total) {
    int idx = blockIdx.x * blockDim.x + threadIdx.x;
    if (idx >= total) return;
    int g = idx / Cq, q = idx % Cq;
    ((float4*)Z)[(size_t)g * stride4 + q] = ((const float4*)src)[(size_t)g * Cq + q];
}

// ------------------------------ Laplacian step -------------------------------
__global__ void lap_kernel(const float* __restrict__ Zin, const float* __restrict__ Zprev,
                           float* __restrict__ Zout, int stride, int Cq,
                           float alpha, float beta,
                           const int* __restrict__ knn, const float* __restrict__ wn,
                           int total) {
    int idx = blockIdx.x * blockDim.x + threadIdx.x;
    if (idx >= total) return;
    int g = idx / Cq, q = idx % Cq;
    int s0 = knn[3 * g], s1 = knn[3 * g + 1], s2 = knn[3 * g + 2];
    float w0 = wn[3 * g], w1 = wn[3 * g + 1], w2 = wn[3 * g + 2];
    float4 a0 = ((const float4*)(Zin + (size_t)s0 * stride))[q];
    float4 a1 = ((const float4*)(Zin + (size_t)s1 * stride))[q];
    float4 a2 = ((const float4*)(Zin + (size_t)s2 * stride))[q];
    float4 r;
    r.x = alpha * (-(w0 * a0.x + w1 * a1.x + w2 * a2.x));
    r.y = alpha * (-(w0 * a0.y + w1 * a1.y + w2 * a2.y));
    r.z = alpha * (-(w0 * a0.z + w1 * a1.z + w2 * a2.z));
    r.w = alpha * (-(w0 * a0.w + w1 * a1.w + w2 * a2.w));
    if (beta != 0.f) {
        float4 p = ((const float4*)(Zprev + (size_t)g * stride))[q];
        r.x += beta * p.x; r.y += beta * p.y; r.z += beta * p.z; r.w += beta * p.w;
    }
    ((float4*)(Zout + (size_t)g * stride))[q] = r;
}

// ------------------------------ fused copy + first lap (stage 2) -------------
__global__ void lap_first_kernel(const float* __restrict__ src, float* __restrict__ Z,
                                 int stride4, int Cq,
                                 const int* __restrict__ knn, const float* __restrict__ wn,
                                 int total) {
    int idx = blockIdx.x * blockDim.x + threadIdx.x;
    if (idx >= total) return;
    int g = idx / Cq, q = idx % Cq;
    int s0 = knn[3 * g], s1 = knn[3 * g + 1], s2 = knn[3 * g + 2];
    float w0 = wn[3 * g], w1 = wn[3 * g + 1], w2 = wn[3 * g + 2];
    const float4* s4 = (const float4*)src;
    float4 own = s4[(size_t)g * Cq + q];
    float4 a0 = s4[(size_t)s0 * Cq + q];
    float4 a1 = s4[(size_t)s1 * Cq + q];
    float4 a2 = s4[(size_t)s2 * Cq + q];
    float4 r;
    r.x = -(w0 * a0.x + w1 * a1.x + w2 * a2.x);
    r.y = -(w0 * a0.y + w1 * a1.y + w2 * a2.y);
    r.z = -(w0 * a0.z + w1 * a1.z + w2 * a2.z);
    r.w = -(w0 * a0.w + w1 * a1.w + w2 * a2.w);
    ((float4*)Z)[(size_t)g * stride4 + q]      = own;
    ((float4*)Z)[(size_t)g * stride4 + Cq + q] = r;
}

// ------------------------------ fp32 FFMA2 GEMM (conv0 only) ----------------
template<int ACT>
__global__ void gemm_kernel(const float* __restrict__ A, const float* __restrict__ B,
                            const float* __restrict__ bias, float* __restrict__ C,
                            int K, int Ncols) {
    __shared__ __align__(16) float As2[16][128];
    __shared__ __align__(16) float Bs[16][64];
    const int tid  = threadIdx.x;
    const int row0 = blockIdx.y * 64;
    const int col0 = blockIdx.x * 64;
    const int tx = tid & 15, ty = tid >> 4;
    unsigned long long acc2[4][2];
#pragma unroll
    for (int i = 0; i < 4; i++) { acc2[i][0] = 0ull; acc2[i][1] = 0ull; }

    const int lin  = tid * 4;
    const int arow = lin >> 4, acol = lin & 15;
    const int brow = lin >> 6, bcol = lin & 63;

    for (int k0 = 0; k0 < K; k0 += 16) {
        float4 av = make_float4(0.f, 0.f, 0.f, 0.f);
        if (k0 + acol < K)
            av = *(const float4*)(A + (size_t)(row0 + arow) * K + k0 + acol);
        *(float2*)&As2[acol + 0][2 * arow] = make_float2(av.x, av.x);
        *(float2*)&As2[acol + 1][2 * arow] = make_float2(av.y, av.y);
        *(float2*)&As2[acol + 2][2 * arow] = make_float2(av.z, av.z);
        *(float2*)&As2[acol + 3][2 * arow] = make_float2(av.w, av.w);

        float4 bv = make_float4(0.f, 0.f, 0.f, 0.f);
        int gk = k0 + brow, gc = col0 + bcol;
        if (gk < K && gc < Ncols)
            bv = *(const float4*)(B + (size_t)gk * Ncols + gc);
        *(float4*)&Bs[brow][bcol] = bv;
        __syncthreads();
#pragma unroll
        for (int kk = 0; kk < 16; kk++) {
            ulonglong2 a01 = *(const ulonglong2*)&As2[kk][ty * 8];
            ulonglong2 a23 = *(const ulonglong2*)&As2[kk][ty * 8 + 4];
            ulonglong2 bq  = *(const ulonglong2*)&Bs[kk][tx * 4];
            ffma2(acc2[0][0], a01.x, bq.x); ffma2(acc2[0][1], a01.x, bq.y);
            ffma2(acc2[1][0], a01.y, bq.x); ffma2(acc2[1][1], a01.y, bq.y);
            ffma2(acc2[2][0], a23.x, bq.x); ffma2(acc2[2][1], a23.x, bq.y);
            ffma2(acc2[3][0], a23.y, bq.x); ffma2(acc2[3][1], a23.y, bq.y);
        }
        __syncthreads();
    }
#pragma unroll
    for (int i = 0; i < 4; i++) {
        float a0, a1, a2, a3;
        unpack2(acc2[i][0], a0, a1);
        unpack2(acc2[i][1], a2, a3);
        float accs[4] = {a0, a1, a2, a3};
        int row = row0 + ty * 4 + i;
#pragma unroll
        for (int j = 0; j < 4; j++) {
            int col = col0 + tx * 4 + j;
            if (col < Ncols) {
                float v = accs[j] + bias[col];
                if (ACT == 1) v = selu_f(v);
                C[(size_t)row * Ncols + col] = v;
            }
        }
    }
}

// ------------------------------ GraphNorm -----------------------------------
__global__ void gn_reduce_kernel(const float* __restrict__ u, const float* __restrict__ alpha,
                                 float* __restrict__ amean, float* __restrict__ rstd) {
    int b = blockIdx.x;
    int t = threadIdx.x;               // 256
    int c = t & 63, rg = t >> 6;
    float s = 0.f;
    for (int n = rg; n < NG_; n += 4) s += u[((size_t)(b * NG_ + n)) * 64 + c];
    __shared__ float sh[256];
    sh[t] = s;
    __syncthreads();
    __shared__ float smean[64];
    if (t < 64) {
        s = sh[t] + sh[t + 64] + sh[t + 128] + sh[t + 192];
        smean[t] = s * (1.f / NG_);
    }
    __syncthreads();
    float am = alpha[c] * smean[c];
    float s2 = 0.f;
    for (int n = rg; n < NG_; n += 4) {
        float v = u[((size_t)(b * NG_ + n)) * 64 + c] - am;
        s2 += v * v;
    }
    sh[t] = s2;
    __syncthreads();
    if (t < 64) {
        s2 = sh[t] + sh[t + 64] + sh[t + 128] + sh[t + 192];
        float var = s2 * (1.f / NG_);
        amean[b * 64 + t] = alpha[t] * smean[t];
        rstd [b * 64 + t] = rsqrtf(var + 1e-5f);
    }
}

__global__ void gn_norm_kernel(float* __restrict__ u, const float* __restrict__ gamma,
                               const float* __restrict__ beta, const float* __restrict__ amean,
                               const float* __restrict__ rstd) {
    int idx = blockIdx.x * blockDim.x + threadIdx.x;
    if (idx >= N_TOT * 64) return;
    int g = idx >> 6, c = idx & 63;
    int b = g >> 12;   // /4096
    float v = u[idx];
    u[idx] = gamma[c] * (v - amean[b * 64 + c]) * rstd[b * 64 + c] + beta[c];
}

// ------------------------------ softmax rows (warp per row) ------------------
__global__ void softmax_kernel(const float* __restrict__ u, float* __restrict__ S) {
    int row = blockIdx.x * 4 + (threadIdx.x >> 5);
    int lane = threadIdx.x & 31;
    if (row >= N_TOT) return;
    const float* rp = u + (size_t)row * M_;
    float v0 = rp[lane], v1 = rp[lane + 32], v2 = rp[lane + 64];
    float v3 = (lane < 4) ? rp[lane + 96] : -3.4e38f;
    float m = fmaxf(fmaxf(v0, v1), fmaxf(v2, v3));
#pragma unroll
    for (int off = 16; off > 0; off >>= 1)
        m = fmaxf(m, __shfl_xor_sync(0xffffffffu, m, off));
    float e0 = expf(v0 - m), e1 = expf(v1 - m), e2 = expf(v2 - m);
    float e3 = (lane < 4) ? expf(v3 - m) : 0.f;
    float s = e0 + e1 + e2 + e3;
#pragma unroll
    for (int off = 16; off > 0; off >>= 1)
        s += __shfl_xor_sync(0xffffffffu, s, off);
    float inv = 1.f / s;
    float* so = S + (size_t)row * M_;
    so[lane] = e0 * inv; so[lane + 32] = e1 * inv; so[lane + 64] = e2 * inv;
    if (lane < 4) so[lane + 96] = e3 * inv;
}

// ------------------------------ DiffPool pooling (tiled, deterministic) ------
__global__ void pool_partial_kernel(const float* __restrict__ S, const float* __restrict__ x,
                                    float* __restrict__ part) {
    extern __shared__ float psm[];         // sS[128*100] + sX[128*32]
    float* sS = psm;
    float* sX = psm + 128 * M_;
    int b = blockIdx.y, nt = blockIdx.x, tid = threadIdx.x;
    size_t nbase = (size_t)(b * NG_ + nt * 128);
    const float4* gS = (const float4*)(S + nbase * M_);
    float4* s4 = (float4*)sS;
    for (int i = tid; i < 128 * M_ / 4; i += 128) s4[i] = gS[i];
    const float4* gX = (const float4*)(x + nbase * 32);
    float4* x4 = (float4*)sX;
    for (int i = tid; i < 128 * 32 / 4; i += 128) x4[i] = gX[i];
    __syncthreads();
    int ty = tid >> 5, tx = tid & 31;
    int mbase = ty * 25;
    float acc[25];
#pragma unroll
    for (int k = 0; k < 25; k++) acc[k] = 0.f;
    for (int n = 0; n < 128; n++) {
        float xv = sX[n * 32 + tx];
        const float* srow = &sS[n * M_ + mbase];
#pragma unroll
        for (int k = 0; k < 25; k++) acc[k] = __fmaf_rn(srow[k], xv, acc[k]);
    }
    float* po = part + ((size_t)nt * NP_ + b * M_) * 33;
#pragma unroll
    for (int k = 0; k < 25; k++) po[(mbase + k) * 33 + tx] = acc[k];
    if (tid < M_) {
        float s = 0.f;
        for (int n = 0; n < 128; n++) s += sS[n * M_ + tid];
        po[tid * 33 + 32] = s;
    }
}

__global__ void pool_reduce_kernel(const float* __restrict__ part, float* __restrict__ xp) {
    int idx = blockIdx.x * blockDim.x + threadIdx.x;
    if (idx >= NP_ * 32) return;
    int g = idx >> 5, c = idx & 31;
    float p = 0.f, s = 0.f;
    for (int t = 0; t < 32; t++) {
        const float* base = part + ((size_t)t * NP_ + g) * 33;
        p += base[c];
        s += base[32];
    }
    xp[idx] = p / s;
}

// ------------------------------ zero-init -----------------------------------
__global__ void zero2_kernel(float* a, float* b, int n) {
    int i = blockIdx.x * blockDim.x + threadIdx.x;
    if (i < n) { a[i] = 0.f; b[i] = 0.f; }
}

// ------------------------------ PPI edge conv -------------------------------
__global__ void ppi_conv_kernel(const float* __restrict__ xp, const int* __restrict__ connect,
                                const float* __restrict__ W2, const float* __restrict__ b2,
                                float* __restrict__ h) {
    __shared__ float feat[4][64];
    int t = threadIdx.x;
    int el = t >> 6, o = t & 63;
    int e = blockIdx.x * 4 + el;
    int dst = 0;
    if (e < B_ * E_PPI_) {
        int b = e / E_PPI_, le = e % E_PPI_;
        int s = connect[le] + b * M_;
        dst   = connect[E_PPI_ + le] + b * M_;
        float v;
        if (o < 32) v = xp[dst * 32 + o];
        else        v = xp[s * 32 + (o - 32)] - xp[dst * 32 + (o - 32)];
        feat[el][o] = v;
    }
    __syncthreads();
    if (e < B_ * E_PPI_) {
        float s = b2[o];
#pragma unroll
        for (int k = 0; k < 64; k++) s += feat[el][k] * W2[k * 64 + o];
        s = fmaxf(s, 0.f);
        atomicMax((int*)&h[dst * 64 + o], __float_as_int(s));
    }
}

// ------------------------------ small kNN on pooled graphs (100 nodes) ------
__global__ void knn_small_kernel(const float* __restrict__ h, int* __restrict__ knn2) {
    __shared__ float xsf[M_ * 64];
    __shared__ float sqs[M_];
    int b = blockIdx.x, t = threadIdx.x;   // 128 threads
    const float4* src4 = (const float4*)(h + (size_t)b * M_ * 64);
    float4* dst4 = (float4*)xsf;
    for (int idx = t; idx < M_ * 16; idx += 128) dst4[idx] = src4[idx];
    __syncthreads();
    if (t < M_) {
        const float* r = xsf + t * 64;
        float p[32];
#pragma unroll
        for (int q = 0; q < 32; q++) {
            float a = __fmaf_rn(r[2 * q], r[2 * q], 0.f);
            p[q] = __fmaf_rn(r[2 * q + 1], r[2 * q + 1], a);
        }
#pragma unroll
        for (int off = 16; off > 0; off >>= 1)
#pragma unroll
            for (int c = 0; c < 16; c++)
                if (c < off) p[c] = __fadd_rn(p[c], p[c + off]);
        sqs[t] = p[0];
    }
    __syncthreads();
    if (t < M_) {
        float sqi = sqs[t];
        float bd0 = 3.4e38f, bd1 = 3.4e38f, bd2 = 3.4e38f;
        int bi0 = 0, bi1 = 0, bi2 = 0;
        for (int j = 0; j < M_; j++) {
            if (j == t) continue;
            float dot = 0.f;
#pragma unroll
            for (int c = 0; c < 64; c++)
                dot = __fmaf_rn(xsf[t * 64 + c], xsf[j * 64 + c], dot);
            float t1 = __fadd_rn(sqi, sqs[j]);
            float t2 = __fmul_rn(2.f, dot);
            float d  = __fsub_rn(t1, t2);
            if (d < bd2) {
                if (d < bd0)      { bd2=bd1; bi2=bi1; bd1=bd0; bi1=bi0; bd0=d; bi0=j; }
                else if (d < bd1) { bd2=bd1; bi2=bi1; bd1=d;   bi1=j; }
                else              { bd2=d;   bi2=j; }
            }
        }
        int g = b * M_ + t;
        knn2[g * 3 + 0] = b * M_ + bi0;
        knn2[g * 3 + 1] = b * M_ + bi1;
        knn2[g * 3 + 2] = b * M_ + bi2;
    }
}

// ------------------------------ dynamic edge conv ---------------------------
__global__ void dyn_conv_kernel(const float* __restrict__ h, const int* __restrict__ knn2,
                                const float* __restrict__ W3, const float* __restrict__ b3,
                                float* __restrict__ y) {
    __shared__ float feat[2][128];
    int t = threadIdx.x;
    int e0 = blockIdx.x * 2;
#pragma unroll
    for (int p = 0; p < 2; p++) {
        int e = e0 + p;
        if (e < NP_ * 3) {
            int g = e / 3;
            int src = knn2[e];
            int c = t;
            float v = (c < 64) ? h[g * 64 + c] : (h[src * 64 + (c - 64)] - h[g * 64 + (c - 64)]);
            feat[p][c] = v;
        }
    }
    __syncthreads();
    int el = t >> 6, o = t & 63;
    int e = e0 + el;
    if (e < NP_ * 3) {
        int g = e / 3;
        float s = b3[o];
#pragma unroll
        for (int k = 0; k < 128; k++) s += feat[el][k] * W3[k * 64 + o];
        s = fmaxf(s, 0.f);
        atomicMax((int*)&y[g * 64 + o], __float_as_int(s));
    }
}

// ------------------------------ final MLP (f2) ------------------------------
__global__ void final_mlp_kernel(const float* __restrict__ h, const float* __restrict__ y,
                                 const float* __restrict__ w1, const float* __restrict__ b1,
                                 const float* __restrict__ w2, const float* __restrict__ b2,
                                 const float* __restrict__ w3, const float* __restrict__ b3,
                                 float* __restrict__ out) {
    int r = blockIdx.x * blockDim.x + threadIdx.x;
    if (r >= NP_) return;
    float z[64];
#pragma unroll
    for (int c = 0; c < 64; c++) z[c] = h[r * 64 + c] + y[r * 64 + c];
    float a1[32];
#pragma unroll
    for (int o = 0; o < 32; o++) {
        float s = b1[o];
        for (int k = 0; k < 64; k++) s += z[k] * w1[k * 32 + o];
        a1[o] = selu_f(s);
    }
    float a2[16];
#pragma unroll
    for (int o = 0; o < 16; o++) {
        float s = b2[o];
        for (int k = 0; k < 32; k++) s += a1[k] * w2[k * 16 + o];
        a2[o] = selu_f(s);
    }
#pragma unroll
    for (int o = 0; o < 16; o++) {
        float s = b3[o];
        for (int k = 0; k < 16; k++) s += a2[k] * w3[k * 16 + o];
        out[r * 16 + o] = s;
    }
}

// ------------------------------ host orchestration --------------------------
template<typename T>
static T* sym_addr(const void* sym) {
    void* p = nullptr;
    cudaGetSymbolAddress(&p, sym);
    return (T*)p;
}

extern "C" void kernel_launch(void* const* d_in, const int* in_sizes, int n_in,
                              void* d_out, int out_size) {
    const float* x    = (const float*)d_in[0];
    const float* ew   = (const float*)d_in[1];
    const int*   conn = (const int*)d_in[3];
    const float* W0   = (const float*)d_in[4];
    const float* b0   = (const float*)d_in[5];
    const float* gna  = (const float*)d_in[6];
    const float* gng  = (const float*)d_in[7];
    const float* gnb  = (const float*)d_in[8];
    const float* W1   = (const float*)d_in[9];
    const float* b1c  = (const float*)d_in[10];
    const float* f1w1 = (const float*)d_in[11];
    const float* f1b1 = (const float*)d_in[12];
    const float* f1w2 = (const float*)d_in[13];
    const float* f1b2 = (const float*)d_in[14];
    const float* f1w3 = (const float*)d_in[15];
    const float* f1b3 = (const float*)d_in[16];
    const float* W2   = (const float*)d_in[17];
    const float* b2   = (const float*)d_in[18];
    const float* W3   = (const float*)d_in[19];
    const float* b3   = (const float*)d_in[20];
    const float* f2w1 = (const float*)d_in[21];
    const float* f2b1 = (const float*)d_in[22];
    const float* f2w2 = (const float*)d_in[23];
    const float* f2b2 = (const float*)d_in[24];
    const float* f2w3 = (const float*)d_in[25];
    const float* f2b3 = (const float*)d_in[26];

    float* out_u = (float*)d_out;                       // [32768, 100]
    float* out_v = out_u + (size_t)N_TOT * M_;          // [800, 16]

    float* sq    = sym_addr<float>(g_sq);
    int*   knn   = sym_addr<int>(g_knn);
    int*   cand  = sym_addr<int>(g_cand);
    float* cdist = sym_addr<float>(g_cdist);
    float* dn    = sym_addr<float>(g_dn);
    float* wn    = sym_addr<float>(g_wn);
    float* Z     = sym_addr<float>(g_Z);
    float* u0    = sym_addr<float>(g_u0);
    float* u1    = sym_addr<float>(g_u1);
    float* t1    = sym_addr<float>(g_t1);
    float* t2    = sym_addr<float>(g_t2);
    float* S     = sym_addr<float>(g_S);
    float* amean = sym_addr<float>(g_amean);
    float* rstd  = sym_addr<float>(g_rstd);
    float* xp    = sym_addr<float>(g_xp);
    float* h     = sym_addr<float>(g_h);
    float* y     = sym_addr<float>(g_y);
    int*   knn2  = sym_addr<int>(g_knn2);
    float* ppart = sym_addr<float>(g_poolpart);
    __nv_bfloat16* imgA = sym_addr<__nv_bfloat16>(g_imgA);
    __nv_bfloat16* imgB = sym_addr<__nv_bfloat16>(g_imgB);
    __nv_bfloat16* whi  = sym_addr<__nv_bfloat16>(g_whi);
    __nv_bfloat16* wlo  = sym_addr<__nv_bfloat16>(g_wlo);

    // K = 3C images: SKW = 3C+16
    const int SM32 = 64 * 112 * 2 + 2 * 32 * 112 * 2 + 2 * 32 * 4;  // 28928 B
    const int SM64 = 64 * 208 * 2 + 2 * 32 * 208 * 2 + 2 * 32 * 4;  // 53504 B
    const int SMPOOL = 128 * (M_ + 32) * 4;                          // 67584 B
    static bool attr_done = false;
    if (!attr_done) {
        cudaFuncSetAttribute(knn_mma_kernel<64>,
                             cudaFuncAttributeMaxDynamicSharedMemorySize, SM64);
        cudaFuncSetAttribute(pool_partial_kernel,
                             cudaFuncAttributeMaxDynamicSharedMemorySize, SMPOOL);
        attr_done = true;
    }

    // ---- stage 1: kNN on x (C=32)  (dn fused into sqprep32)
    sqprep32_kernel<<<(N_TOT + 127) / 128, 128>>>(x, sq, imgA, imgB, ew, dn);
    knn_mma_kernel<32><<<dim3(NG_ / 64, 4, B_), 128, SM32>>>(imgA, imgB, sq, cdist, cand, NG_);
    rerank_kernel<32><<<(N_TOT * 8 + 255) / 256, 256>>>(x, sq, cdist, cand, knn, ew, dn, wn, N_TOT);

    // ---- conv0: Chebyshev terms into Z (N x 128), fp32 GEMM (u0 bit-exact)
    {
        int total = N_TOT * 8;   // N * C/4, C=32
        copy_slice_kernel<<<(total + 255) / 256, 256>>>(x, Z, 8, 32, total);
        lap_kernel<<<(total + 255) / 256, 256>>>(Z + 0,  Z,       Z + 32, 128, 8, 1.f,  0.f, knn, wn, total);
        lap_kernel<<<(total + 255) / 256, 256>>>(Z + 32, Z + 0,   Z + 64, 128, 8, 2.f, -1.f, knn, wn, total);
        lap_kernel<<<(total + 255) / 256, 256>>>(Z + 64, Z + 32,  Z + 96, 128, 8, 2.f, -1.f, knn, wn, total);
        gemm_kernel<0><<<dim3(1, N_TOT / 64), 256>>>(Z, W0, b0, u0, 128, 64);
    }

    // ---- GraphNorm (unchanged; u0 bits preserved)
    gn_reduce_kernel<<<B_, 256>>>(u0, gna, amean, rstd);
    gn_norm_kernel<<<(N_TOT * 64) / 256, 256>>>(u0, gng, gnb, amean, rstd);

    // ---- stage 2: kNN on u0 (C=64)
    sqprep64_kernel<<<(N_TOT + 127) / 128, 128>>>(u0, sq, imgA, imgB);
    knn_mma_kernel<64><<<dim3(NG_ / 64, 4, B_), 128, SM64>>>(imgA, imgB, sq, cdist, cand, NG_);
    rerank_kernel<64><<<(N_TOT * 8 + 255) / 256, 256>>>(u0, sq, cdist, cand, knn, ew, dn, wn, N_TOT);

    // ---- conv1: fused copy+lap, laps, bf16-split tensor GEMM -> u1
    {
        int total = N_TOT * 16;  // N * C/4, C=64
        lap_first_kernel<<<(total + 255) / 256, 256>>>(u0, Z, 64, 16, knn, wn, total);
        lap_kernel<<<(total + 255) / 256, 256>>>(Z + 64,  Z + 0,    Z + 128, 256, 16, 2.f, -1.f, knn, wn, total);
        lap_kernel<<<(total + 255) / 256, 256>>>(Z + 128, Z + 64,   Z + 192, 256, 16, 2.f, -1.f, knn, wn, total);
        prep_w_kernel<<<(448 * 32 + 255) / 256, 256>>>(W1, whi, wlo, 256, 400, 256, 448);
        gemm_bf16_kernel<0><<<dim3(7, N_TOT / 64), 128>>>(Z, whi, wlo, b1c, u1, 256, 256, 400);
    }

    // ---- fc1 MLP: 400 -> 200 -> 100 -> 100 (bf16-split tensor GEMMs)
    prep_w_kernel<<<(256 * 52 + 255) / 256, 256>>>(f1w1, whi, wlo, 400, 200, 416, 256);
    gemm_bf16_kernel<1><<<dim3(4, N_TOT / 64), 128>>>(u1, whi, wlo, f1b1, t1, 400, 416, 200);
    prep_w_kernel<<<(128 * 28 + 255) / 256, 256>>>(f1w2, whi, wlo, 200, 100, 224, 128);
    gemm_bf16_kernel<1><<<dim3(2, N_TOT / 64), 128>>>(t1, whi, wlo, f1b2, t2, 200, 224, 100);
    prep_w_kernel<<<(128 * 16 + 255) / 256, 256>>>(f1w3, whi, wlo, 100, 100, 128, 128);
    gemm_bf16_kernel<0><<<dim3(2, N_TOT / 64), 128>>>(t2, whi, wlo, f1b3, out_u, 100, 128, 100);

    // ---- DiffPool soft pooling (tiled partials + deterministic reduce)
    softmax_kernel<<<N_TOT / 4, 128>>>(out_u, S);
    pool_partial_kernel<<<dim3(NG_ / 128, B_), 128, SMPOOL>>>(S, x, ppart);
    pool_reduce_kernel<<<(NP_ * 32 + 255) / 256, 256>>>(ppart, xp);

    // ---- PPI edge conv + dynamic edge conv
    zero2_kernel<<<(NP_ * HID_ + 255) / 256, 256>>>(h, y, NP_ * HID_);
    ppi_conv_kernel<<<(B_ * E_PPI_ + 3) / 4, 256>>>(xp, conn, W2, b2, h);
    knn_small_kernel<<<B_, 128>>>(h, knn2);
    dyn_conv_kernel<<<(NP_ * 3 + 1) / 2, 128>>>(h, knn2, W3, b3, y);

    // ---- final MLP -> v
    final_mlp_kernel<<<(NP_ + 127) / 128, 128>>>(h, y, f2w1, f2b1, f2w2, f2b2,
                                                 f2w3, f2b3, out_v);
}

// round 16
// speedup vs baseline: 1.4051x; 1.0441x over previous
#include <cuda_runtime.h>
#include <cuda_bf16.h>
#include <math.h>
#include <stdint.h>

#define N_TOT 32768
#define B_    8
#define NG_   4096
#define KNN_  3
#define IN_CH_ 32
#define HID_  64
#define M_    100
#define OUT_CH_ 16
#define NP_   800      // B*M pooled nodes
#define E_PPI_ 600

// ------------------------------ scratch (device globals; no allocs) ---------
__device__ float g_sq[N_TOT];
__device__ int   g_knn[N_TOT * 3];
__device__ int   g_cand [N_TOT * 64];
__device__ float g_cdist[N_TOT * 64];
__device__ float g_dn[N_TOT];
__device__ float g_wn[N_TOT * 3];
__device__ float g_Z[(size_t)N_TOT * 256];
__device__ float g_u0[(size_t)N_TOT * 64];
__device__ float g_u1[(size_t)N_TOT * 400];
__device__ float g_t1[(size_t)N_TOT * 200];
__device__ float g_t2[(size_t)N_TOT * 100];
__device__ float g_S [(size_t)N_TOT * 100];
__device__ float g_amean[B_ * HID_];
__device__ float g_rstd [B_ * HID_];
__device__ float g_xp[NP_ * IN_CH_];
__device__ float g_h [NP_ * HID_];
__device__ float g_y [NP_ * HID_];
__device__ int   g_knn2[NP_ * 3];
__device__ float g_poolpart[32 * NP_ * 33];   // [ntile][g][c(32)+ssum]
// bf16 split images for kNN, row-major [N][K<=192]
__device__ __nv_bfloat16 g_imgA[(size_t)N_TOT * 192];
__device__ __nv_bfloat16 g_imgB[(size_t)N_TOT * 192];
// bf16 split weight images for GEMM, row-major [Nimg][Kp] (max 448*416)
__device__ __nv_bfloat16 g_whi[448 * 416];
__device__ __nv_bfloat16 g_wlo[448 * 416];

// ------------------------------ helpers -------------------------------------
__device__ __forceinline__ float selu_f(float x) {
    const float sc = 1.0507009873554804934193349852946f;
    const float al = 1.6732632423543772848170429916717f;
    return x > 0.f ? sc * x : sc * al * expm1f(x);
}

__device__ __forceinline__ void ffma2(unsigned long long& d,
                                      unsigned long long a,
                                      unsigned long long b) {
    asm("fma.rn.f32x2 %0, %1, %2, %3;" : "=l"(d) : "l"(a), "l"(b), "l"(d));
}
__device__ __forceinline__ void unpack2(unsigned long long v, float& lo, float& hi) {
    unsigned int a, b;
    asm("mov.b64 {%0, %1}, %2;" : "=r"(a), "=r"(b) : "l"(v));
    lo = __uint_as_float(a); hi = __uint_as_float(b);
}

__device__ __forceinline__ unsigned int smem_u32(const void* p) {
    unsigned int a;
    asm("{ .reg .u64 t; cvta.to.shared.u64 t, %1; cvt.u32.u64 %0, t; }"
        : "=r"(a) : "l"(p));
    return a;
}
__device__ __forceinline__ void ldm4(unsigned& r0, unsigned& r1, unsigned& r2,
                                     unsigned& r3, unsigned addr) {
    asm volatile("ldmatrix.sync.aligned.m8n8.x4.shared.b16 {%0,%1,%2,%3}, [%4];"
                 : "=r"(r0), "=r"(r1), "=r"(r2), "=r"(r3) : "r"(addr));
}
__device__ __forceinline__ void mma_bf16(float* d, const unsigned* a, const unsigned* b) {
    asm volatile("mma.sync.aligned.m16n8k16.row.col.f32.bf16.bf16.f32 "
        "{%0,%1,%2,%3}, {%4,%5,%6,%7}, {%8,%9}, {%0,%1,%2,%3};"
        : "+f"(d[0]), "+f"(d[1]), "+f"(d[2]), "+f"(d[3])
        : "r"(a[0]), "r"(a[1]), "r"(a[2]), "r"(a[3]), "r"(b[0]), "r"(b[1]));
}
__device__ __forceinline__ void cp_async16(unsigned int saddr, const void* g) {
    asm volatile("cp.async.cg.shared.global [%0], [%1], 16;"
                 :: "r"(saddr), "l"(g));
}
__device__ __forceinline__ void cp_commit() {
    asm volatile("cp.async.commit_group;");
}
__device__ __forceinline__ void cp_wait1() {
    asm volatile("cp.async.wait_group 1;");
}
__device__ __forceinline__ void cp_wait0() {
    asm volatile("cp.async.wait_group 0;");
}
__device__ __forceinline__ unsigned packbf2(__nv_bfloat16 a, __nv_bfloat16 b) {
    return (unsigned)__bfloat16_as_ushort(a)
         | ((unsigned)__bfloat16_as_ushort(b) << 16);
}

// ---- fused sq-norm + dn + bf16-split image prep (stage 1, C=32, K=96) ------
__global__ void sqprep32_kernel(const float* __restrict__ x, float* __restrict__ sq,
                                __nv_bfloat16* __restrict__ imgA,
                                __nv_bfloat16* __restrict__ imgB,
                                const float* __restrict__ ew, float* __restrict__ dn) {
    int gi = blockIdx.x * blockDim.x + threadIdx.x;
    if (gi >= N_TOT) return;
    {
        float d = ew[3 * gi] + ew[3 * gi + 1] + ew[3 * gi + 2];
        dn[gi] = d > 0.f ? rsqrtf(fmaxf(d, 1e-12f)) : 0.f;
    }
    const float4* r4 = (const float4*)(x + (size_t)gi * 32);
    uint4* a4 = (uint4*)(imgA + (size_t)gi * 96);
    uint4* b4 = (uint4*)(imgB + (size_t)gi * 96);
    float p[32];
#pragma unroll
    for (int t = 0; t < 4; t++) {
        float4 va = r4[2 * t], vb = r4[2 * t + 1];
        float vv[8] = {va.x, va.y, va.z, va.w, vb.x, vb.y, vb.z, vb.w};
        unsigned hw[4], lw[4];
#pragma unroll
        for (int i = 0; i < 4; i++) {
            float v0 = vv[2 * i], v1 = vv[2 * i + 1];
            __nv_bfloat16 h0 = __float2bfloat16(v0), h1 = __float2bfloat16(v1);
            __nv_bfloat16 l0 = __float2bfloat16(v0 - __bfloat162float(h0));
            __nv_bfloat16 l1 = __float2bfloat16(v1 - __bfloat162float(h1));
            hw[i] = packbf2(h0, h1);
            lw[i] = packbf2(l0, l1);
        }
#pragma unroll
        for (int i = 0; i < 8; i++) p[8 * t + i] = __fmul_rn(vv[i], vv[i]);
        uint4 H = make_uint4(hw[0], hw[1], hw[2], hw[3]);
        uint4 L = make_uint4(lw[0], lw[1], lw[2], lw[3]);
        a4[t] = H; a4[4 + t] = H; a4[8 + t] = L;   // A: [hi|hi|lo]
        b4[t] = H; b4[4 + t] = L; b4[8 + t] = H;   // B: [hi|lo|hi]
    }
#pragma unroll
    for (int off = 16; off > 0; off >>= 1)
#pragma unroll
        for (int c = 0; c < 16; c++)
            if (c < off) p[c] = __fadd_rn(p[c], p[c + off]);
    sq[gi] = p[0];
}

// ---- fused sq-norm + image prep (stage 2, C=64, K=192) ---------------------
__global__ void sqprep64_kernel(const float* __restrict__ u, float* __restrict__ sq,
                                __nv_bfloat16* __restrict__ imgA,
                                __nv_bfloat16* __restrict__ imgB) {
    int gi = blockIdx.x * blockDim.x + threadIdx.x;
    if (gi >= N_TOT) return;
    const float4* r4 = (const float4*)(u + (size_t)gi * 64);
    uint4* a4 = (uint4*)(imgA + (size_t)gi * 192);
    uint4* b4 = (uint4*)(imgB + (size_t)gi * 192);
    float p[32];
#pragma unroll
    for (int t = 0; t < 8; t++) {
        float4 va = r4[2 * t], vb = r4[2 * t + 1];
        float vv[8] = {va.x, va.y, va.z, va.w, vb.x, vb.y, vb.z, vb.w};
        unsigned hw[4], lw[4];
#pragma unroll
        for (int i = 0; i < 4; i++) {
            float v0 = vv[2 * i], v1 = vv[2 * i + 1];
            __nv_bfloat16 h0 = __float2bfloat16(v0), h1 = __float2bfloat16(v1);
            __nv_bfloat16 l0 = __float2bfloat16(v0 - __bfloat162float(h0));
            __nv_bfloat16 l1 = __float2bfloat16(v1 - __bfloat162float(h1));
            hw[i] = packbf2(h0, h1);
            lw[i] = packbf2(l0, l1);
        }
        float a0 = __fmaf_rn(vv[0], vv[0], 0.f);
        p[4 * t + 0] = __fmaf_rn(vv[1], vv[1], a0);
        float a1 = __fmaf_rn(vv[2], vv[2], 0.f);
        p[4 * t + 1] = __fmaf_rn(vv[3], vv[3], a1);
        float a2 = __fmaf_rn(vv[4], vv[4], 0.f);
        p[4 * t + 2] = __fmaf_rn(vv[5], vv[5], a2);
        float a3 = __fmaf_rn(vv[6], vv[6], 0.f);
        p[4 * t + 3] = __fmaf_rn(vv[7], vv[7], a3);
        uint4 H = make_uint4(hw[0], hw[1], hw[2], hw[3]);
        uint4 L = make_uint4(lw[0], lw[1], lw[2], lw[3]);
        a4[t] = H; a4[8 + t] = H; a4[16 + t] = L;  // A: [hi|hi|lo]
        b4[t] = H; b4[8 + t] = L; b4[16 + t] = H;  // B: [hi|lo|hi]
    }
#pragma unroll
    for (int off = 16; off > 0; off >>= 1)
#pragma unroll
        for (int c = 0; c < 16; c++)
            if (c < off) p[c] = __fadd_rn(p[c], p[c + off]);
    sq[gi] = p[0];
}

// ------------------------------ weight split prep (GEMM) ---------------------
__global__ void prep_w_kernel(const float* __restrict__ W,
                              __nv_bfloat16* __restrict__ whi,
                              __nv_bfloat16* __restrict__ wlo,
                              int K, int N, int Kp, int Nimg) {
    int idx = blockIdx.x * blockDim.x + threadIdx.x;
    int total = Nimg * (Kp / 8);
    if (idx >= total) return;
    int n = idx / (Kp / 8), k0 = (idx % (Kp / 8)) * 8;
    unsigned hh[4], ll[4];
#pragma unroll
    for (int e = 0; e < 4; e++) {
        float v0 = 0.f, v1 = 0.f;
        int k = k0 + 2 * e;
        if (n < N && k < K)     v0 = W[(size_t)k * N + n];
        if (n < N && k + 1 < K) v1 = W[(size_t)(k + 1) * N + n];
        __nv_bfloat16 h0 = __float2bfloat16(v0), h1 = __float2bfloat16(v1);
        __nv_bfloat16 l0 = __float2bfloat16(v0 - __bfloat162float(h0));
        __nv_bfloat16 l1 = __float2bfloat16(v1 - __bfloat162float(h1));
        hh[e] = packbf2(h0, h1);
        ll[e] = packbf2(l0, l1);
    }
    *(uint4*)&whi[(size_t)n * Kp + k0] = make_uint4(hh[0], hh[1], hh[2], hh[3]);
    *(uint4*)&wlo[(size_t)n * Kp + k0] = make_uint4(ll[0], ll[1], ll[2], ll[3]);
}

// ------------------------------ bf16-split tensor GEMM -----------------------
template<int ACT>
__global__ void __launch_bounds__(128) gemm_bf16_kernel(
        const float* __restrict__ A, const __nv_bfloat16* __restrict__ whi,
        const __nv_bfloat16* __restrict__ wlo, const float* __restrict__ bias,
        float* __restrict__ C, int K, int Kp, int Ncols) {
    const int SKW = 40;
    __shared__ __align__(16) __nv_bfloat16 Ahi[64][SKW], Alo[64][SKW],
                                           Bhi[64][SKW], Blo[64][SKW];
    int tid = threadIdx.x, lane = tid & 31, w = tid >> 5;
    int row0 = blockIdx.y * 64, col0 = blockIdx.x * 64;

    float acc[8][4];
#pragma unroll
    for (int nt = 0; nt < 8; nt++)
#pragma unroll
        for (int e = 0; e < 4; e++) acc[nt][e] = 0.f;

    const int ar = lane & 7, ah = (lane >> 3) & 1, akh = (lane >> 4) & 1;
    const int bn = (lane & 7) | (((lane >> 4) & 1) << 3), bh = (lane >> 3) & 1;
    const int m0 = w * 16;

    for (int k0 = 0; k0 < Kp; k0 += 32) {
#pragma unroll
        for (int s = 0; s < 4; s++) {
            int idx = tid + s * 128;
            int r = idx >> 3, c4 = idx & 7;
            int gk = k0 + c4 * 4;
            float4 v = make_float4(0.f, 0.f, 0.f, 0.f);
            if (gk < K) v = *(const float4*)(A + (size_t)(row0 + r) * K + gk);
            __nv_bfloat16 h0 = __float2bfloat16(v.x), h1 = __float2bfloat16(v.y);
            __nv_bfloat16 h2 = __float2bfloat16(v.z), h3 = __float2bfloat16(v.w);
            __nv_bfloat16 l0 = __float2bfloat16(v.x - __bfloat162float(h0));
            __nv_bfloat16 l1 = __float2bfloat16(v.y - __bfloat162float(h1));
            __nv_bfloat16 l2 = __float2bfloat16(v.z - __bfloat162float(h2));
            __nv_bfloat16 l3 = __float2bfloat16(v.w - __bfloat162float(h3));
            *(uint2*)&Ahi[r][c4 * 4] = make_uint2(packbf2(h0, h1), packbf2(h2, h3));
            *(uint2*)&Alo[r][c4 * 4] = make_uint2(packbf2(l0, l1), packbf2(l2, l3));
        }
#pragma unroll
        for (int s = 0; s < 2; s++) {
            int idx = tid + s * 128;
            int n = idx >> 2, c = idx & 3;
            size_t go = (size_t)(col0 + n) * Kp + k0 + c * 8;
            *(uint4*)&Bhi[n][c * 8] = *(const uint4*)&whi[go];
            *(uint4*)&Blo[n][c * 8] = *(const uint4*)&wlo[go];
        }
        __syncthreads();
#pragma unroll
        for (int kc = 0; kc < 2; kc++) {
            unsigned afh[4], afl[4];
            ldm4(afh[0], afh[1], afh[2], afh[3],
                 smem_u32(&Ahi[m0 + ar + 8 * ah][kc * 16 + 8 * akh]));
            ldm4(afl[0], afl[1], afl[2], afl[3],
                 smem_u32(&Alo[m0 + ar + 8 * ah][kc * 16 + 8 * akh]));
            unsigned bfh[8][2], bfl[8][2];
#pragma unroll
            for (int np = 0; np < 4; np++) {
                unsigned r0, r1, r2, r3;
                ldm4(r0, r1, r2, r3,
                     smem_u32(&Bhi[np * 16 + bn][kc * 16 + 8 * bh]));
                bfh[2 * np][0] = r0; bfh[2 * np][1] = r1;
                bfh[2 * np + 1][0] = r2; bfh[2 * np + 1][1] = r3;
                ldm4(r0, r1, r2, r3,
                     smem_u32(&Blo[np * 16 + bn][kc * 16 + 8 * bh]));
                bfl[2 * np][0] = r0; bfl[2 * np][1] = r1;
                bfl[2 * np + 1][0] = r2; bfl[2 * np + 1][1] = r3;
            }
#pragma unroll
            for (int nt = 0; nt < 8; nt++) {
                mma_bf16(acc[nt], afh, bfh[nt]);
                mma_bf16(acc[nt], afh, bfl[nt]);
                mma_bf16(acc[nt], afl, bfh[nt]);
            }
        }
        __syncthreads();
    }
    int r0e = row0 + m0 + (lane >> 2);
    int c0e = col0 + 2 * (lane & 3);
#pragma unroll
    for (int nt = 0; nt < 8; nt++)
#pragma unroll
        for (int e = 0; e < 4; e++) {
            int row = r0e + 8 * (e >> 1);
            int col = c0e + nt * 8 + (e & 1);
            if (col < Ncols) {
                float v = acc[nt][e] + bias[col];
                if (ACT == 1) v = selu_f(v);
                C[(size_t)row * Ncols + col] = v;
            }
        }
}

// ------------------------------ epilogue insert (kNN, min-gated) -------------
template<bool SELF>
__device__ __forceinline__ void epi_insert(float (&acc)[4][4], const float* sqb,
                                           const int (&jc16)[16], int j0,
                                           const int (&li2)[2],
                                           float (&cd)[2][4], int (&ci)[2][4]) {
#pragma unroll
    for (int nt = 0; nt < 4; nt++)
#pragma unroll
        for (int e = 0; e < 4; e++) {
            int jc = jc16[nt * 4 + e];
            float dv = __fmaf_rn(-2.f, acc[nt][e], sqb[jc]);
            if (SELF && (j0 + jc) == li2[e >> 1]) dv = 3.4e38f;
            acc[nt][e] = dv;
        }
    float mn0 = fminf(fminf(fminf(acc[0][0], acc[0][1]), fminf(acc[1][0], acc[1][1])),
                      fminf(fminf(acc[2][0], acc[2][1]), fminf(acc[3][0], acc[3][1])));
    float mn1 = fminf(fminf(fminf(acc[0][2], acc[0][3]), fminf(acc[1][2], acc[1][3])),
                      fminf(fminf(acc[2][2], acc[2][3]), fminf(acc[3][2], acc[3][3])));
    if (mn0 < cd[0][3]) {
#pragma unroll
        for (int nt = 0; nt < 4; nt++)
#pragma unroll
            for (int e = 0; e < 2; e++) {
                float d = acc[nt][e];
                if (d < cd[0][3]) {
                    int col = j0 + jc16[nt * 4 + e];
                    float vd = d; int vi = col;
#pragma unroll
                    for (int p = 0; p < 4; p++) {
                        if (vd < cd[0][p]) {
                            float td = cd[0][p]; int ti = ci[0][p];
                            cd[0][p] = vd; ci[0][p] = vi;
                            vd = td; vi = ti;
                        }
                    }
                }
            }
    }
    if (mn1 < cd[1][3]) {
#pragma unroll
        for (int nt = 0; nt < 4; nt++)
#pragma unroll
            for (int e = 2; e < 4; e++) {
                float d = acc[nt][e];
                if (d < cd[1][3]) {
                    int col = j0 + jc16[nt * 4 + e];
                    float vd = d; int vi = col;
#pragma unroll
                    for (int p = 0; p < 4; p++) {
                        if (vd < cd[1][p]) {
                            float td = cd[1][p]; int ti = ci[1][p];
                            cd[1][p] = vd; ci[1][p] = vi;
                            vd = td; vi = ti;
                        }
                    }
                }
            }
    }
}

// ------------------------------ mma.sync kNN candidates (K = 3C) -------------
// A fragments live in registers: the A tile is staged through the B
// double-buffer region once, ldmatrix'd into per-warp registers, then that
// shared region is recycled for the B pipeline. Values and mma order are
// bit-identical to the shared-A version.
template<int C>
__global__ void __launch_bounds__(128) knn_mma_kernel(
        const __nv_bfloat16* __restrict__ imgA, const __nv_bfloat16* __restrict__ imgB,
        const float* __restrict__ sq, float* __restrict__ candd,
        int* __restrict__ candi, int nper) {
    const int K   = 3 * C;
    const int SKW = K + 16;
    const int KC  = K / 16;
    const int JT  = 32;
    const int CH  = K / 8;
    const int SLOTS = JT * CH / 128;
    extern __shared__ __align__(16) __nv_bfloat16 sh[];
    __nv_bfloat16* Bsh  = sh;                           // [2][JT][SKW]
    float*         sqsh = (float*)(Bsh + 2 * JT * SKW); // [2][JT]

    int tid  = threadIdx.x;
    int lane = tid & 31, w = tid >> 5;
    int b = blockIdx.z, it = blockIdx.x, split = blockIdx.y;
    int ibase = it * 64;
    int gbase = b * nper;
    int jlen  = nper >> 2;
    int js    = split * jlen;
    const int NT = jlen / JT;

    const int m0 = w * 16;
    const int ar  = lane & 7;
    const int ah  = (lane >> 3) & 1;
    const int akh = (lane >> 4) & 1;
    const int bn  = (lane & 7) | (((lane >> 4) & 1) << 3);
    const int bh  = (lane >> 3) & 1;

    // ---- stage A tile through the B-buffer region, ldsm into registers ----
    for (int t = tid; t < 64 * CH; t += 128) {
        int r = t / CH, cc = t % CH;
        *(uint4*)&Bsh[r * SKW + cc * 8] =
            *(const uint4*)&imgA[((size_t)(gbase + ibase + r)) * K + cc * 8];
    }
    __syncthreads();
    unsigned af[KC][4];
    {
        unsigned aStage = smem_u32(&Bsh[(m0 + ar + 8 * ah) * SKW + 8 * akh]);
#pragma unroll
        for (int kc = 0; kc < KC; kc++)
            ldm4(af[kc][0], af[kc][1], af[kc][2], af[kc][3], aStage + kc * 32);
    }
    __syncthreads();

    // ---- B pipeline setup --------------------------------------------------
    unsigned sBoff[SLOTS]; unsigned gBoff[SLOTS];
#pragma unroll
    for (int s = 0; s < SLOTS; s++) {
        int q = tid + s * 128;
        int r = q / CH, cc = q % CH;
        sBoff[s] = (unsigned)((r * SKW + cc * 8) * 2);
        gBoff[s] = (unsigned)(r * K + cc * 8);
    }
    unsigned bufB[2] = { smem_u32(Bsh), smem_u32(Bsh + JT * SKW) };
    unsigned sqBuf[2] = { smem_u32(sqsh), smem_u32(sqsh + JT) };

    const __nv_bfloat16* gtile = imgB + (size_t)(gbase + js) * K;
    const float* gsq = sq + gbase + js;
#pragma unroll
    for (int s = 0; s < SLOTS; s++)
        cp_async16(bufB[0] + sBoff[s], gtile + gBoff[s]);
    if (tid < JT / 4)
        cp_async16(sqBuf[0] + tid * 16, gsq + tid * 4);
    cp_commit();
    const __nv_bfloat16* gnext = gtile + (size_t)JT * K;
    const float* gsqnext = gsq + JT;

    int li2[2];
#pragma unroll
    for (int s = 0; s < 2; s++) li2[s] = ibase + m0 + (lane >> 2) + 8 * s;
    float cd[2][4]; int ci[2][4];
#pragma unroll
    for (int s = 0; s < 2; s++)
#pragma unroll
        for (int p = 0; p < 4; p++) { cd[s][p] = 3.4e38f; ci[s][p] = 0; }

    unsigned bnOff = (unsigned)((bn * SKW + 8 * bh) * 2);

    int jc16[16];
#pragma unroll
    for (int nt = 0; nt < 4; nt++)
#pragma unroll
        for (int e = 0; e < 4; e++)
            jc16[nt * 4 + e] = nt * 8 + 2 * (lane & 3) + (e & 1);

    int j0 = js;
    for (int t = 0; t < NT; t++) {
        if (t + 1 < NT) {
            unsigned bb = bufB[(t + 1) & 1];
#pragma unroll
            for (int s = 0; s < SLOTS; s++)
                cp_async16(bb + sBoff[s], gnext + gBoff[s]);
            if (tid < JT / 4)
                cp_async16(sqBuf[(t + 1) & 1] + tid * 16, gsqnext + tid * 4);
            cp_commit();
            cp_wait1();
            gnext += (size_t)JT * K;
            gsqnext += JT;
        } else {
            cp_wait0();
        }
        __syncthreads();

        unsigned bBufBase = bufB[t & 1] + bnOff;
        const float* sqb = (t & 1) ? (sqsh + JT) : sqsh;

        float acc[4][4];
#pragma unroll
        for (int nt = 0; nt < 4; nt++)
#pragma unroll
            for (int e = 0; e < 4; e++) acc[nt][e] = 0.f;

#pragma unroll
        for (int kc = 0; kc < KC; kc++) {
            unsigned bf[4][2];
#pragma unroll
            for (int np = 0; np < 2; np++) {
                unsigned r0, r1, r2, r3;
                ldm4(r0, r1, r2, r3, bBufBase + np * (16 * SKW * 2) + kc * 32);
                bf[2 * np][0] = r0; bf[2 * np][1] = r1;
                bf[2 * np + 1][0] = r2; bf[2 * np + 1][1] = r3;
            }
#pragma unroll
            for (int nt = 0; nt < 4; nt++)
                mma_bf16(acc[nt], af[kc], bf[nt]);
        }

        bool ovl = (j0 < ibase + 64) && (j0 + JT > ibase);
        if (ovl) epi_insert<true >(acc, sqb, jc16, j0, li2, cd, ci);
        else     epi_insert<false>(acc, sqb, jc16, j0, li2, cd, ci);
        j0 += JT;
        __syncthreads();
    }
#pragma unroll
    for (int s = 0; s < 2; s++)
#pragma unroll
        for (int p = 0; p < 4; p++) {
            size_t base = ((size_t)(gbase + li2[s])) * 64 + split * 16 + (lane & 3) * 4 + p;
            candd[base] = cd[s][p];
            candi[base] = gbase + ci[s][p];
        }
}

// ------------------------------ warp-cooperative re-rank + wn ----------------
template<int C>
__global__ void rerank_kernel(const float* __restrict__ x, const float* __restrict__ sq,
                              const float* __restrict__ candd, const int* __restrict__ candi,
                              int* __restrict__ knn,
                              const float* __restrict__ ew, const float* __restrict__ dnv,
                              float* __restrict__ wn, int n) {
    int t = blockIdx.x * blockDim.x + threadIdx.x;
    int gi = t >> 3;
    int r8 = t & 7;
    if (gi >= n) return;

    const float* cdp = candd + (size_t)gi * 64 + r8 * 8;
    const int*   cip = candi + (size_t)gi * 64 + r8 * 8;
    float d8[8]; int i8[8];
#pragma unroll
    for (int p = 0; p < 8; p++) { d8[p] = cdp[p]; i8[p] = cip[p]; }

    unsigned taken = 0;
    float myD = 3.4e38f; int myI = 0;
#pragma unroll
    for (int r = 0; r < 8; r++) {
        float ld = 3.4e38f; int li = 0x7fffffff; int lp = -1;
#pragma unroll
        for (int p = 0; p < 8; p++) {
            if (!(taken & (1u << p)) &&
                (d8[p] < ld || (d8[p] == ld && i8[p] < li))) {
                ld = d8[p]; li = i8[p]; lp = p;
            }
        }
        float bd = ld; int bi = li; int bl = r8;
#pragma unroll
        for (int off = 4; off > 0; off >>= 1) {
            float od = __shfl_xor_sync(0xffffffffu, bd, off);
            int   oi = __shfl_xor_sync(0xffffffffu, bi, off);
            int   ol = __shfl_xor_sync(0xffffffffu, bl, off);
            if (od < bd || (od == bd && (oi < bi || (oi == bi && ol < bl)))) {
                bd = od; bi = oi; bl = ol;
            }
        }
        if (bl == r8 && lp >= 0) taken |= (1u << lp);
        if (r == r8) { myD = bd; myI = bi; }
    }

    const float* xi = x + (size_t)gi * C;
    const float* xr = x + (size_t)myI * C;
    float dot = 0.f;
#pragma unroll
    for (int c = 0; c < C; c++) dot = __fmaf_rn(__ldg(xi + c), __ldg(xr + c), dot);
    float dd = __fsub_rn(__fadd_rn(sq[gi], sq[myI]), __fmul_rn(2.f, dot));

    bool used = false;
    float dng = dnv[gi];
#pragma unroll
    for (int r = 0; r < 3; r++) {
        float bd = used ? 3.4e38f : dd;
        int   bi = used ? 0x7fffffff : myI;
        int   bl = r8;
#pragma unroll
        for (int off = 4; off > 0; off >>= 1) {
            float od = __shfl_xor_sync(0xffffffffu, bd, off);
            int   oi = __shfl_xor_sync(0xffffffffu, bi, off);
            int   ol = __shfl_xor_sync(0xffffffffu, bl, off);
            if (od < bd || (od == bd && (oi < bi || (oi == bi && ol < bl)))) {
                bd = od; bi = oi; bl = ol;
            }
        }
        if (bl == r8) used = true;
        if (r8 == 0) {
            knn[gi * 3 + r] = bi;
            wn [gi * 3 + r] = __fmul_rn(__fmul_rn(ew[gi * 3 + r], dng), dnv[bi]);
        }
    }
}

// ------------------------------ copy into Z slice (stage 1 only) -------------
__global__ void copy_slice_kernel(const float* __restrict__ src, float* __restrict__ Z,
                                  int Cq, int stride4, int total) {
    int idx = blockIdx.x * blockDim.x + threadIdx.x;
    if (idx >= total) return;
    int g = idx / Cq, q = idx % Cq;
    ((float4*)Z)[(size_t)g * stride4 + q] = ((const float4*)src)[(size_t)g * Cq + q];
}

// ------------------------------ Laplacian step -------------------------------
__global__ void lap_kernel(const float* __restrict__ Zin, const float* __restrict__ Zprev,
                           float* __restrict__ Zout, int stride, int Cq,
                           float alpha, float beta,
                           const int* __restrict__ knn, const float* __restrict__ wn,
                           int total) {
    int idx = blockIdx.x * blockDim.x + threadIdx.x;
    if (idx >= total) return;
    int g = idx / Cq, q = idx % Cq;
    int s0 = knn[3 * g], s1 = knn[3 * g + 1], s2 = knn[3 * g + 2];
    float w0 = wn[3 * g], w1 = wn[3 * g + 1], w2 = wn[3 * g + 2];
    float4 a0 = ((const float4*)(Zin + (size_t)s0 * stride))[q];
    float4 a1 = ((const float4*)(Zin + (size_t)s1 * stride))[q];
    float4 a2 = ((const float4*)(Zin + (size_t)s2 * stride))[q];
    float4 r;
    r.x = alpha * (-(w0 * a0.x + w1 * a1.x + w2 * a2.x));
    r.y = alpha * (-(w0 * a0.y + w1 * a1.y + w2 * a2.y));
    r.z = alpha * (-(w0 * a0.z + w1 * a1.z + w2 * a2.z));
    r.w = alpha * (-(w0 * a0.w + w1 * a1.w + w2 * a2.w));
    if (beta != 0.f) {
        float4 p = ((const float4*)(Zprev + (size_t)g * stride))[q];
        r.x += beta * p.x; r.y += beta * p.y; r.z += beta * p.z; r.w += beta * p.w;
    }
    ((float4*)(Zout + (size_t)g * stride))[q] = r;
}

// ------------------------------ fused copy + first lap (stage 2) -------------
__global__ void lap_first_kernel(const float* __restrict__ src, float* __restrict__ Z,
                                 int stride4, int Cq,
                                 const int* __restrict__ knn, const float* __restrict__ wn,
                                 int total) {
    int idx = blockIdx.x * blockDim.x + threadIdx.x;
    if (idx >= total) return;
    int g = idx / Cq, q = idx % Cq;
    int s0 = knn[3 * g], s1 = knn[3 * g + 1], s2 = knn[3 * g + 2];
    float w0 = wn[3 * g], w1 = wn[3 * g + 1], w2 = wn[3 * g + 2];
    const float4* s4 = (const float4*)src;
    float4 own = s4[(size_t)g * Cq + q];
    float4 a0 = s4[(size_t)s0 * Cq + q];
    float4 a1 = s4[(size_t)s1 * Cq + q];
    float4 a2 = s4[(size_t)s2 * Cq + q];
    float4 r;
    r.x = -(w0 * a0.x + w1 * a1.x + w2 * a2.x);
    r.y = -(w0 * a0.y + w1 * a1.y + w2 * a2.y);
    r.z = -(w0 * a0.z + w1 * a1.z + w2 * a2.z);
    r.w = -(w0 * a0.w + w1 * a1.w + w2 * a2.w);
    ((float4*)Z)[(size_t)g * stride4 + q]      = own;
    ((float4*)Z)[(size_t)g * stride4 + Cq + q] = r;
}

// ------------------------------ fp32 FFMA2 GEMM (conv0 only) ----------------
template<int ACT>
__global__ void gemm_kernel(const float* __restrict__ A, const float* __restrict__ B,
                            const float* __restrict__ bias, float* __restrict__ C,
                            int K, int Ncols) {
    __shared__ __align__(16) float As2[16][128];
    __shared__ __align__(16) float Bs[16][64];
    const int tid  = threadIdx.x;
    const int row0 = blockIdx.y * 64;
    const int col0 = blockIdx.x * 64;
    const int tx = tid & 15, ty = tid >> 4;
    unsigned long long acc2[4][2];
#pragma unroll
    for (int i = 0; i < 4; i++) { acc2[i][0] = 0ull; acc2[i][1] = 0ull; }

    const int lin  = tid * 4;
    const int arow = lin >> 4, acol = lin & 15;
    const int brow = lin >> 6, bcol = lin & 63;

    for (int k0 = 0; k0 < K; k0 += 16) {
        float4 av = make_float4(0.f, 0.f, 0.f, 0.f);
        if (k0 + acol < K)
            av = *(const float4*)(A + (size_t)(row0 + arow) * K + k0 + acol);
        *(float2*)&As2[acol + 0][2 * arow] = make_float2(av.x, av.x);
        *(float2*)&As2[acol + 1][2 * arow] = make_float2(av.y, av.y);
        *(float2*)&As2[acol + 2][2 * arow] = make_float2(av.z, av.z);
        *(float2*)&As2[acol + 3][2 * arow] = make_float2(av.w, av.w);

        float4 bv = make_float4(0.f, 0.f, 0.f, 0.f);
        int gk = k0 + brow, gc = col0 + bcol;
        if (gk < K && gc < Ncols)
            bv = *(const float4*)(B + (size_t)gk * Ncols + gc);
        *(float4*)&Bs[brow][bcol] = bv;
        __syncthreads();
#pragma unroll
        for (int kk = 0; kk < 16; kk++) {
            ulonglong2 a01 = *(const ulonglong2*)&As2[kk][ty * 8];
            ulonglong2 a23 = *(const ulonglong2*)&As2[kk][ty * 8 + 4];
            ulonglong2 bq  = *(const ulonglong2*)&Bs[kk][tx * 4];
            ffma2(acc2[0][0], a01.x, bq.x); ffma2(acc2[0][1], a01.x, bq.y);
            ffma2(acc2[1][0], a01.y, bq.x); ffma2(acc2[1][1], a01.y, bq.y);
            ffma2(acc2[2][0], a23.x, bq.x); ffma2(acc2[2][1], a23.x, bq.y);
            ffma2(acc2[3][0], a23.y, bq.x); ffma2(acc2[3][1], a23.y, bq.y);
        }
        __syncthreads();
    }
#pragma unroll
    for (int i = 0; i < 4; i++) {
        float a0, a1, a2, a3;
        unpack2(acc2[i][0], a0, a1);
        unpack2(acc2[i][1], a2, a3);
        float accs[4] = {a0, a1, a2, a3};
        int row = row0 + ty * 4 + i;
#pragma unroll
        for (int j = 0; j < 4; j++) {
            int col = col0 + tx * 4 + j;
            if (col < Ncols) {
                float v = accs[j] + bias[col];
                if (ACT == 1) v = selu_f(v);
                C[(size_t)row * Ncols + col] = v;
            }
        }
    }
}

// ------------------------------ GraphNorm -----------------------------------
__global__ void gn_reduce_kernel(const float* __restrict__ u, const float* __restrict__ alpha,
                                 float* __restrict__ amean, float* __restrict__ rstd) {
    int b = blockIdx.x;
    int t = threadIdx.x;               // 256
    int c = t & 63, rg = t >> 6;
    float s = 0.f;
    for (int n = rg; n < NG_; n += 4) s += u[((size_t)(b * NG_ + n)) * 64 + c];
    __shared__ float sh[256];
    sh[t] = s;
    __syncthreads();
    __shared__ float smean[64];
    if (t < 64) {
        s = sh[t] + sh[t + 64] + sh[t + 128] + sh[t + 192];
        smean[t] = s * (1.f / NG_);
    }
    __syncthreads();
    float am = alpha[c] * smean[c];
    float s2 = 0.f;
    for (int n = rg; n < NG_; n += 4) {
        float v = u[((size_t)(b * NG_ + n)) * 64 + c] - am;
        s2 += v * v;
    }
    sh[t] = s2;
    __syncthreads();
    if (t < 64) {
        s2 = sh[t] + sh[t + 64] + sh[t + 128] + sh[t + 192];
        float var = s2 * (1.f / NG_);
        amean[b * 64 + t] = alpha[t] * smean[t];
        rstd [b * 64 + t] = rsqrtf(var + 1e-5f);
    }
}

__global__ void gn_norm_kernel(float* __restrict__ u, const float* __restrict__ gamma,
                               const float* __restrict__ beta, const float* __restrict__ amean,
                               const float* __restrict__ rstd) {
    int idx = blockIdx.x * blockDim.x + threadIdx.x;
    if (idx >= N_TOT * 64) return;
    int g = idx >> 6, c = idx & 63;
    int b = g >> 12;   // /4096
    float v = u[idx];
    u[idx] = gamma[c] * (v - amean[b * 64 + c]) * rstd[b * 64 + c] + beta[c];
}

// ------------------------------ softmax rows (warp per row) ------------------
__global__ void softmax_kernel(const float* __restrict__ u, float* __restrict__ S) {
    int row = blockIdx.x * 4 + (threadIdx.x >> 5);
    int lane = threadIdx.x & 31;
    if (row >= N_TOT) return;
    const float* rp = u + (size_t)row * M_;
    float v0 = rp[lane], v1 = rp[lane + 32], v2 = rp[lane + 64];
    float v3 = (lane < 4) ? rp[lane + 96] : -3.4e38f;
    float m = fmaxf(fmaxf(v0, v1), fmaxf(v2, v3));
#pragma unroll
    for (int off = 16; off > 0; off >>= 1)
        m = fmaxf(m, __shfl_xor_sync(0xffffffffu, m, off));
    float e0 = expf(v0 - m), e1 = expf(v1 - m), e2 = expf(v2 - m);
    float e3 = (lane < 4) ? expf(v3 - m) : 0.f;
    float s = e0 + e1 + e2 + e3;
#pragma unroll
    for (int off = 16; off > 0; off >>= 1)
        s += __shfl_xor_sync(0xffffffffu, s, off);
    float inv = 1.f / s;
    float* so = S + (size_t)row * M_;
    so[lane] = e0 * inv; so[lane + 32] = e1 * inv; so[lane + 64] = e2 * inv;
    if (lane < 4) so[lane + 96] = e3 * inv;
}

// ------------------------------ DiffPool pooling (tiled, deterministic) ------
__global__ void pool_partial_kernel(const float* __restrict__ S, const float* __restrict__ x,
                                    float* __restrict__ part) {
    extern __shared__ float psm[];         // sS[128*100] + sX[128*32]
    float* sS = psm;
    float* sX = psm + 128 * M_;
    int b = blockIdx.y, nt = blockIdx.x, tid = threadIdx.x;
    size_t nbase = (size_t)(b * NG_ + nt * 128);
    const float4* gS = (const float4*)(S + nbase * M_);
    float4* s4 = (float4*)sS;
    for (int i = tid; i < 128 * M_ / 4; i += 128) s4[i] = gS[i];
    const float4* gX = (const float4*)(x + nbase * 32);
    float4* x4 = (float4*)sX;
    for (int i = tid; i < 128 * 32 / 4; i += 128) x4[i] = gX[i];
    __syncthreads();
    int ty = tid >> 5, tx = tid & 31;
    int mbase = ty * 25;
    float acc[25];
#pragma unroll
    for (int k = 0; k < 25; k++) acc[k] = 0.f;
    for (int n = 0; n < 128; n++) {
        float xv = sX[n * 32 + tx];
        const float* srow = &sS[n * M_ + mbase];
#pragma unroll
        for (int k = 0; k < 25; k++) acc[k] = __fmaf_rn(srow[k], xv, acc[k]);
    }
    float* po = part + ((size_t)nt * NP_ + b * M_) * 33;
#pragma unroll
    for (int k = 0; k < 25; k++) po[(mbase + k) * 33 + tx] = acc[k];
    if (tid < M_) {
        float s = 0.f;
        for (int n = 0; n < 128; n++) s += sS[n * M_ + tid];
        po[tid * 33 + 32] = s;
    }
}

__global__ void pool_reduce_kernel(const float* __restrict__ part, float* __restrict__ xp) {
    int idx = blockIdx.x * blockDim.x + threadIdx.x;
    if (idx >= NP_ * 32) return;
    int g = idx >> 5, c = idx & 31;
    float p = 0.f, s = 0.f;
    for (int t = 0; t < 32; t++) {
        const float* base = part + ((size_t)t * NP_ + g) * 33;
        p += base[c];
        s += base[32];
    }
    xp[idx] = p / s;
}

// ------------------------------ zero-init -----------------------------------
__global__ void zero2_kernel(float* a, float* b, int n) {
    int i = blockIdx.x * blockDim.x + threadIdx.x;
    if (i < n) { a[i] = 0.f; b[i] = 0.f; }
}

// ------------------------------ PPI edge conv -------------------------------
__global__ void ppi_conv_kernel(const float* __restrict__ xp, const int* __restrict__ connect,
                                const float* __restrict__ W2, const float* __restrict__ b2,
                                float* __restrict__ h) {
    __shared__ float feat[4][64];
    int t = threadIdx.x;
    int el = t >> 6, o = t & 63;
    int e = blockIdx.x * 4 + el;
    int dst = 0;
    if (e < B_ * E_PPI_) {
        int b = e / E_PPI_, le = e % E_PPI_;
        int s = connect[le] + b * M_;
        dst   = connect[E_PPI_ + le] + b * M_;
        float v;
        if (o < 32) v = xp[dst * 32 + o];
        else        v = xp[s * 32 + (o - 32)] - xp[dst * 32 + (o - 32)];
        feat[el][o] = v;
    }
    __syncthreads();
    if (e < B_ * E_PPI_) {
        float s = b2[o];
#pragma unroll
        for (int k = 0; k < 64; k++) s += feat[el][k] * W2[k * 64 + o];
        s = fmaxf(s, 0.f);
        atomicMax((int*)&h[dst * 64 + o], __float_as_int(s));
    }
}

// ------------------------------ small kNN on pooled graphs (100 nodes) ------
__global__ void knn_small_kernel(const float* __restrict__ h, int* __restrict__ knn2) {
    __shared__ float xsf[M_ * 64];
    __shared__ float sqs[M_];
    int b = blockIdx.x, t = threadIdx.x;   // 128 threads
    const float4* src4 = (const float4*)(h + (size_t)b * M_ * 64);
    float4* dst4 = (float4*)xsf;
    for (int idx = t; idx < M_ * 16; idx += 128) dst4[idx] = src4[idx];
    __syncthreads();
    if (t < M_) {
        const float* r = xsf + t * 64;
        float p[32];
#pragma unroll
        for (int q = 0; q < 32; q++) {
            float a = __fmaf_rn(r[2 * q], r[2 * q], 0.f);
            p[q] = __fmaf_rn(r[2 * q + 1], r[2 * q + 1], a);
        }
#pragma unroll
        for (int off = 16; off > 0; off >>= 1)
#pragma unroll
            for (int c = 0; c < 16; c++)
                if (c < off) p[c] = __fadd_rn(p[c], p[c + off]);
        sqs[t] = p[0];
    }
    __syncthreads();
    if (t < M_) {
        float sqi = sqs[t];
        float bd0 = 3.4e38f, bd1 = 3.4e38f, bd2 = 3.4e38f;
        int bi0 = 0, bi1 = 0, bi2 = 0;
        for (int j = 0; j < M_; j++) {
            if (j == t) continue;
            float dot = 0.f;
#pragma unroll
            for (int c = 0; c < 64; c++)
                dot = __fmaf_rn(xsf[t * 64 + c], xsf[j * 64 + c], dot);
            float t1 = __fadd_rn(sqi, sqs[j]);
            float t2 = __fmul_rn(2.f, dot);
            float d  = __fsub_rn(t1, t2);
            if (d < bd2) {
                if (d < bd0)      { bd2=bd1; bi2=bi1; bd1=bd0; bi1=bi0; bd0=d; bi0=j; }
                else if (d < bd1) { bd2=bd1; bi2=bi1; bd1=d;   bi1=j; }
                else              { bd2=d;   bi2=j; }
            }
        }
        int g = b * M_ + t;
        knn2[g * 3 + 0] = b * M_ + bi0;
        knn2[g * 3 + 1] = b * M_ + bi1;
        knn2[g * 3 + 2] = b * M_ + bi2;
    }
}

// ------------------------------ dynamic edge conv ---------------------------
__global__ void dyn_conv_kernel(const float* __restrict__ h, const int* __restrict__ knn2,
                                const float* __restrict__ W3, const float* __restrict__ b3,
                                float* __restrict__ y) {
    __shared__ float feat[2][128];
    int t = threadIdx.x;
    int e0 = blockIdx.x * 2;
#pragma unroll
    for (int p = 0; p < 2; p++) {
        int e = e0 + p;
        if (e < NP_ * 3) {
            int g = e / 3;
            int src = knn2[e];
            int c = t;
            float v = (c < 64) ? h[g * 64 + c] : (h[src * 64 + (c - 64)] - h[g * 64 + (c - 64)]);
            feat[p][c] = v;
        }
    }
    __syncthreads();
    int el = t >> 6, o = t & 63;
    int e = e0 + el;
    if (e < NP_ * 3) {
        int g = e / 3;
        float s = b3[o];
#pragma unroll
        for (int k = 0; k < 128; k++) s += feat[el][k] * W3[k * 64 + o];
        s = fmaxf(s, 0.f);
        atomicMax((int*)&y[g * 64 + o], __float_as_int(s));
    }
}

// ------------------------------ final MLP (f2) ------------------------------
__global__ void final_mlp_kernel(const float* __restrict__ h, const float* __restrict__ y,
                                 const float* __restrict__ w1, const float* __restrict__ b1,
                                 const float* __restrict__ w2, const float* __restrict__ b2,
                                 const float* __restrict__ w3, const float* __restrict__ b3,
                                 float* __restrict__ out) {
    int r = blockIdx.x * blockDim.x + threadIdx.x;
    if (r >= NP_) return;
    float z[64];
#pragma unroll
    for (int c = 0; c < 64; c++) z[c] = h[r * 64 + c] + y[r * 64 + c];
    float a1[32];
#pragma unroll
    for (int o = 0; o < 32; o++) {
        float s = b1[o];
        for (int k = 0; k < 64; k++) s += z[k] * w1[k * 32 + o];
        a1[o] = selu_f(s);
    }
    float a2[16];
#pragma unroll
    for (int o = 0; o < 16; o++) {
        float s = b2[o];
        for (int k = 0; k < 32; k++) s += a1[k] * w2[k * 16 + o];
        a2[o] = selu_f(s);
    }
#pragma unroll
    for (int o = 0; o < 16; o++) {
        float s = b3[o];
        for (int k = 0; k < 16; k++) s += a2[k] * w3[k * 16 + o];
        out[r * 16 + o] = s;
    }
}

// ------------------------------ host orchestration --------------------------
template<typename T>
static T* sym_addr(const void* sym) {
    void* p = nullptr;
    cudaGetSymbolAddress(&p, sym);
    return (T*)p;
}

extern "C" void kernel_launch(void* const* d_in, const int* in_sizes, int n_in,
                              void* d_out, int out_size) {
    const float* x    = (const float*)d_in[0];
    const float* ew   = (const float*)d_in[1];
    const int*   conn = (const int*)d_in[3];
    const float* W0   = (const float*)d_in[4];
    const float* b0   = (const float*)d_in[5];
    const float* gna  = (const float*)d_in[6];
    const float* gng  = (const float*)d_in[7];
    const float* gnb  = (const float*)d_in[8];
    const float* W1   = (const float*)d_in[9];
    const float* b1c  = (const float*)d_in[10];
    const float* f1w1 = (const float*)d_in[11];
    const float* f1b1 = (const float*)d_in[12];
    const float* f1w2 = (const float*)d_in[13];
    const float* f1b2 = (const float*)d_in[14];
    const float* f1w3 = (const float*)d_in[15];
    const float* f1b3 = (const float*)d_in[16];
    const float* W2   = (const float*)d_in[17];
    const float* b2   = (const float*)d_in[18];
    const float* W3   = (const float*)d_in[19];
    const float* b3   = (const float*)d_in[20];
    const float* f2w1 = (const float*)d_in[21];
    const float* f2b1 = (const float*)d_in[22];
    const float* f2w2 = (const float*)d_in[23];
    const float* f2b2 = (const float*)d_in[24];
    const float* f2w3 = (const float*)d_in[25];
    const float* f2b3 = (const float*)d_in[26];

    float* out_u = (float*)d_out;                       // [32768, 100]
    float* out_v = out_u + (size_t)N_TOT * M_;          // [800, 16]

    float* sq    = sym_addr<float>(g_sq);
    int*   knn   = sym_addr<int>(g_knn);
    int*   cand  = sym_addr<int>(g_cand);
    float* cdist = sym_addr<float>(g_cdist);
    float* dn    = sym_addr<float>(g_dn);
    float* wn    = sym_addr<float>(g_wn);
    float* Z     = sym_addr<float>(g_Z);
    float* u0    = sym_addr<float>(g_u0);
    float* u1    = sym_addr<float>(g_u1);
    float* t1    = sym_addr<float>(g_t1);
    float* t2    = sym_addr<float>(g_t2);
    float* S     = sym_addr<float>(g_S);
    float* amean = sym_addr<float>(g_amean);
    float* rstd  = sym_addr<float>(g_rstd);
    float* xp    = sym_addr<float>(g_xp);
    float* h     = sym_addr<float>(g_h);
    float* y     = sym_addr<float>(g_y);
    int*   knn2  = sym_addr<int>(g_knn2);
    float* ppart = sym_addr<float>(g_poolpart);
    __nv_bfloat16* imgA = sym_addr<__nv_bfloat16>(g_imgA);
    __nv_bfloat16* imgB = sym_addr<__nv_bfloat16>(g_imgB);
    __nv_bfloat16* whi  = sym_addr<__nv_bfloat16>(g_whi);
    __nv_bfloat16* wlo  = sym_addr<__nv_bfloat16>(g_wlo);

    // smem: 2*B[JT][SKW] + 2*sqs[JT]  (A now register-resident)
    const int SM32 = 2 * 32 * 112 * 2 + 2 * 32 * 4;  // 14592 B
    const int SM64 = 2 * 32 * 208 * 2 + 2 * 32 * 4;  // 26880 B
    const int SMPOOL = 128 * (M_ + 32) * 4;          // 67584 B
    static bool attr_done = false;
    if (!attr_done) {
        cudaFuncSetAttribute(pool_partial_kernel,
                             cudaFuncAttributeMaxDynamicSharedMemorySize, SMPOOL);
        attr_done = true;
    }

    // ---- stage 1: kNN on x (C=32)  (dn fused into sqprep32)
    sqprep32_kernel<<<(N_TOT + 127) / 128, 128>>>(x, sq, imgA, imgB, ew, dn);
    knn_mma_kernel<32><<<dim3(NG_ / 64, 4, B_), 128, SM32>>>(imgA, imgB, sq, cdist, cand, NG_);
    rerank_kernel<32><<<(N_TOT * 8 + 255) / 256, 256>>>(x, sq, cdist, cand, knn, ew, dn, wn, N_TOT);

    // ---- conv0: Chebyshev terms into Z (N x 128), fp32 GEMM (u0 bit-exact)
    {
        int total = N_TOT * 8;   // N * C/4, C=32
        copy_slice_kernel<<<(total + 255) / 256, 256>>>(x, Z, 8, 32, total);
        lap_kernel<<<(total + 255) / 256, 256>>>(Z + 0,  Z,       Z + 32, 128, 8, 1.f,  0.f, knn, wn, total);
        lap_kernel<<<(total + 255) / 256, 256>>>(Z + 32, Z + 0,   Z + 64, 128, 8, 2.f, -1.f, knn, wn, total);
        lap_kernel<<<(total + 255) / 256, 256>>>(Z + 64, Z + 32,  Z + 96, 128, 8, 2.f, -1.f, knn, wn, total);
        gemm_kernel<0><<<dim3(1, N_TOT / 64), 256>>>(Z, W0, b0, u0, 128, 64);
    }

    // ---- GraphNorm (unchanged; u0 bits preserved)
    gn_reduce_kernel<<<B_, 256>>>(u0, gna, amean, rstd);
    gn_norm_kernel<<<(N_TOT * 64) / 256, 256>>>(u0, gng, gnb, amean, rstd);

    // ---- stage 2: kNN on u0 (C=64)
    sqprep64_kernel<<<(N_TOT + 127) / 128, 128>>>(u0, sq, imgA, imgB);
    knn_mma_kernel<64><<<dim3(NG_ / 64, 4, B_), 128, SM64>>>(imgA, imgB, sq, cdist, cand, NG_);
    rerank_kernel<64><<<(N_TOT * 8 + 255) / 256, 256>>>(u0, sq, cdist, cand, knn, ew, dn, wn, N_TOT);

    // ---- conv1: fused copy+lap, laps, bf16-split tensor GEMM -> u1
    {
        int total = N_TOT * 16;  // N * C/4, C=64
        lap_first_kernel<<<(total + 255) / 256, 256>>>(u0, Z, 64, 16, knn, wn, total);
        lap_kernel<<<(total + 255) / 256, 256>>>(Z + 64,  Z + 0,    Z + 128, 256, 16, 2.f, -1.f, knn, wn, total);
        lap_kernel<<<(total + 255) / 256, 256>>>(Z + 128, Z + 64,   Z + 192, 256, 16, 2.f, -1.f, knn, wn, total);
        prep_w_kernel<<<(448 * 32 + 255) / 256, 256>>>(W1, whi, wlo, 256, 400, 256, 448);
        gemm_bf16_kernel<0><<<dim3(7, N_TOT / 64), 128>>>(Z, whi, wlo, b1c, u1, 256, 256, 400);
    }

    // ---- fc1 MLP: 400 -> 200 -> 100 -> 100 (bf16-split tensor GEMMs)
    prep_w_kernel<<<(256 * 52 + 255) / 256, 256>>>(f1w1, whi, wlo, 400, 200, 416, 256);
    gemm_bf16_kernel<1><<<dim3(4, N_TOT / 64), 128>>>(u1, whi, wlo, f1b1, t1, 400, 416, 200);
    prep_w_kernel<<<(128 * 28 + 255) / 256, 256>>>(f1w2, whi, wlo, 200, 100, 224, 128);
    gemm_bf16_kernel<1><<<dim3(2, N_TOT / 64), 128>>>(t1, whi, wlo, f1b2, t2, 200, 224, 100);
    prep_w_kernel<<<(128 * 16 + 255) / 256, 256>>>(f1w3, whi, wlo, 100, 100, 128, 128);
    gemm_bf16_kernel<0><<<dim3(2, N_TOT / 64), 128>>>(t2, whi, wlo, f1b3, out_u, 100, 128, 100);

    // ---- DiffPool soft pooling (tiled partials + deterministic reduce)
    softmax_kernel<<<N_TOT / 4, 128>>>(out_u, S);
    pool_partial_kernel<<<dim3(NG_ / 128, B_), 128, SMPOOL>>>(S, x, ppart);
    pool_reduce_kernel<<<(NP_ * 32 + 255) / 256, 256>>>(ppart, xp);

    // ---- PPI edge conv + dynamic edge conv
    zero2_kernel<<<(NP_ * HID_ + 255) / 256, 256>>>(h, y, NP_ * HID_);
    ppi_conv_kernel<<<(B_ * E_PPI_ + 3) / 4, 256>>>(xp, conn, W2, b2, h);
    knn_small_kernel<<<B_, 128>>>(h, knn2);
    dyn_conv_kernel<<<(NP_ * 3 + 1) / 2, 128>>>(h, knn2, W3, b3, y);

    // ---- final MLP -> v
    final_mlp_kernel<<<(NP_ + 127) / 128, 128>>>(h, y, f2w1, f2b1, f2w2, f2b2,
                                                 f2w3, f2b3, out_v);
}

// round 17
// speedup vs baseline: 1.4945x; 1.0636x over previous
#include <cuda_runtime.h>
#include <cuda_bf16.h>
#include <math.h>
#include <stdint.h>

#define N_TOT 32768
#define B_    8
#define NG_   4096
#define KNN_  3
#define IN_CH_ 32
#define HID_  64
#define M_    100
#define OUT_CH_ 16
#define NP_   800      // B*M pooled nodes
#define E_PPI_ 600

// ------------------------------ scratch (device globals; no allocs) ---------
__device__ float g_sq[N_TOT];
__device__ int   g_knn[N_TOT * 3];
__device__ int   g_cand [N_TOT * 64];
__device__ float g_cdist[N_TOT * 64];
__device__ float g_dn[N_TOT];
__device__ float g_wn[N_TOT * 3];
__device__ float g_Z[(size_t)N_TOT * 256];
__device__ float g_u0[(size_t)N_TOT * 64];
__device__ float g_u1[(size_t)N_TOT * 400];
__device__ float g_t1[(size_t)N_TOT * 200];
__device__ float g_t2[(size_t)N_TOT * 100];
__device__ float g_S [(size_t)N_TOT * 100];
__device__ float g_amean[B_ * HID_];
__device__ float g_rstd [B_ * HID_];
__device__ float g_xp[NP_ * IN_CH_];
__device__ float g_h [NP_ * HID_];
__device__ float g_y [NP_ * HID_];
__device__ int   g_knn2[NP_ * 3];
__device__ float g_poolpart[32 * NP_ * 33];   // [ntile][g][c(32)+ssum]
// bf16 split images for kNN, row-major [N][K<=192]
__device__ __nv_bfloat16 g_imgA[(size_t)N_TOT * 192];
__device__ __nv_bfloat16 g_imgB[(size_t)N_TOT * 192];
// bf16 split weight images for GEMM, row-major [Nimg][Kp] (max 448*416)
__device__ __nv_bfloat16 g_whi[448 * 416];
__device__ __nv_bfloat16 g_wlo[448 * 416];

// ------------------------------ helpers -------------------------------------
__device__ __forceinline__ float selu_f(float x) {
    const float sc = 1.0507009873554804934193349852946f;
    const float al = 1.6732632423543772848170429916717f;
    return x > 0.f ? sc * x : sc * al * expm1f(x);
}

__device__ __forceinline__ void ffma2(unsigned long long& d,
                                      unsigned long long a,
                                      unsigned long long b) {
    asm("fma.rn.f32x2 %0, %1, %2, %3;" : "=l"(d) : "l"(a), "l"(b), "l"(d));
}
__device__ __forceinline__ void unpack2(unsigned long long v, float& lo, float& hi) {
    unsigned int a, b;
    asm("mov.b64 {%0, %1}, %2;" : "=r"(a), "=r"(b) : "l"(v));
    lo = __uint_as_float(a); hi = __uint_as_float(b);
}

__device__ __forceinline__ unsigned int smem_u32(const void* p) {
    unsigned int a;
    asm("{ .reg .u64 t; cvta.to.shared.u64 t, %1; cvt.u32.u64 %0, t; }"
        : "=r"(a) : "l"(p));
    return a;
}
__device__ __forceinline__ void ldm4(unsigned& r0, unsigned& r1, unsigned& r2,
                                     unsigned& r3, unsigned addr) {
    asm volatile("ldmatrix.sync.aligned.m8n8.x4.shared.b16 {%0,%1,%2,%3}, [%4];"
                 : "=r"(r0), "=r"(r1), "=r"(r2), "=r"(r3) : "r"(addr));
}
__device__ __forceinline__ void mma_bf16(float* d, const unsigned* a, const unsigned* b) {
    asm volatile("mma.sync.aligned.m16n8k16.row.col.f32.bf16.bf16.f32 "
        "{%0,%1,%2,%3}, {%4,%5,%6,%7}, {%8,%9}, {%0,%1,%2,%3};"
        : "+f"(d[0]), "+f"(d[1]), "+f"(d[2]), "+f"(d[3])
        : "r"(a[0]), "r"(a[1]), "r"(a[2]), "r"(a[3]), "r"(b[0]), "r"(b[1]));
}
__device__ __forceinline__ void cp_async16(unsigned int saddr, const void* g) {
    asm volatile("cp.async.cg.shared.global [%0], [%1], 16;"
                 :: "r"(saddr), "l"(g));
}
__device__ __forceinline__ void cp_commit() {
    asm volatile("cp.async.commit_group;");
}
__device__ __forceinline__ void cp_wait1() {
    asm volatile("cp.async.wait_group 1;");
}
__device__ __forceinline__ void cp_wait0() {
    asm volatile("cp.async.wait_group 0;");
}
__device__ __forceinline__ unsigned packbf2(__nv_bfloat16 a, __nv_bfloat16 b) {
    return (unsigned)__bfloat16_as_ushort(a)
         | ((unsigned)__bfloat16_as_ushort(b) << 16);
}

// ---- fused sq-norm + dn + bf16-split image prep (stage 1, C=32, K=96) ------
__global__ void sqprep32_kernel(const float* __restrict__ x, float* __restrict__ sq,
                                __nv_bfloat16* __restrict__ imgA,
                                __nv_bfloat16* __restrict__ imgB,
                                const float* __restrict__ ew, float* __restrict__ dn) {
    int gi = blockIdx.x * blockDim.x + threadIdx.x;
    if (gi >= N_TOT) return;
    {
        float d = ew[3 * gi] + ew[3 * gi + 1] + ew[3 * gi + 2];
        dn[gi] = d > 0.f ? rsqrtf(fmaxf(d, 1e-12f)) : 0.f;
    }
    const float4* r4 = (const float4*)(x + (size_t)gi * 32);
    uint4* a4 = (uint4*)(imgA + (size_t)gi * 96);
    uint4* b4 = (uint4*)(imgB + (size_t)gi * 96);
    float p[32];
#pragma unroll
    for (int t = 0; t < 4; t++) {
        float4 va = r4[2 * t], vb = r4[2 * t + 1];
        float vv[8] = {va.x, va.y, va.z, va.w, vb.x, vb.y, vb.z, vb.w};
        unsigned hw[4], lw[4];
#pragma unroll
        for (int i = 0; i < 4; i++) {
            float v0 = vv[2 * i], v1 = vv[2 * i + 1];
            __nv_bfloat16 h0 = __float2bfloat16(v0), h1 = __float2bfloat16(v1);
            __nv_bfloat16 l0 = __float2bfloat16(v0 - __bfloat162float(h0));
            __nv_bfloat16 l1 = __float2bfloat16(v1 - __bfloat162float(h1));
            hw[i] = packbf2(h0, h1);
            lw[i] = packbf2(l0, l1);
        }
#pragma unroll
        for (int i = 0; i < 8; i++) p[8 * t + i] = __fmul_rn(vv[i], vv[i]);
        uint4 H = make_uint4(hw[0], hw[1], hw[2], hw[3]);
        uint4 L = make_uint4(lw[0], lw[1], lw[2], lw[3]);
        a4[t] = H; a4[4 + t] = H; a4[8 + t] = L;   // A: [hi|hi|lo]
        b4[t] = H; b4[4 + t] = L; b4[8 + t] = H;   // B: [hi|lo|hi]
    }
#pragma unroll
    for (int off = 16; off > 0; off >>= 1)
#pragma unroll
        for (int c = 0; c < 16; c++)
            if (c < off) p[c] = __fadd_rn(p[c], p[c + off]);
    sq[gi] = p[0];
}

// ---- fused sq-norm + image prep (stage 2, C=64, K=192) ---------------------
__global__ void sqprep64_kernel(const float* __restrict__ u, float* __restrict__ sq,
                                __nv_bfloat16* __restrict__ imgA,
                                __nv_bfloat16* __restrict__ imgB) {
    int gi = blockIdx.x * blockDim.x + threadIdx.x;
    if (gi >= N_TOT) return;
    const float4* r4 = (const float4*)(u + (size_t)gi * 64);
    uint4* a4 = (uint4*)(imgA + (size_t)gi * 192);
    uint4* b4 = (uint4*)(imgB + (size_t)gi * 192);
    float p[32];
#pragma unroll
    for (int t = 0; t < 8; t++) {
        float4 va = r4[2 * t], vb = r4[2 * t + 1];
        float vv[8] = {va.x, va.y, va.z, va.w, vb.x, vb.y, vb.z, vb.w};
        unsigned hw[4], lw[4];
#pragma unroll
        for (int i = 0; i < 4; i++) {
            float v0 = vv[2 * i], v1 = vv[2 * i + 1];
            __nv_bfloat16 h0 = __float2bfloat16(v0), h1 = __float2bfloat16(v1);
            __nv_bfloat16 l0 = __float2bfloat16(v0 - __bfloat162float(h0));
            __nv_bfloat16 l1 = __float2bfloat16(v1 - __bfloat162float(h1));
            hw[i] = packbf2(h0, h1);
            lw[i] = packbf2(l0, l1);
        }
        float a0 = __fmaf_rn(vv[0], vv[0], 0.f);
        p[4 * t + 0] = __fmaf_rn(vv[1], vv[1], a0);
        float a1 = __fmaf_rn(vv[2], vv[2], 0.f);
        p[4 * t + 1] = __fmaf_rn(vv[3], vv[3], a1);
        float a2 = __fmaf_rn(vv[4], vv[4], 0.f);
        p[4 * t + 2] = __fmaf_rn(vv[5], vv[5], a2);
        float a3 = __fmaf_rn(vv[6], vv[6], 0.f);
        p[4 * t + 3] = __fmaf_rn(vv[7], vv[7], a3);
        uint4 H = make_uint4(hw[0], hw[1], hw[2], hw[3]);
        uint4 L = make_uint4(lw[0], lw[1], lw[2], lw[3]);
        a4[t] = H; a4[8 + t] = H; a4[16 + t] = L;  // A: [hi|hi|lo]
        b4[t] = H; b4[8 + t] = L; b4[16 + t] = H;  // B: [hi|lo|hi]
    }
#pragma unroll
    for (int off = 16; off > 0; off >>= 1)
#pragma unroll
        for (int c = 0; c < 16; c++)
            if (c < off) p[c] = __fadd_rn(p[c], p[c + off]);
    sq[gi] = p[0];
}

// ------------------------------ weight split prep (GEMM) ---------------------
__global__ void prep_w_kernel(const float* __restrict__ W,
                              __nv_bfloat16* __restrict__ whi,
                              __nv_bfloat16* __restrict__ wlo,
                              int K, int N, int Kp, int Nimg) {
    int idx = blockIdx.x * blockDim.x + threadIdx.x;
    int total = Nimg * (Kp / 8);
    if (idx >= total) return;
    int n = idx / (Kp / 8), k0 = (idx % (Kp / 8)) * 8;
    unsigned hh[4], ll[4];
#pragma unroll
    for (int e = 0; e < 4; e++) {
        float v0 = 0.f, v1 = 0.f;
        int k = k0 + 2 * e;
        if (n < N && k < K)     v0 = W[(size_t)k * N + n];
        if (n < N && k + 1 < K) v1 = W[(size_t)(k + 1) * N + n];
        __nv_bfloat16 h0 = __float2bfloat16(v0), h1 = __float2bfloat16(v1);
        __nv_bfloat16 l0 = __float2bfloat16(v0 - __bfloat162float(h0));
        __nv_bfloat16 l1 = __float2bfloat16(v1 - __bfloat162float(h1));
        hh[e] = packbf2(h0, h1);
        ll[e] = packbf2(l0, l1);
    }
    *(uint4*)&whi[(size_t)n * Kp + k0] = make_uint4(hh[0], hh[1], hh[2], hh[3]);
    *(uint4*)&wlo[(size_t)n * Kp + k0] = make_uint4(ll[0], ll[1], ll[2], ll[3]);
}

// ------------------------------ bf16-split tensor GEMM -----------------------
template<int ACT>
__global__ void __launch_bounds__(128) gemm_bf16_kernel(
        const float* __restrict__ A, const __nv_bfloat16* __restrict__ whi,
        const __nv_bfloat16* __restrict__ wlo, const float* __restrict__ bias,
        float* __restrict__ C, int K, int Kp, int Ncols) {
    const int SKW = 40;
    __shared__ __align__(16) __nv_bfloat16 Ahi[64][SKW], Alo[64][SKW],
                                           Bhi[64][SKW], Blo[64][SKW];
    int tid = threadIdx.x, lane = tid & 31, w = tid >> 5;
    int row0 = blockIdx.y * 64, col0 = blockIdx.x * 64;

    float acc[8][4];
#pragma unroll
    for (int nt = 0; nt < 8; nt++)
#pragma unroll
        for (int e = 0; e < 4; e++) acc[nt][e] = 0.f;

    const int ar = lane & 7, ah = (lane >> 3) & 1, akh = (lane >> 4) & 1;
    const int bn = (lane & 7) | (((lane >> 4) & 1) << 3), bh = (lane >> 3) & 1;
    const int m0 = w * 16;

    for (int k0 = 0; k0 < Kp; k0 += 32) {
#pragma unroll
        for (int s = 0; s < 4; s++) {
            int idx = tid + s * 128;
            int r = idx >> 3, c4 = idx & 7;
            int gk = k0 + c4 * 4;
            float4 v = make_float4(0.f, 0.f, 0.f, 0.f);
            if (gk < K) v = *(const float4*)(A + (size_t)(row0 + r) * K + gk);
            __nv_bfloat16 h0 = __float2bfloat16(v.x), h1 = __float2bfloat16(v.y);
            __nv_bfloat16 h2 = __float2bfloat16(v.z), h3 = __float2bfloat16(v.w);
            __nv_bfloat16 l0 = __float2bfloat16(v.x - __bfloat162float(h0));
            __nv_bfloat16 l1 = __float2bfloat16(v.y - __bfloat162float(h1));
            __nv_bfloat16 l2 = __float2bfloat16(v.z - __bfloat162float(h2));
            __nv_bfloat16 l3 = __float2bfloat16(v.w - __bfloat162float(h3));
            *(uint2*)&Ahi[r][c4 * 4] = make_uint2(packbf2(h0, h1), packbf2(h2, h3));
            *(uint2*)&Alo[r][c4 * 4] = make_uint2(packbf2(l0, l1), packbf2(l2, l3));
        }
#pragma unroll
        for (int s = 0; s < 2; s++) {
            int idx = tid + s * 128;
            int n = idx >> 2, c = idx & 3;
            size_t go = (size_t)(col0 + n) * Kp + k0 + c * 8;
            *(uint4*)&Bhi[n][c * 8] = *(const uint4*)&whi[go];
            *(uint4*)&Blo[n][c * 8] = *(const uint4*)&wlo[go];
        }
        __syncthreads();
#pragma unroll
        for (int kc = 0; kc < 2; kc++) {
            unsigned afh[4], afl[4];
            ldm4(afh[0], afh[1], afh[2], afh[3],
                 smem_u32(&Ahi[m0 + ar + 8 * ah][kc * 16 + 8 * akh]));
            ldm4(afl[0], afl[1], afl[2], afl[3],
                 smem_u32(&Alo[m0 + ar + 8 * ah][kc * 16 + 8 * akh]));
            unsigned bfh[8][2], bfl[8][2];
#pragma unroll
            for (int np = 0; np < 4; np++) {
                unsigned r0, r1, r2, r3;
                ldm4(r0, r1, r2, r3,
                     smem_u32(&Bhi[np * 16 + bn][kc * 16 + 8 * bh]));
                bfh[2 * np][0] = r0; bfh[2 * np][1] = r1;
                bfh[2 * np + 1][0] = r2; bfh[2 * np + 1][1] = r3;
                ldm4(r0, r1, r2, r3,
                     smem_u32(&Blo[np * 16 + bn][kc * 16 + 8 * bh]));
                bfl[2 * np][0] = r0; bfl[2 * np][1] = r1;
                bfl[2 * np + 1][0] = r2; bfl[2 * np + 1][1] = r3;
            }
#pragma unroll
            for (int nt = 0; nt < 8; nt++) {
                mma_bf16(acc[nt], afh, bfh[nt]);
                mma_bf16(acc[nt], afh, bfl[nt]);
                mma_bf16(acc[nt], afl, bfh[nt]);
            }
        }
        __syncthreads();
    }
    int r0e = row0 + m0 + (lane >> 2);
    int c0e = col0 + 2 * (lane & 3);
#pragma unroll
    for (int nt = 0; nt < 8; nt++)
#pragma unroll
        for (int e = 0; e < 4; e++) {
            int row = r0e + 8 * (e >> 1);
            int col = c0e + nt * 8 + (e & 1);
            if (col < Ncols) {
                float v = acc[nt][e] + bias[col];
                if (ACT == 1) v = selu_f(v);
                C[(size_t)row * Ncols + col] = v;
            }
        }
}

// ------------------------------ epilogue insert (kNN, min-gated) -------------
template<bool SELF>
__device__ __forceinline__ void epi_insert(float (&acc)[4][4], const float* sqb,
                                           const int (&jc16)[16], int j0,
                                           const int (&li2)[2],
                                           float (&cd)[2][4], int (&ci)[2][4]) {
#pragma unroll
    for (int nt = 0; nt < 4; nt++)
#pragma unroll
        for (int e = 0; e < 4; e++) {
            int jc = jc16[nt * 4 + e];
            float dv = __fmaf_rn(-2.f, acc[nt][e], sqb[jc]);
            if (SELF && (j0 + jc) == li2[e >> 1]) dv = 3.4e38f;
            acc[nt][e] = dv;
        }
    float mn0 = fminf(fminf(fminf(acc[0][0], acc[0][1]), fminf(acc[1][0], acc[1][1])),
                      fminf(fminf(acc[2][0], acc[2][1]), fminf(acc[3][0], acc[3][1])));
    float mn1 = fminf(fminf(fminf(acc[0][2], acc[0][3]), fminf(acc[1][2], acc[1][3])),
                      fminf(fminf(acc[2][2], acc[2][3]), fminf(acc[3][2], acc[3][3])));
    if (mn0 < cd[0][3]) {
#pragma unroll
        for (int nt = 0; nt < 4; nt++)
#pragma unroll
            for (int e = 0; e < 2; e++) {
                float d = acc[nt][e];
                if (d < cd[0][3]) {
                    int col = j0 + jc16[nt * 4 + e];
                    float vd = d; int vi = col;
#pragma unroll
                    for (int p = 0; p < 4; p++) {
                        if (vd < cd[0][p]) {
                            float td = cd[0][p]; int ti = ci[0][p];
                            cd[0][p] = vd; ci[0][p] = vi;
                            vd = td; vi = ti;
                        }
                    }
                }
            }
    }
    if (mn1 < cd[1][3]) {
#pragma unroll
        for (int nt = 0; nt < 4; nt++)
#pragma unroll
            for (int e = 2; e < 4; e++) {
                float d = acc[nt][e];
                if (d < cd[1][3]) {
                    int col = j0 + jc16[nt * 4 + e];
                    float vd = d; int vi = col;
#pragma unroll
                    for (int p = 0; p < 4; p++) {
                        if (vd < cd[1][p]) {
                            float td = cd[1][p]; int ti = ci[1][p];
                            cd[1][p] = vd; ci[1][p] = vi;
                            vd = td; vi = ti;
                        }
                    }
                }
            }
    }
}

// ------------------------------ mma.sync kNN candidates (K = 3C) -------------
// A fragments register-resident (staged once through the B buffer).
template<int C>
__global__ void __launch_bounds__(128) knn_mma_kernel(
        const __nv_bfloat16* __restrict__ imgA, const __nv_bfloat16* __restrict__ imgB,
        const float* __restrict__ sq, float* __restrict__ candd,
        int* __restrict__ candi, int nper) {
    const int K   = 3 * C;
    const int SKW = K + 16;
    const int KC  = K / 16;
    const int JT  = 32;
    const int CH  = K / 8;
    const int SLOTS = JT * CH / 128;
    extern __shared__ __align__(16) __nv_bfloat16 sh[];
    __nv_bfloat16* Bsh  = sh;                           // [2][JT][SKW]
    float*         sqsh = (float*)(Bsh + 2 * JT * SKW); // [2][JT]

    int tid  = threadIdx.x;
    int lane = tid & 31, w = tid >> 5;
    int b = blockIdx.z, it = blockIdx.x, split = blockIdx.y;
    int ibase = it * 64;
    int gbase = b * nper;
    int jlen  = nper >> 2;
    int js    = split * jlen;
    const int NT = jlen / JT;

    const int m0 = w * 16;
    const int ar  = lane & 7;
    const int ah  = (lane >> 3) & 1;
    const int akh = (lane >> 4) & 1;
    const int bn  = (lane & 7) | (((lane >> 4) & 1) << 3);
    const int bh  = (lane >> 3) & 1;

    // ---- stage A tile through the B-buffer region, ldsm into registers ----
    for (int t = tid; t < 64 * CH; t += 128) {
        int r = t / CH, cc = t % CH;
        *(uint4*)&Bsh[r * SKW + cc * 8] =
            *(const uint4*)&imgA[((size_t)(gbase + ibase + r)) * K + cc * 8];
    }
    __syncthreads();
    unsigned af[KC][4];
    {
        unsigned aStage = smem_u32(&Bsh[(m0 + ar + 8 * ah) * SKW + 8 * akh]);
#pragma unroll
        for (int kc = 0; kc < KC; kc++)
            ldm4(af[kc][0], af[kc][1], af[kc][2], af[kc][3], aStage + kc * 32);
    }
    __syncthreads();

    // ---- B pipeline setup --------------------------------------------------
    unsigned sBoff[SLOTS]; unsigned gBoff[SLOTS];
#pragma unroll
    for (int s = 0; s < SLOTS; s++) {
        int q = tid + s * 128;
        int r = q / CH, cc = q % CH;
        sBoff[s] = (unsigned)((r * SKW + cc * 8) * 2);
        gBoff[s] = (unsigned)(r * K + cc * 8);
    }
    unsigned bufB[2] = { smem_u32(Bsh), smem_u32(Bsh + JT * SKW) };
    unsigned sqBuf[2] = { smem_u32(sqsh), smem_u32(sqsh + JT) };

    const __nv_bfloat16* gtile = imgB + (size_t)(gbase + js) * K;
    const float* gsq = sq + gbase + js;
#pragma unroll
    for (int s = 0; s < SLOTS; s++)
        cp_async16(bufB[0] + sBoff[s], gtile + gBoff[s]);
    if (tid < JT / 4)
        cp_async16(sqBuf[0] + tid * 16, gsq + tid * 4);
    cp_commit();
    const __nv_bfloat16* gnext = gtile + (size_t)JT * K;
    const float* gsqnext = gsq + JT;

    int li2[2];
#pragma unroll
    for (int s = 0; s < 2; s++) li2[s] = ibase + m0 + (lane >> 2) + 8 * s;
    float cd[2][4]; int ci[2][4];
#pragma unroll
    for (int s = 0; s < 2; s++)
#pragma unroll
        for (int p = 0; p < 4; p++) { cd[s][p] = 3.4e38f; ci[s][p] = 0; }

    unsigned bnOff = (unsigned)((bn * SKW + 8 * bh) * 2);

    int jc16[16];
#pragma unroll
    for (int nt = 0; nt < 4; nt++)
#pragma unroll
        for (int e = 0; e < 4; e++)
            jc16[nt * 4 + e] = nt * 8 + 2 * (lane & 3) + (e & 1);

    int j0 = js;
    for (int t = 0; t < NT; t++) {
        if (t + 1 < NT) {
            unsigned bb = bufB[(t + 1) & 1];
#pragma unroll
            for (int s = 0; s < SLOTS; s++)
                cp_async16(bb + sBoff[s], gnext + gBoff[s]);
            if (tid < JT / 4)
                cp_async16(sqBuf[(t + 1) & 1] + tid * 16, gsqnext + tid * 4);
            cp_commit();
            cp_wait1();
            gnext += (size_t)JT * K;
            gsqnext += JT;
        } else {
            cp_wait0();
        }
        __syncthreads();

        unsigned bBufBase = bufB[t & 1] + bnOff;
        const float* sqb = (t & 1) ? (sqsh + JT) : sqsh;

        float acc[4][4];
#pragma unroll
        for (int nt = 0; nt < 4; nt++)
#pragma unroll
            for (int e = 0; e < 4; e++) acc[nt][e] = 0.f;

#pragma unroll
        for (int kc = 0; kc < KC; kc++) {
            unsigned bf[4][2];
#pragma unroll
            for (int np = 0; np < 2; np++) {
                unsigned r0, r1, r2, r3;
                ldm4(r0, r1, r2, r3, bBufBase + np * (16 * SKW * 2) + kc * 32);
                bf[2 * np][0] = r0; bf[2 * np][1] = r1;
                bf[2 * np + 1][0] = r2; bf[2 * np + 1][1] = r3;
            }
#pragma unroll
            for (int nt = 0; nt < 4; nt++)
                mma_bf16(acc[nt], af[kc], bf[nt]);
        }

        bool ovl = (j0 < ibase + 64) && (j0 + JT > ibase);
        if (ovl) epi_insert<true >(acc, sqb, jc16, j0, li2, cd, ci);
        else     epi_insert<false>(acc, sqb, jc16, j0, li2, cd, ci);
        j0 += JT;
        __syncthreads();
    }
#pragma unroll
    for (int s = 0; s < 2; s++)
#pragma unroll
        for (int p = 0; p < 4; p++) {
            size_t base = ((size_t)(gbase + li2[s])) * 64 + split * 16 + (lane & 3) * 4 + p;
            candd[base] = cd[s][p];
            candi[base] = gbase + ci[s][p];
        }
}

// ------------------------------ warp-cooperative re-rank + wn ----------------
// 8 lanes per node; vectorized loads (float4/int4); exact phase-2 dot keeps
// the sequential ascending-c FMA chain (bit-identical rounding).
template<int C>
__global__ void rerank_kernel(const float* __restrict__ x, const float* __restrict__ sq,
                              const float* __restrict__ candd, const int* __restrict__ candi,
                              int* __restrict__ knn,
                              const float* __restrict__ ew, const float* __restrict__ dnv,
                              float* __restrict__ wn, int n) {
    int t = blockIdx.x * blockDim.x + threadIdx.x;
    int gi = t >> 3;
    int r8 = t & 7;
    if (gi >= n) return;

    float d8[8]; int i8[8];
    {
        const float4* cd4 = (const float4*)(candd + (size_t)gi * 64 + r8 * 8);
        const int4*   ci4 = (const int4*)  (candi + (size_t)gi * 64 + r8 * 8);
        float4 da = cd4[0], db = cd4[1];
        int4   ia = ci4[0], ib = ci4[1];
        d8[0] = da.x; d8[1] = da.y; d8[2] = da.z; d8[3] = da.w;
        d8[4] = db.x; d8[5] = db.y; d8[6] = db.z; d8[7] = db.w;
        i8[0] = ia.x; i8[1] = ia.y; i8[2] = ia.z; i8[3] = ia.w;
        i8[4] = ib.x; i8[5] = ib.y; i8[6] = ib.z; i8[7] = ib.w;
    }

    unsigned taken = 0;
    float myD = 3.4e38f; int myI = 0;
#pragma unroll
    for (int r = 0; r < 8; r++) {
        float ld = 3.4e38f; int li = 0x7fffffff; int lp = -1;
#pragma unroll
        for (int p = 0; p < 8; p++) {
            if (!(taken & (1u << p)) &&
                (d8[p] < ld || (d8[p] == ld && i8[p] < li))) {
                ld = d8[p]; li = i8[p]; lp = p;
            }
        }
        float bd = ld; int bi = li; int bl = r8;
#pragma unroll
        for (int off = 4; off > 0; off >>= 1) {
            float od = __shfl_xor_sync(0xffffffffu, bd, off);
            int   oi = __shfl_xor_sync(0xffffffffu, bi, off);
            int   ol = __shfl_xor_sync(0xffffffffu, bl, off);
            if (od < bd || (od == bd && (oi < bi || (oi == bi && ol < bl)))) {
                bd = od; bi = oi; bl = ol;
            }
        }
        if (bl == r8 && lp >= 0) taken |= (1u << lp);
        if (r == r8) { myD = bd; myI = bi; }
    }

    // exact reference-rounded distance (sequential ascending-c FMA chain)
    const float4* xi4 = (const float4*)(x + (size_t)gi * C);
    const float4* xr4 = (const float4*)(x + (size_t)myI * C);
    float dot = 0.f;
#pragma unroll
    for (int q = 0; q < C / 4; q++) {
        float4 va = xi4[q];
        float4 vb = __ldg(&xr4[q]);
        dot = __fmaf_rn(va.x, vb.x, dot);
        dot = __fmaf_rn(va.y, vb.y, dot);
        dot = __fmaf_rn(va.z, vb.z, dot);
        dot = __fmaf_rn(va.w, vb.w, dot);
    }
    float dd = __fsub_rn(__fadd_rn(sq[gi], sq[myI]), __fmul_rn(2.f, dot));

    bool used = false;
    float dng = dnv[gi];
#pragma unroll
    for (int r = 0; r < 3; r++) {
        float bd = used ? 3.4e38f : dd;
        int   bi = used ? 0x7fffffff : myI;
        int   bl = r8;
#pragma unroll
        for (int off = 4; off > 0; off >>= 1) {
            float od = __shfl_xor_sync(0xffffffffu, bd, off);
            int   oi = __shfl_xor_sync(0xffffffffu, bi, off);
            int   ol = __shfl_xor_sync(0xffffffffu, bl, off);
            if (od < bd || (od == bd && (oi < bi || (oi == bi && ol < bl)))) {
                bd = od; bi = oi; bl = ol;
            }
        }
        if (bl == r8) used = true;
        if (r8 == 0) {
            knn[gi * 3 + r] = bi;
            wn [gi * 3 + r] = __fmul_rn(__fmul_rn(ew[gi * 3 + r], dng), dnv[bi]);
        }
    }
}

// ------------------------------ Laplacian step -------------------------------
__global__ void lap_kernel(const float* __restrict__ Zin, const float* __restrict__ Zprev,
                           float* __restrict__ Zout, int stride, int Cq,
                           float alpha, float beta,
                           const int* __restrict__ knn, const float* __restrict__ wn,
                           int total) {
    int idx = blockIdx.x * blockDim.x + threadIdx.x;
    if (idx >= total) return;
    int g = idx / Cq, q = idx % Cq;
    int s0 = knn[3 * g], s1 = knn[3 * g + 1], s2 = knn[3 * g + 2];
    float w0 = wn[3 * g], w1 = wn[3 * g + 1], w2 = wn[3 * g + 2];
    float4 a0 = ((const float4*)(Zin + (size_t)s0 * stride))[q];
    float4 a1 = ((const float4*)(Zin + (size_t)s1 * stride))[q];
    float4 a2 = ((const float4*)(Zin + (size_t)s2 * stride))[q];
    float4 r;
    r.x = alpha * (-(w0 * a0.x + w1 * a1.x + w2 * a2.x));
    r.y = alpha * (-(w0 * a0.y + w1 * a1.y + w2 * a2.y));
    r.z = alpha * (-(w0 * a0.z + w1 * a1.z + w2 * a2.z));
    r.w = alpha * (-(w0 * a0.w + w1 * a1.w + w2 * a2.w));
    if (beta != 0.f) {
        float4 p = ((const float4*)(Zprev + (size_t)g * stride))[q];
        r.x += beta * p.x; r.y += beta * p.y; r.z += beta * p.z; r.w += beta * p.w;
    }
    ((float4*)(Zout + (size_t)g * stride))[q] = r;
}

// ------------------------------ fused copy + first lap ----------------------
// own -> Z[:, 0:Cq], -(Σ w v) -> Z[:, Cq:2Cq]. Arithmetic identical to
// copy_slice + lap(alpha=1, beta=0) (multiply-by-1 exact; same source bits).
__global__ void lap_first_kernel(const float* __restrict__ src, float* __restrict__ Z,
                                 int stride4, int Cq,
                                 const int* __restrict__ knn, const float* __restrict__ wn,
                                 int total) {
    int idx = blockIdx.x * blockDim.x + threadIdx.x;
    if (idx >= total) return;
    int g = idx / Cq, q = idx % Cq;
    int s0 = knn[3 * g], s1 = knn[3 * g + 1], s2 = knn[3 * g + 2];
    float w0 = wn[3 * g], w1 = wn[3 * g + 1], w2 = wn[3 * g + 2];
    const float4* s4 = (const float4*)src;
    float4 own = s4[(size_t)g * Cq + q];
    float4 a0 = s4[(size_t)s0 * Cq + q];
    float4 a1 = s4[(size_t)s1 * Cq + q];
    float4 a2 = s4[(size_t)s2 * Cq + q];
    float4 r;
    r.x = -(w0 * a0.x + w1 * a1.x + w2 * a2.x);
    r.y = -(w0 * a0.y + w1 * a1.y + w2 * a2.y);
    r.z = -(w0 * a0.z + w1 * a1.z + w2 * a2.z);
    r.w = -(w0 * a0.w + w1 * a1.w + w2 * a2.w);
    ((float4*)Z)[(size_t)g * stride4 + q]      = own;
    ((float4*)Z)[(size_t)g * stride4 + Cq + q] = r;
}

// ------------------------------ fp32 FFMA2 GEMM (conv0 only) ----------------
template<int ACT>
__global__ void gemm_kernel(const float* __restrict__ A, const float* __restrict__ B,
                            const float* __restrict__ bias, float* __restrict__ C,
                            int K, int Ncols) {
    __shared__ __align__(16) float As2[16][128];
    __shared__ __align__(16) float Bs[16][64];
    const int tid  = threadIdx.x;
    const int row0 = blockIdx.y * 64;
    const int col0 = blockIdx.x * 64;
    const int tx = tid & 15, ty = tid >> 4;
    unsigned long long acc2[4][2];
#pragma unroll
    for (int i = 0; i < 4; i++) { acc2[i][0] = 0ull; acc2[i][1] = 0ull; }

    const int lin  = tid * 4;
    const int arow = lin >> 4, acol = lin & 15;
    const int brow = lin >> 6, bcol = lin & 63;

    for (int k0 = 0; k0 < K; k0 += 16) {
        float4 av = make_float4(0.f, 0.f, 0.f, 0.f);
        if (k0 + acol < K)
            av = *(const float4*)(A + (size_t)(row0 + arow) * K + k0 + acol);
        *(float2*)&As2[acol + 0][2 * arow] = make_float2(av.x, av.x);
        *(float2*)&As2[acol + 1][2 * arow] = make_float2(av.y, av.y);
        *(float2*)&As2[acol + 2][2 * arow] = make_float2(av.z, av.z);
        *(float2*)&As2[acol + 3][2 * arow] = make_float2(av.w, av.w);

        float4 bv = make_float4(0.f, 0.f, 0.f, 0.f);
        int gk = k0 + brow, gc = col0 + bcol;
        if (gk < K && gc < Ncols)
            bv = *(const float4*)(B + (size_t)gk * Ncols + gc);
        *(float4*)&Bs[brow][bcol] = bv;
        __syncthreads();
#pragma unroll
        for (int kk = 0; kk < 16; kk++) {
            ulonglong2 a01 = *(const ulonglong2*)&As2[kk][ty * 8];
            ulonglong2 a23 = *(const ulonglong2*)&As2[kk][ty * 8 + 4];
            ulonglong2 bq  = *(const ulonglong2*)&Bs[kk][tx * 4];
            ffma2(acc2[0][0], a01.x, bq.x); ffma2(acc2[0][1], a01.x, bq.y);
            ffma2(acc2[1][0], a01.y, bq.x); ffma2(acc2[1][1], a01.y, bq.y);
            ffma2(acc2[2][0], a23.x, bq.x); ffma2(acc2[2][1], a23.x, bq.y);
            ffma2(acc2[3][0], a23.y, bq.x); ffma2(acc2[3][1], a23.y, bq.y);
        }
        __syncthreads();
    }
#pragma unroll
    for (int i = 0; i < 4; i++) {
        float a0, a1, a2, a3;
        unpack2(acc2[i][0], a0, a1);
        unpack2(acc2[i][1], a2, a3);
        float accs[4] = {a0, a1, a2, a3};
        int row = row0 + ty * 4 + i;
#pragma unroll
        for (int j = 0; j < 4; j++) {
            int col = col0 + tx * 4 + j;
            if (col < Ncols) {
                float v = accs[j] + bias[col];
                if (ACT == 1) v = selu_f(v);
                C[(size_t)row * Ncols + col] = v;
            }
        }
    }
}

// ------------------------------ GraphNorm -----------------------------------
__global__ void gn_reduce_kernel(const float* __restrict__ u, const float* __restrict__ alpha,
                                 float* __restrict__ amean, float* __restrict__ rstd) {
    int b = blockIdx.x;
    int t = threadIdx.x;               // 256
    int c = t & 63, rg = t >> 6;
    float s = 0.f;
    for (int n = rg; n < NG_; n += 4) s += u[((size_t)(b * NG_ + n)) * 64 + c];
    __shared__ float sh[256];
    sh[t] = s;
    __syncthreads();
    __shared__ float smean[64];
    if (t < 64) {
        s = sh[t] + sh[t + 64] + sh[t + 128] + sh[t + 192];
        smean[t] = s * (1.f / NG_);
    }
    __syncthreads();
    float am = alpha[c] * smean[c];
    float s2 = 0.f;
    for (int n = rg; n < NG_; n += 4) {
        float v = u[((size_t)(b * NG_ + n)) * 64 + c] - am;
        s2 += v * v;
    }
    sh[t] = s2;
    __syncthreads();
    if (t < 64) {
        s2 = sh[t] + sh[t + 64] + sh[t + 128] + sh[t + 192];
        float var = s2 * (1.f / NG_);
        amean[b * 64 + t] = alpha[t] * smean[t];
        rstd [b * 64 + t] = rsqrtf(var + 1e-5f);
    }
}

__global__ void gn_norm_kernel(float* __restrict__ u, const float* __restrict__ gamma,
                               const float* __restrict__ beta, const float* __restrict__ amean,
                               const float* __restrict__ rstd) {
    int idx = blockIdx.x * blockDim.x + threadIdx.x;
    if (idx >= N_TOT * 64) return;
    int g = idx >> 6, c = idx & 63;
    int b = g >> 12;   // /4096
    float v = u[idx];
    u[idx] = gamma[c] * (v - amean[b * 64 + c]) * rstd[b * 64 + c] + beta[c];
}

// ------------------------------ softmax rows (warp per row) ------------------
__global__ void softmax_kernel(const float* __restrict__ u, float* __restrict__ S) {
    int row = blockIdx.x * 4 + (threadIdx.x >> 5);
    int lane = threadIdx.x & 31;
    if (row >= N_TOT) return;
    const float* rp = u + (size_t)row * M_;
    float v0 = rp[lane], v1 = rp[lane + 32], v2 = rp[lane + 64];
    float v3 = (lane < 4) ? rp[lane + 96] : -3.4e38f;
    float m = fmaxf(fmaxf(v0, v1), fmaxf(v2, v3));
#pragma unroll
    for (int off = 16; off > 0; off >>= 1)
        m = fmaxf(m, __shfl_xor_sync(0xffffffffu, m, off));
    float e0 = expf(v0 - m), e1 = expf(v1 - m), e2 = expf(v2 - m);
    float e3 = (lane < 4) ? expf(v3 - m) : 0.f;
    float s = e0 + e1 + e2 + e3;
#pragma unroll
    for (int off = 16; off > 0; off >>= 1)
        s += __shfl_xor_sync(0xffffffffu, s, off);
    float inv = 1.f / s;
    float* so = S + (size_t)row * M_;
    so[lane] = e0 * inv; so[lane + 32] = e1 * inv; so[lane + 64] = e2 * inv;
    if (lane < 4) so[lane + 96] = e3 * inv;
}

// ------------------------------ DiffPool pooling (tiled, deterministic) ------
__global__ void pool_partial_kernel(const float* __restrict__ S, const float* __restrict__ x,
                                    float* __restrict__ part) {
    extern __shared__ float psm[];         // sS[128*100] + sX[128*32]
    float* sS = psm;
    float* sX = psm + 128 * M_;
    int b = blockIdx.y, nt = blockIdx.x, tid = threadIdx.x;
    size_t nbase = (size_t)(b * NG_ + nt * 128);
    const float4* gS = (const float4*)(S + nbase * M_);
    float4* s4 = (float4*)sS;
    for (int i = tid; i < 128 * M_ / 4; i += 128) s4[i] = gS[i];
    const float4* gX = (const float4*)(x + nbase * 32);
    float4* x4 = (float4*)sX;
    for (int i = tid; i < 128 * 32 / 4; i += 128) x4[i] = gX[i];
    __syncthreads();
    int ty = tid >> 5, tx = tid & 31;
    int mbase = ty * 25;
    float acc[25];
#pragma unroll
    for (int k = 0; k < 25; k++) acc[k] = 0.f;
    for (int n = 0; n < 128; n++) {
        float xv = sX[n * 32 + tx];
        const float* srow = &sS[n * M_ + mbase];
#pragma unroll
        for (int k = 0; k < 25; k++) acc[k] = __fmaf_rn(srow[k], xv, acc[k]);
    }
    float* po = part + ((size_t)nt * NP_ + b * M_) * 33;
#pragma unroll
    for (int k = 0; k < 25; k++) po[(mbase + k) * 33 + tx] = acc[k];
    if (tid < M_) {
        float s = 0.f;
        for (int n = 0; n < 128; n++) s += sS[n * M_ + tid];
        po[tid * 33 + 32] = s;
    }
}

__global__ void pool_reduce_kernel(const float* __restrict__ part, float* __restrict__ xp) {
    int idx = blockIdx.x * blockDim.x + threadIdx.x;
    if (idx >= NP_ * 32) return;
    int g = idx >> 5, c = idx & 31;
    float p = 0.f, s = 0.f;
    for (int t = 0; t < 32; t++) {
        const float* base = part + ((size_t)t * NP_ + g) * 33;
        p += base[c];
        s += base[32];
    }
    xp[idx] = p / s;
}

// ------------------------------ zero-init -----------------------------------
__global__ void zero2_kernel(float* a, float* b, int n) {
    int i = blockIdx.x * blockDim.x + threadIdx.x;
    if (i < n) { a[i] = 0.f; b[i] = 0.f; }
}

// ------------------------------ PPI edge conv -------------------------------
__global__ void ppi_conv_kernel(const float* __restrict__ xp, const int* __restrict__ connect,
                                const float* __restrict__ W2, const float* __restrict__ b2,
                                float* __restrict__ h) {
    __shared__ float feat[4][64];
    int t = threadIdx.x;
    int el = t >> 6, o = t & 63;
    int e = blockIdx.x * 4 + el;
    int dst = 0;
    if (e < B_ * E_PPI_) {
        int b = e / E_PPI_, le = e % E_PPI_;
        int s = connect[le] + b * M_;
        dst   = connect[E_PPI_ + le] + b * M_;
        float v;
        if (o < 32) v = xp[dst * 32 + o];
        else        v = xp[s * 32 + (o - 32)] - xp[dst * 32 + (o - 32)];
        feat[el][o] = v;
    }
    __syncthreads();
    if (e < B_ * E_PPI_) {
        float s = b2[o];
#pragma unroll
        for (int k = 0; k < 64; k++) s += feat[el][k] * W2[k * 64 + o];
        s = fmaxf(s, 0.f);
        atomicMax((int*)&h[dst * 64 + o], __float_as_int(s));
    }
}

// ------------------------------ small kNN on pooled graphs (100 nodes) ------
__global__ void knn_small_kernel(const float* __restrict__ h, int* __restrict__ knn2) {
    __shared__ float xsf[M_ * 64];
    __shared__ float sqs[M_];
    int b = blockIdx.x, t = threadIdx.x;   // 128 threads
    const float4* src4 = (const float4*)(h + (size_t)b * M_ * 64);
    float4* dst4 = (float4*)xsf;
    for (int idx = t; idx < M_ * 16; idx += 128) dst4[idx] = src4[idx];
    __syncthreads();
    if (t < M_) {
        const float* r = xsf + t * 64;
        float p[32];
#pragma unroll
        for (int q = 0; q < 32; q++) {
            float a = __fmaf_rn(r[2 * q], r[2 * q], 0.f);
            p[q] = __fmaf_rn(r[2 * q + 1], r[2 * q + 1], a);
        }
#pragma unroll
        for (int off = 16; off > 0; off >>= 1)
#pragma unroll
            for (int c = 0; c < 16; c++)
                if (c < off) p[c] = __fadd_rn(p[c], p[c + off]);
        sqs[t] = p[0];
    }
    __syncthreads();
    if (t < M_) {
        float sqi = sqs[t];
        float bd0 = 3.4e38f, bd1 = 3.4e38f, bd2 = 3.4e38f;
        int bi0 = 0, bi1 = 0, bi2 = 0;
        for (int j = 0; j < M_; j++) {
            if (j == t) continue;
            float dot = 0.f;
#pragma unroll
            for (int c = 0; c < 64; c++)
                dot = __fmaf_rn(xsf[t * 64 + c], xsf[j * 64 + c], dot);
            float t1 = __fadd_rn(sqi, sqs[j]);
            float t2 = __fmul_rn(2.f, dot);
            float d  = __fsub_rn(t1, t2);
            if (d < bd2) {
                if (d < bd0)      { bd2=bd1; bi2=bi1; bd1=bd0; bi1=bi0; bd0=d; bi0=j; }
                else if (d < bd1) { bd2=bd1; bi2=bi1; bd1=d;   bi1=j; }
                else              { bd2=d;   bi2=j; }
            }
        }
        int g = b * M_ + t;
        knn2[g * 3 + 0] = b * M_ + bi0;
        knn2[g * 3 + 1] = b * M_ + bi1;
        knn2[g * 3 + 2] = b * M_ + bi2;
    }
}

// ------------------------------ dynamic edge conv ---------------------------
__global__ void dyn_conv_kernel(const float* __restrict__ h, const int* __restrict__ knn2,
                                const float* __restrict__ W3, const float* __restrict__ b3,
                                float* __restrict__ y) {
    __shared__ float feat[2][128];
    int t = threadIdx.x;
    int e0 = blockIdx.x * 2;
#pragma unroll
    for (int p = 0; p < 2; p++) {
        int e = e0 + p;
        if (e < NP_ * 3) {
            int g = e / 3;
            int src = knn2[e];
            int c = t;
            float v = (c < 64) ? h[g * 64 + c] : (h[src * 64 + (c - 64)] - h[g * 64 + (c - 64)]);
            feat[p][c] = v;
        }
    }
    __syncthreads();
    int el = t >> 6, o = t & 63;
    int e = e0 + el;
    if (e < NP_ * 3) {
        int g = e / 3;
        float s = b3[o];
#pragma unroll
        for (int k = 0; k < 128; k++) s += feat[el][k] * W3[k * 64 + o];
        s = fmaxf(s, 0.f);
        atomicMax((int*)&y[g * 64 + o], __float_as_int(s));
    }
}

// ------------------------------ final MLP (f2) ------------------------------
__global__ void final_mlp_kernel(const float* __restrict__ h, const float* __restrict__ y,
                                 const float* __restrict__ w1, const float* __restrict__ b1,
                                 const float* __restrict__ w2, const float* __restrict__ b2,
                                 const float* __restrict__ w3, const float* __restrict__ b3,
                                 float* __restrict__ out) {
    int r = blockIdx.x * blockDim.x + threadIdx.x;
    if (r >= NP_) return;
    float z[64];
#pragma unroll
    for (int c = 0; c < 64; c++) z[c] = h[r * 64 + c] + y[r * 64 + c];
    float a1[32];
#pragma unroll
    for (int o = 0; o < 32; o++) {
        float s = b1[o];
        for (int k = 0; k < 64; k++) s += z[k] * w1[k * 32 + o];
        a1[o] = selu_f(s);
    }
    float a2[16];
#pragma unroll
    for (int o = 0; o < 16; o++) {
        float s = b2[o];
        for (int k = 0; k < 32; k++) s += a1[k] * w2[k * 16 + o];
        a2[o] = selu_f(s);
    }
#pragma unroll
    for (int o = 0; o < 16; o++) {
        float s = b3[o];
        for (int k = 0; k < 16; k++) s += a2[k] * w3[k * 16 + o];
        out[r * 16 + o] = s;
    }
}

// ------------------------------ host orchestration --------------------------
template<typename T>
static T* sym_addr(const void* sym) {
    void* p = nullptr;
    cudaGetSymbolAddress(&p, sym);
    return (T*)p;
}

extern "C" void kernel_launch(void* const* d_in, const int* in_sizes, int n_in,
                              void* d_out, int out_size) {
    const float* x    = (const float*)d_in[0];
    const float* ew   = (const float*)d_in[1];
    const int*   conn = (const int*)d_in[3];
    const float* W0   = (const float*)d_in[4];
    const float* b0   = (const float*)d_in[5];
    const float* gna  = (const float*)d_in[6];
    const float* gng  = (const float*)d_in[7];
    const float* gnb  = (const float*)d_in[8];
    const float* W1   = (const float*)d_in[9];
    const float* b1c  = (const float*)d_in[10];
    const float* f1w1 = (const float*)d_in[11];
    const float* f1b1 = (const float*)d_in[12];
    const float* f1w2 = (const float*)d_in[13];
    const float* f1b2 = (const float*)d_in[14];
    const float* f1w3 = (const float*)d_in[15];
    const float* f1b3 = (const float*)d_in[16];
    const float* W2   = (const float*)d_in[17];
    const float* b2   = (const float*)d_in[18];
    const float* W3   = (const float*)d_in[19];
    const float* b3   = (const float*)d_in[20];
    const float* f2w1 = (const float*)d_in[21];
    const float* f2b1 = (const float*)d_in[22];
    const float* f2w2 = (const float*)d_in[23];
    const float* f2b2 = (const float*)d_in[24];
    const float* f2w3 = (const float*)d_in[25];
    const float* f2b3 = (const float*)d_in[26];

    float* out_u = (float*)d_out;                       // [32768, 100]
    float* out_v = out_u + (size_t)N_TOT * M_;          // [800, 16]

    float* sq    = sym_addr<float>(g_sq);
    int*   knn   = sym_addr<int>(g_knn);
    int*   cand  = sym_addr<int>(g_cand);
    float* cdist = sym_addr<float>(g_cdist);
    float* dn    = sym_addr<float>(g_dn);
    float* wn    = sym_addr<float>(g_wn);
    float* Z     = sym_addr<float>(g_Z);
    float* u0    = sym_addr<float>(g_u0);
    float* u1    = sym_addr<float>(g_u1);
    float* t1    = sym_addr<float>(g_t1);
    float* t2    = sym_addr<float>(g_t2);
    float* S     = sym_addr<float>(g_S);
    float* amean = sym_addr<float>(g_amean);
    float* rstd  = sym_addr<float>(g_rstd);
    float* xp    = sym_addr<float>(g_xp);
    float* h     = sym_addr<float>(g_h);
    float* y     = sym_addr<float>(g_y);
    int*   knn2  = sym_addr<int>(g_knn2);
    float* ppart = sym_addr<float>(g_poolpart);
    __nv_bfloat16* imgA = sym_addr<__nv_bfloat16>(g_imgA);
    __nv_bfloat16* imgB = sym_addr<__nv_bfloat16>(g_imgB);
    __nv_bfloat16* whi  = sym_addr<__nv_bfloat16>(g_whi);
    __nv_bfloat16* wlo  = sym_addr<__nv_bfloat16>(g_wlo);

    // smem: 2*B[JT][SKW] + 2*sqs[JT]  (A register-resident)
    const int SM32 = 2 * 32 * 112 * 2 + 2 * 32 * 4;  // 14592 B
    const int SM64 = 2 * 32 * 208 * 2 + 2 * 32 * 4;  // 26880 B
    const int SMPOOL = 128 * (M_ + 32) * 4;          // 67584 B
    static bool attr_done = false;
    if (!attr_done) {
        cudaFuncSetAttribute(pool_partial_kernel,
                             cudaFuncAttributeMaxDynamicSharedMemorySize, SMPOOL);
        attr_done = true;
    }

    // ---- stage 1: kNN on x (C=32)  (dn fused into sqprep32)
    sqprep32_kernel<<<(N_TOT + 127) / 128, 128>>>(x, sq, imgA, imgB, ew, dn);
    knn_mma_kernel<32><<<dim3(NG_ / 64, 4, B_), 128, SM32>>>(imgA, imgB, sq, cdist, cand, NG_);
    rerank_kernel<32><<<(N_TOT * 8 + 255) / 256, 256>>>(x, sq, cdist, cand, knn, ew, dn, wn, N_TOT);

    // ---- conv0: fused copy+lap0, laps, fp32 GEMM (u0 bit-exact)
    {
        int total = N_TOT * 8;   // N * C/4, C=32
        lap_first_kernel<<<(total + 255) / 256, 256>>>(x, Z, 32, 8, knn, wn, total);
        lap_kernel<<<(total + 255) / 256, 256>>>(Z + 32, Z + 0,   Z + 64, 128, 8, 2.f, -1.f, knn, wn, total);
        lap_kernel<<<(total + 255) / 256, 256>>>(Z + 64, Z + 32,  Z + 96, 128, 8, 2.f, -1.f, knn, wn, total);
        gemm_kernel<0><<<dim3(1, N_TOT / 64), 256>>>(Z, W0, b0, u0, 128, 64);
    }

    // ---- GraphNorm (unchanged; u0 bits preserved)
    gn_reduce_kernel<<<B_, 256>>>(u0, gna, amean, rstd);
    gn_norm_kernel<<<(N_TOT * 64) / 256, 256>>>(u0, gng, gnb, amean, rstd);

    // ---- stage 2: kNN on u0 (C=64)
    sqprep64_kernel<<<(N_TOT + 127) / 128, 128>>>(u0, sq, imgA, imgB);
    knn_mma_kernel<64><<<dim3(NG_ / 64, 4, B_), 128, SM64>>>(imgA, imgB, sq, cdist, cand, NG_);
    rerank_kernel<64><<<(N_TOT * 8 + 255) / 256, 256>>>(u0, sq, cdist, cand, knn, ew, dn, wn, N_TOT);

    // ---- conv1: fused copy+lap, laps, bf16-split tensor GEMM -> u1
    {
        int total = N_TOT * 16;  // N * C/4, C=64
        lap_first_kernel<<<(total + 255) / 256, 256>>>(u0, Z, 64, 16, knn, wn, total);
        lap_kernel<<<(total + 255) / 256, 256>>>(Z + 64,  Z + 0,    Z + 128, 256, 16, 2.f, -1.f, knn, wn, total);
        lap_kernel<<<(total + 255) / 256, 256>>>(Z + 128, Z + 64,   Z + 192, 256, 16, 2.f, -1.f, knn, wn, total);
        prep_w_kernel<<<(448 * 32 + 255) / 256, 256>>>(W1, whi, wlo, 256, 400, 256, 448);
        gemm_bf16_kernel<0><<<dim3(7, N_TOT / 64), 128>>>(Z, whi, wlo, b1c, u1, 256, 256, 400);
    }

    // ---- fc1 MLP: 400 -> 200 -> 100 -> 100 (bf16-split tensor GEMMs)
    prep_w_kernel<<<(256 * 52 + 255) / 256, 256>>>(f1w1, whi, wlo, 400, 200, 416, 256);
    gemm_bf16_kernel<1><<<dim3(4, N_TOT / 64), 128>>>(u1, whi, wlo, f1b1, t1, 400, 416, 200);
    prep_w_kernel<<<(128 * 28 + 255) / 256, 256>>>(f1w2, whi, wlo, 200, 100, 224, 128);
    gemm_bf16_kernel<1><<<dim3(2, N_TOT / 64), 128>>>(t1, whi, wlo, f1b2, t2, 200, 224, 100);
    prep_w_kernel<<<(128 * 16 + 255) / 256, 256>>>(f1w3, whi, wlo, 100, 100, 128, 128);
    gemm_bf16_kernel<0><<<dim3(2, N_TOT / 64), 128>>>(t2, whi, wlo, f1b3, out_u, 100, 128, 100);

    // ---- DiffPool soft pooling (tiled partials + deterministic reduce)
    softmax_kernel<<<N_TOT / 4, 128>>>(out_u, S);
    pool_partial_kernel<<<dim3(NG_ / 128, B_), 128, SMPOOL>>>(S, x, ppart);
    pool_reduce_kernel<<<(NP_ * 32 + 255) / 256, 256>>>(ppart, xp);

    // ---- PPI edge conv + dynamic edge conv
    zero2_kernel<<<(NP_ * HID_ + 255) / 256, 256>>>(h, y, NP_ * HID_);
    ppi_conv_kernel<<<(B_ * E_PPI_ + 3) / 4, 256>>>(xp, conn, W2, b2, h);
    knn_small_kernel<<<B_, 128>>>(h, knn2);
    dyn_conv_kernel<<<(NP_ * 3 + 1) / 2, 128>>>(h, knn2, W3, b3, y);

    // ---- final MLP -> v
    final_mlp_kernel<<<(NP_ + 127) / 128, 128>>>(h, y, f2w1, f2b1, f2w2, f2b2,
                                                 f2w3, f2b3, out_v);
}